// round 2
// baseline (speedup 1.0000x reference)
#include <cuda_runtime.h>
#include <cuda_bf16.h>
#include <math.h>

// Problem constants
#define NB   4
#define LQ   2048
#define LK   2048
#define DIM  1024
#define NH   16
#define DH   64

// ---------------- scratch (static device arrays; no allocation) -------------
__device__ float g_Q[NB * NH * LQ * DH];   // (n,h,l,dh)
__device__ float g_K[NB * NH * LK * DH];
__device__ float g_V[NB * NH * LK * DH];
__device__ int   g_valid[NB];
__device__ float g_rscale[NB];

// ---------------- valid-length + scaling from padding mask ------------------
// The padding mask is a bool array logically (NB, LK). Depending on how the
// harness materializes bools it may be stored as uint8 (1B), int32, or float32.
// The rows are monotone (zeros then ones), which gives each storage layout a
// unique 32-bit word signature over the first 8192 bytes (safe to read in all
// layouts):
//   uint8 : words in {0, 0x01000000, 0x01010000, 0x01010100, 0x01010101}
//   int32 : words in {0, 0x00000001}
//   float : words in {0, 0x3F800000}
__global__ void valid_kernel(const void* __restrict__ pad) {
    const int tid = threadIdx.x;
    const int n   = blockIdx.x;
    __shared__ int red[256];

    // ---- layout detection (every block redundantly; cheap) ----
    const unsigned* w = (const unsigned*)pad;
    int f = 0;
    for (int i = tid; i < 2048; i += 256) {
        unsigned v = w[i];
        if (v == 0x3F800000u) f |= 4;
        else if (v == 0x00000001u) f |= 2;
        else if (v == 0x01000000u || v == 0x01010000u ||
                 v == 0x01010100u || v == 0x01010101u) f |= 1;
    }
    red[tid] = f;
    __syncthreads();
    for (int s = 128; s > 0; s >>= 1) {
        if (tid < s) red[tid] |= red[tid + s];
        __syncthreads();
    }
    const int fl = red[0];
    const int layout = (fl & 1) ? 0 : ((fl & 4) ? 2 : 1);  // 0:u8 1:i32 2:f32
    __syncthreads();

    // ---- count non-padded entries of row n ----
    int c = 0;
    if (layout == 0) {
        const unsigned char* p = (const unsigned char*)pad;
        for (int j = tid; j < LK; j += 256) c += (p[n * LK + j] == 0);
    } else if (layout == 1) {
        const int* p = (const int*)pad;
        for (int j = tid; j < LK; j += 256) c += (p[n * LK + j] == 0);
    } else {
        const float* p = (const float*)pad;
        for (int j = tid; j < LK; j += 256) c += (p[n * LK + j] == 0.0f);
    }
    red[tid] = c;
    __syncthreads();
    for (int s = 128; s > 0; s >>= 1) {
        if (tid < s) red[tid] += red[tid + s];
        __syncthreads();
    }
    if (tid == 0) {
        g_valid[n]  = red[0];
        g_rscale[n] = rsqrtf((float)red[0]);
    }
}

// ---------------- projection GEMM: Out = X @ W^T, head-split output ---------
__global__ void proj_kernel(const float* __restrict__ X,
                            const float* __restrict__ W,
                            int which /*0:Q 1:K 2:V*/) {
    float* __restrict__ Out = (which == 0) ? g_Q : (which == 1) ? g_K : g_V;

    __shared__ float As[64][17];
    __shared__ float Bs[64][17];

    const int tid = threadIdx.x;
    const int ty  = tid >> 4;
    const int tx  = tid & 15;
    const int ry  = ty << 2;
    const int cx  = tx << 2;

    const int m0 = blockIdx.y * 64;
    const int n0 = blockIdx.x * 64;

    const int lrow = tid >> 2;
    const int lc4  = (tid & 3) << 2;

    float acc[4][4];
#pragma unroll
    for (int i = 0; i < 4; i++)
#pragma unroll
        for (int j = 0; j < 4; j++) acc[i][j] = 0.f;

    for (int k0 = 0; k0 < DIM; k0 += 16) {
        float4 av = *reinterpret_cast<const float4*>(&X[(size_t)(m0 + lrow) * DIM + k0 + lc4]);
        float4 bv = *reinterpret_cast<const float4*>(&W[(size_t)(n0 + lrow) * DIM + k0 + lc4]);
        As[lrow][lc4 + 0] = av.x; As[lrow][lc4 + 1] = av.y;
        As[lrow][lc4 + 2] = av.z; As[lrow][lc4 + 3] = av.w;
        Bs[lrow][lc4 + 0] = bv.x; Bs[lrow][lc4 + 1] = bv.y;
        Bs[lrow][lc4 + 2] = bv.z; Bs[lrow][lc4 + 3] = bv.w;
        __syncthreads();

#pragma unroll
        for (int kk = 0; kk < 16; kk++) {
            float a[4], b[4];
#pragma unroll
            for (int i = 0; i < 4; i++) a[i] = As[ry + i][kk];
#pragma unroll
            for (int j = 0; j < 4; j++) b[j] = Bs[cx + j][kk];
#pragma unroll
            for (int i = 0; i < 4; i++)
#pragma unroll
                for (int j = 0; j < 4; j++)
                    acc[i][j] = fmaf(a[i], b[j], acc[i][j]);
        }
        __syncthreads();
    }

    const int h = blockIdx.x;
#pragma unroll
    for (int i = 0; i < 4; i++) {
        int m = m0 + ry + i;
        int n = m >> 11;
        int l = m & 2047;
        float* orow = &Out[(((size_t)(n * NH + h)) * LQ + l) * DH];
#pragma unroll
        for (int j = 0; j < 4; j++) orow[cx + j] = acc[i][j];
    }
}

// ---------------- flash attention, fp32, BQ=BK=64, 256 threads --------------
__global__ void attn_kernel(float* __restrict__ out) {
    extern __shared__ float sm[];
    float* Qs = sm;                 // [64][65]
    float* Ks = Qs + 64 * 65;       // [64][65]
    float* Vs = Ks + 64 * 65;       // [64][65]
    float* Ss = Vs + 64 * 65;       // [64][65]
    float* ms = Ss + 64 * 65;       // [64]
    float* ls = ms + 64;            // [64]
    float* fs = ls + 64;            // [64]

    const int tid = threadIdx.x;
    const int ty  = tid >> 4;
    const int tx  = tid & 15;
    const int ry  = ty << 2;
    const int cx  = tx << 2;

    const int q0 = blockIdx.x * 64;
    const int nh = blockIdx.y;
    const int n  = nh >> 4;
    const int h  = nh & 15;

    const int   valid  = g_valid[n];
    const float rscale = g_rscale[n];
    const int   kend   = min(valid, q0 + 64);
    const int   nkb    = (kend + 63) >> 6;

    const float* __restrict__ Qb = &g_Q[(size_t)nh * LQ * DH];
    const float* __restrict__ Kb = &g_K[(size_t)nh * LK * DH];
    const float* __restrict__ Vb = &g_V[(size_t)nh * LK * DH];

    for (int idx = tid; idx < 64 * 64; idx += 256) {
        int r = idx >> 6, c = idx & 63;
        Qs[r * 65 + c] = Qb[(size_t)(q0 + r) * DH + c];
    }
    if (tid < 64) { ms[tid] = -1e30f; ls[tid] = 0.f; }

    float oacc[4][4];
#pragma unroll
    for (int i = 0; i < 4; i++)
#pragma unroll
        for (int j = 0; j < 4; j++) oacc[i][j] = 0.f;

    for (int kb = 0; kb < nkb; kb++) {
        const int k0 = kb << 6;
        __syncthreads();

        for (int idx = tid; idx < 64 * 64; idx += 256) {
            int r = idx >> 6, c = idx & 63;
            Ks[r * 65 + c] = Kb[(size_t)(k0 + r) * DH + c];
            Vs[r * 65 + c] = Vb[(size_t)(k0 + r) * DH + c];
        }
        __syncthreads();

        float sacc[4][4];
#pragma unroll
        for (int i = 0; i < 4; i++)
#pragma unroll
            for (int j = 0; j < 4; j++) sacc[i][j] = 0.f;

#pragma unroll 8
        for (int kk = 0; kk < 64; kk++) {
            float qv[4], kv[4];
#pragma unroll
            for (int i = 0; i < 4; i++) qv[i] = Qs[(ry + i) * 65 + kk];
#pragma unroll
            for (int j = 0; j < 4; j++) kv[j] = Ks[(cx + j) * 65 + kk];
#pragma unroll
            for (int i = 0; i < 4; i++)
#pragma unroll
                for (int j = 0; j < 4; j++)
                    sacc[i][j] = fmaf(qv[i], kv[j], sacc[i][j]);
        }

#pragma unroll
        for (int i = 0; i < 4; i++) {
            int qr = q0 + ry + i;
#pragma unroll
            for (int j = 0; j < 4; j++) {
                int kc = k0 + cx + j;
                float s = (kc > qr || kc >= valid) ? -1e30f : sacc[i][j] * rscale;
                Ss[(ry + i) * 65 + cx + j] = s;
            }
        }
        __syncthreads();

        {
            int r = tid >> 2;
            int g = tid & 3;
            float* srow = &Ss[r * 65 + g * 16];
            float mloc = -1e30f;
#pragma unroll
            for (int c = 0; c < 16; c++) mloc = fmaxf(mloc, srow[c]);
            mloc = fmaxf(mloc, __shfl_xor_sync(0xffffffffu, mloc, 1));
            mloc = fmaxf(mloc, __shfl_xor_sync(0xffffffffu, mloc, 2));
            float mold = ms[r];
            float mnew = fmaxf(mold, mloc);
            float f = __expf(mold - mnew);
            float sum = 0.f;
#pragma unroll
            for (int c = 0; c < 16; c++) {
                float p = __expf(srow[c] - mnew);
                srow[c] = p;
                sum += p;
            }
            sum += __shfl_xor_sync(0xffffffffu, sum, 1);
            sum += __shfl_xor_sync(0xffffffffu, sum, 2);
            if (g == 0) {
                ms[r] = mnew;
                ls[r] = ls[r] * f + sum;
                fs[r] = f;
            }
        }
        __syncthreads();

        float frow[4];
#pragma unroll
        for (int i = 0; i < 4; i++) frow[i] = fs[ry + i];
#pragma unroll
        for (int i = 0; i < 4; i++)
#pragma unroll
            for (int j = 0; j < 4; j++) oacc[i][j] *= frow[i];

#pragma unroll 8
        for (int kk = 0; kk < 64; kk++) {
            float pv[4], vv[4];
#pragma unroll
            for (int i = 0; i < 4; i++) pv[i] = Ss[(ry + i) * 65 + kk];
#pragma unroll
            for (int j = 0; j < 4; j++) vv[j] = Vs[kk * 65 + cx + j];
#pragma unroll
            for (int i = 0; i < 4; i++)
#pragma unroll
                for (int j = 0; j < 4; j++)
                    oacc[i][j] = fmaf(pv[i], vv[j], oacc[i][j]);
        }
    }
    __syncthreads();

#pragma unroll
    for (int i = 0; i < 4; i++) {
        float inv_l = 1.0f / ls[ry + i];
        int l = q0 + ry + i;
        float* orow = &out[((size_t)n * LQ + l) * DIM + h * DH];
#pragma unroll
        for (int j = 0; j < 4; j++) orow[cx + j] = oacc[i][j] * inv_l;
    }
}

// ----------------------------- launcher -------------------------------------
extern "C" void kernel_launch(void* const* d_in, const int* in_sizes, int n_in,
                              void* d_out, int out_size) {
    const float* query = (const float*)d_in[0];
    const float* key   = (const float*)d_in[1];
    const float* Wq    = (const float*)d_in[2];
    const float* Wk    = (const float*)d_in[3];
    const float* Wv    = (const float*)d_in[4];
    // padding_mask has NB*LK = 8192 elements; causal mask has LQ*LK = 4M.
    // Select by element count so input ordering of the two masks can't bite us.
    const void* pad = (in_sizes[6] == NB * LK) ? d_in[6]
                    : (in_sizes[5] == NB * LK) ? d_in[5]
                    : d_in[6];
    float* out = (float*)d_out;

    valid_kernel<<<NB, 256>>>(pad);

    dim3 pgrid(DIM / 64, (NB * LQ) / 64);   // (16, 128)
    proj_kernel<<<pgrid, 256>>>(query, Wq, 0);
    proj_kernel<<<pgrid, 256>>>(key,   Wk, 1);
    proj_kernel<<<pgrid, 256>>>(key,   Wv, 2);

    const int smem = (4 * 64 * 65 + 3 * 64) * sizeof(float);  // ~67.3 KB
    cudaFuncSetAttribute(attn_kernel, cudaFuncAttributeMaxDynamicSharedMemorySize, smem);

    dim3 agrid(LQ / 64, NB * NH);            // (32, 64)
    attn_kernel<<<agrid, 256, smem>>>(out);
}

// round 4
// speedup vs baseline: 1.0085x; 1.0085x over previous
#include <cuda_runtime.h>
#include <cuda_bf16.h>
#include <math.h>
#include <stdint.h>

// Problem constants
#define NB   4
#define LQ   2048
#define LK   2048
#define DIM  1024
#define NH   16
#define DH   64

// ---------------- scratch (static device arrays; no allocation) -------------
__device__ float g_Q[NB * NH * LQ * DH];   // (n,h,l,dh)
__device__ float g_K[NB * NH * LK * DH];
__device__ float g_V[NB * NH * LK * DH];
__device__ int   g_valid[NB];
__device__ float g_rscale[NB];

// ======================= mma.sync helpers (sm_80+ path) =====================
__device__ __forceinline__ uint32_t smem_u32(const void* p) {
    uint32_t a;
    asm("{ .reg .u64 t; cvta.to.shared.u64 t, %1; cvt.u32.u64 %0, t; }"
        : "=r"(a) : "l"(p));
    return a;
}

__device__ __forceinline__ void ldsm4(uint32_t* r, uint32_t addr) {
    asm volatile("ldmatrix.sync.aligned.m8n8.x4.shared.b16 {%0,%1,%2,%3}, [%4];"
                 : "=r"(r[0]), "=r"(r[1]), "=r"(r[2]), "=r"(r[3]) : "r"(addr));
}

__device__ __forceinline__ void mma16816(float* d, const uint32_t* a,
                                         const uint32_t* b) {
    asm volatile(
        "mma.sync.aligned.m16n8k16.row.col.f32.bf16.bf16.f32 "
        "{%0,%1,%2,%3}, {%4,%5,%6,%7}, {%8,%9}, {%0,%1,%2,%3};"
        : "+f"(d[0]), "+f"(d[1]), "+f"(d[2]), "+f"(d[3])
        : "r"(a[0]), "r"(a[1]), "r"(a[2]), "r"(a[3]), "r"(b[0]), "r"(b[1]));
}

__device__ __forceinline__ void hilo2(float x, float y, uint32_t& h, uint32_t& l) {
    __nv_bfloat16 hx = __float2bfloat16(x);
    __nv_bfloat16 hy = __float2bfloat16(y);
    __nv_bfloat16 lx = __float2bfloat16(x - __bfloat162float(hx));
    __nv_bfloat16 ly = __float2bfloat16(y - __bfloat162float(hy));
    __nv_bfloat162 H; H.x = hx; H.y = hy;
    __nv_bfloat162 L; L.x = lx; L.y = ly;
    h = *reinterpret_cast<uint32_t*>(&H);
    l = *reinterpret_cast<uint32_t*>(&L);
}

// ---------------- valid-length + scaling from padding mask ------------------
__global__ void valid_kernel(const void* __restrict__ pad) {
    const int tid = threadIdx.x;
    const int n   = blockIdx.x;
    __shared__ int red[256];

    const unsigned* w = (const unsigned*)pad;
    int f = 0;
    for (int i = tid; i < 2048; i += 256) {
        unsigned v = w[i];
        if (v == 0x3F800000u) f |= 4;
        else if (v == 0x00000001u) f |= 2;
        else if (v == 0x01000000u || v == 0x01010000u ||
                 v == 0x01010100u || v == 0x01010101u) f |= 1;
    }
    red[tid] = f;
    __syncthreads();
    for (int s = 128; s > 0; s >>= 1) {
        if (tid < s) red[tid] |= red[tid + s];
        __syncthreads();
    }
    const int fl = red[0];
    const int layout = (fl & 1) ? 0 : ((fl & 4) ? 2 : 1);
    __syncthreads();

    int c = 0;
    if (layout == 0) {
        const unsigned char* p = (const unsigned char*)pad;
        for (int j = tid; j < LK; j += 256) c += (p[n * LK + j] == 0);
    } else if (layout == 1) {
        const int* p = (const int*)pad;
        for (int j = tid; j < LK; j += 256) c += (p[n * LK + j] == 0);
    } else {
        const float* p = (const float*)pad;
        for (int j = tid; j < LK; j += 256) c += (p[n * LK + j] == 0.0f);
    }
    red[tid] = c;
    __syncthreads();
    for (int s = 128; s > 0; s >>= 1) {
        if (tid < s) red[tid] += red[tid + s];
        __syncthreads();
    }
    if (tid == 0) {
        g_valid[n]  = red[0];
        g_rscale[n] = rsqrtf((float)red[0]);
    }
}

// ============ HMMA projection: Out = X @ W^T (bf16 hi/lo, 3 passes) =========
// Block: 128x128 tile, BK=32, 256 threads (8 warps of 64x32).
// smem rows padded to 40 bf16 (80B) -> conflict-free ldmatrix.
#define SKT   40                         // bf16 elements per smem row
#define TB    (128 * SKT * 2)            // bytes per tile buffer (10240)
// layout: AH[2] AL[2] BH[2] BL[2]
#define OFF_AH(b) ((b) * TB)
#define OFF_AL(b) (2 * TB + (b) * TB)
#define OFF_BH(b) (4 * TB + (b) * TB)
#define OFF_BL(b) (6 * TB + (b) * TB)
#define PROJ_SMEM (8 * TB)               // 81920 bytes

__global__ __launch_bounds__(256, 1)
void proj_mma_kernel(const float* __restrict__ Xq, const float* __restrict__ Xk,
                     const float* __restrict__ Wq, const float* __restrict__ Wk,
                     const float* __restrict__ Wv) {
    extern __shared__ char smem[];
    const uint32_t sb = smem_u32(smem);

    const int tid  = threadIdx.x;
    const int wid  = tid >> 5;
    const int lane = tid & 31;

    const int which = blockIdx.z;
    const float* __restrict__ X = (which == 0) ? Xq : Xk;
    const float* __restrict__ W = (which == 0) ? Wq : (which == 1) ? Wk : Wv;
    float* __restrict__ Out = (which == 0) ? g_Q : (which == 1) ? g_K : g_V;

    const int m0B = blockIdx.y * 128;
    const int n0B = blockIdx.x * 128;

    const int m0W = (wid >> 2) * 64;
    const int n0W = (wid & 3) * 32;

    // global load mapping: 2 chunks per matrix per thread; each chunk = 8 floats
    const int s0   = tid;          // slots 0..255 then +256
    // slot -> row = slot>>2 (0..127), c8 = slot&3 (k-offset = c8*8)

    float4 fa[2][2], fb[2][2];

    auto load_stage = [&](int kbase) {
#pragma unroll
        for (int ca = 0; ca < 2; ca++) {
            int slot = s0 + ca * 256;
            int r = slot >> 2, c8 = slot & 3;
            const float* pa = &X[(size_t)(m0B + r) * DIM + kbase + c8 * 8];
            fa[ca][0] = *reinterpret_cast<const float4*>(pa);
            fa[ca][1] = *reinterpret_cast<const float4*>(pa + 4);
            const float* pb = &W[(size_t)(n0B + r) * DIM + kbase + c8 * 8];
            fb[ca][0] = *reinterpret_cast<const float4*>(pb);
            fb[ca][1] = *reinterpret_cast<const float4*>(pb + 4);
        }
    };

    auto store_stage = [&](int buf) {
#pragma unroll
        for (int ca = 0; ca < 2; ca++) {
            int slot = s0 + ca * 256;
            int r = slot >> 2, c8 = slot & 3;
            int boff = r * (SKT * 2) + c8 * 16;     // bytes
            uint4 H, L;
            hilo2(fa[ca][0].x, fa[ca][0].y, H.x, L.x);
            hilo2(fa[ca][0].z, fa[ca][0].w, H.y, L.y);
            hilo2(fa[ca][1].x, fa[ca][1].y, H.z, L.z);
            hilo2(fa[ca][1].z, fa[ca][1].w, H.w, L.w);
            *reinterpret_cast<uint4*>(smem + OFF_AH(buf) + boff) = H;
            *reinterpret_cast<uint4*>(smem + OFF_AL(buf) + boff) = L;
            hilo2(fb[ca][0].x, fb[ca][0].y, H.x, L.x);
            hilo2(fb[ca][0].z, fb[ca][0].w, H.y, L.y);
            hilo2(fb[ca][1].x, fb[ca][1].y, H.z, L.z);
            hilo2(fb[ca][1].z, fb[ca][1].w, H.w, L.w);
            *reinterpret_cast<uint4*>(smem + OFF_BH(buf) + boff) = H;
            *reinterpret_cast<uint4*>(smem + OFF_BL(buf) + boff) = L;
        }
    };

    float acc[4][4][4];
#pragma unroll
    for (int mt = 0; mt < 4; mt++)
#pragma unroll
        for (int nt = 0; nt < 4; nt++)
#pragma unroll
            for (int q = 0; q < 4; q++) acc[mt][nt][q] = 0.f;

    // ldmatrix lane addressing (byte offsets within a tile buffer)
    const int rA   = m0W + (lane & 15);
    const int cA   = (lane >> 4) * 8;
    const int grp  = lane >> 3;
    const int rB0  = n0W + ((grp >> 1) * 8) + (lane & 7);
    const int cB   = (grp & 1) * 8;
    const int aoff = rA * (SKT * 2) + cA * 2;
    const int boff0 = rB0 * (SKT * 2) + cB * 2;

    load_stage(0);
    store_stage(0);
    __syncthreads();

    int buf = 0;
    for (int it = 0; it < 32; it++) {
        if (it < 31) load_stage((it + 1) * 32);

        const uint32_t aH = sb + OFF_AH(buf) + aoff;
        const uint32_t aL = sb + OFF_AL(buf) + aoff;
        const uint32_t bH = sb + OFF_BH(buf) + boff0;
        const uint32_t bL = sb + OFF_BL(buf) + boff0;

#pragma unroll
        for (int ks = 0; ks < 2; ks++) {
            const int kb = ks * 16 * 2;   // byte offset of k-step
            uint32_t ah[4][4], al[4][4], bh[4][2], bl[4][2];
#pragma unroll
            for (int mt = 0; mt < 4; mt++) {
                ldsm4(ah[mt], aH + mt * 16 * (SKT * 2) + kb);
                ldsm4(al[mt], aL + mt * 16 * (SKT * 2) + kb);
            }
#pragma unroll
            for (int bt = 0; bt < 2; bt++) {
                uint32_t t[4];
                ldsm4(t, bH + bt * 16 * (SKT * 2) + kb);
                bh[bt * 2][0] = t[0]; bh[bt * 2][1] = t[1];
                bh[bt * 2 + 1][0] = t[2]; bh[bt * 2 + 1][1] = t[3];
                ldsm4(t, bL + bt * 16 * (SKT * 2) + kb);
                bl[bt * 2][0] = t[0]; bl[bt * 2][1] = t[1];
                bl[bt * 2 + 1][0] = t[2]; bl[bt * 2 + 1][1] = t[3];
            }
#pragma unroll
            for (int mt = 0; mt < 4; mt++)
#pragma unroll
                for (int nt = 0; nt < 4; nt++)
                    mma16816(acc[mt][nt], ah[mt], bh[nt]);
#pragma unroll
            for (int mt = 0; mt < 4; mt++)
#pragma unroll
                for (int nt = 0; nt < 4; nt++)
                    mma16816(acc[mt][nt], ah[mt], bl[nt]);
#pragma unroll
            for (int mt = 0; mt < 4; mt++)
#pragma unroll
                for (int nt = 0; nt < 4; nt++)
                    mma16816(acc[mt][nt], al[mt], bh[nt]);
        }

        if (it < 31) {
            store_stage(buf ^ 1);
            __syncthreads();
        }
        buf ^= 1;
    }

    // Epilogue: c-frag layout -> head-split global store (float2 per pair)
    const int rr = lane >> 2;
    const int cc = (lane & 3) * 2;
#pragma unroll
    for (int mt = 0; mt < 4; mt++) {
#pragma unroll
        for (int half = 0; half < 2; half++) {
            const int m = m0B + m0W + mt * 16 + rr + half * 8;
            const int n = m >> 11;
            const int l = m & 2047;
            float* obase = &Out[((size_t)(n * NH) * LQ + l) * DH];
#pragma unroll
            for (int nt = 0; nt < 4; nt++) {
                const int j = n0B + n0W + nt * 8 + cc;
                const int h = j >> 6;
                const int dh = j & 63;
                float2 v;
                v.x = acc[mt][nt][half * 2 + 0];
                v.y = acc[mt][nt][half * 2 + 1];
                *reinterpret_cast<float2*>(&obase[(size_t)h * LQ * DH + dh]) = v;
            }
        }
    }
}

// ---------------- flash attention, fp32, BQ=BK=64, 256 threads --------------
__global__ void attn_kernel(float* __restrict__ out) {
    extern __shared__ float sm[];
    float* Qs = sm;                 // [64][65]
    float* Ks = Qs + 64 * 65;       // [64][65]
    float* Vs = Ks + 64 * 65;       // [64][65]
    float* Ss = Vs + 64 * 65;       // [64][65]
    float* ms = Ss + 64 * 65;       // [64]
    float* ls = ms + 64;            // [64]
    float* fs = ls + 64;            // [64]

    const int tid = threadIdx.x;
    const int ty  = tid >> 4;
    const int tx  = tid & 15;
    const int ry  = ty << 2;
    const int cx  = tx << 2;

    const int q0 = blockIdx.x * 64;
    const int nh = blockIdx.y;
    const int n  = nh >> 4;
    const int h  = nh & 15;

    const int   valid  = g_valid[n];
    const float rscale = g_rscale[n];
    const int   kend   = min(valid, q0 + 64);
    const int   nkb    = (kend + 63) >> 6;

    const float* __restrict__ Qb = &g_Q[(size_t)nh * LQ * DH];
    const float* __restrict__ Kb = &g_K[(size_t)nh * LK * DH];
    const float* __restrict__ Vb = &g_V[(size_t)nh * LK * DH];

    for (int idx = tid; idx < 64 * 64; idx += 256) {
        int r = idx >> 6, c = idx & 63;
        Qs[r * 65 + c] = Qb[(size_t)(q0 + r) * DH + c];
    }
    if (tid < 64) { ms[tid] = -1e30f; ls[tid] = 0.f; }

    float oacc[4][4];
#pragma unroll
    for (int i = 0; i < 4; i++)
#pragma unroll
        for (int j = 0; j < 4; j++) oacc[i][j] = 0.f;

    for (int kb = 0; kb < nkb; kb++) {
        const int k0 = kb << 6;
        __syncthreads();

        for (int idx = tid; idx < 64 * 64; idx += 256) {
            int r = idx >> 6, c = idx & 63;
            Ks[r * 65 + c] = Kb[(size_t)(k0 + r) * DH + c];
            Vs[r * 65 + c] = Vb[(size_t)(k0 + r) * DH + c];
        }
        __syncthreads();

        float sacc[4][4];
#pragma unroll
        for (int i = 0; i < 4; i++)
#pragma unroll
            for (int j = 0; j < 4; j++) sacc[i][j] = 0.f;

#pragma unroll 8
        for (int kk = 0; kk < 64; kk++) {
            float qv[4], kv[4];
#pragma unroll
            for (int i = 0; i < 4; i++) qv[i] = Qs[(ry + i) * 65 + kk];
#pragma unroll
            for (int j = 0; j < 4; j++) kv[j] = Ks[(cx + j) * 65 + kk];
#pragma unroll
            for (int i = 0; i < 4; i++)
#pragma unroll
                for (int j = 0; j < 4; j++)
                    sacc[i][j] = fmaf(qv[i], kv[j], sacc[i][j]);
        }

#pragma unroll
        for (int i = 0; i < 4; i++) {
            int qr = q0 + ry + i;
#pragma unroll
            for (int j = 0; j < 4; j++) {
                int kc = k0 + cx + j;
                float s = (kc > qr || kc >= valid) ? -1e30f : sacc[i][j] * rscale;
                Ss[(ry + i) * 65 + cx + j] = s;
            }
        }
        __syncthreads();

        {
            int r = tid >> 2;
            int g = tid & 3;
            float* srow = &Ss[r * 65 + g * 16];
            float mloc = -1e30f;
#pragma unroll
            for (int c = 0; c < 16; c++) mloc = fmaxf(mloc, srow[c]);
            mloc = fmaxf(mloc, __shfl_xor_sync(0xffffffffu, mloc, 1));
            mloc = fmaxf(mloc, __shfl_xor_sync(0xffffffffu, mloc, 2));
            float mold = ms[r];
            float mnew = fmaxf(mold, mloc);
            float f = __expf(mold - mnew);
            float sum = 0.f;
#pragma unroll
            for (int c = 0; c < 16; c++) {
                float p = __expf(srow[c] - mnew);
                srow[c] = p;
                sum += p;
            }
            sum += __shfl_xor_sync(0xffffffffu, sum, 1);
            sum += __shfl_xor_sync(0xffffffffu, sum, 2);
            if (g == 0) {
                ms[r] = mnew;
                ls[r] = ls[r] * f + sum;
                fs[r] = f;
            }
        }
        __syncthreads();

        float frow[4];
#pragma unroll
        for (int i = 0; i < 4; i++) frow[i] = fs[ry + i];
#pragma unroll
        for (int i = 0; i < 4; i++)
#pragma unroll
            for (int j = 0; j < 4; j++) oacc[i][j] *= frow[i];

#pragma unroll 8
        for (int kk = 0; kk < 64; kk++) {
            float pv[4], vv[4];
#pragma unroll
            for (int i = 0; i < 4; i++) pv[i] = Ss[(ry + i) * 65 + kk];
#pragma unroll
            for (int j = 0; j < 4; j++) vv[j] = Vs[kk * 65 + cx + j];
#pragma unroll
            for (int i = 0; i < 4; i++)
#pragma unroll
                for (int j = 0; j < 4; j++)
                    oacc[i][j] = fmaf(pv[i], vv[j], oacc[i][j]);
        }
    }
    __syncthreads();

#pragma unroll
    for (int i = 0; i < 4; i++) {
        float inv_l = 1.0f / ls[ry + i];
        int l = q0 + ry + i;
        float* orow = &out[((size_t)n * LQ + l) * DIM + h * DH];
#pragma unroll
        for (int j = 0; j < 4; j++) orow[cx + j] = oacc[i][j] * inv_l;
    }
}

// ----------------------------- launcher -------------------------------------
extern "C" void kernel_launch(void* const* d_in, const int* in_sizes, int n_in,
                              void* d_out, int out_size) {
    const float* query = (const float*)d_in[0];
    const float* key   = (const float*)d_in[1];
    const float* Wq    = (const float*)d_in[2];
    const float* Wk    = (const float*)d_in[3];
    const float* Wv    = (const float*)d_in[4];
    const void* pad = (in_sizes[6] == NB * LK) ? d_in[6]
                    : (in_sizes[5] == NB * LK) ? d_in[5]
                    : d_in[6];
    float* out = (float*)d_out;

    valid_kernel<<<NB, 256>>>(pad);

    cudaFuncSetAttribute(proj_mma_kernel,
                         cudaFuncAttributeMaxDynamicSharedMemorySize, PROJ_SMEM);
    dim3 pgrid(DIM / 128, (NB * LQ) / 128, 3);   // (8, 64, 3)
    proj_mma_kernel<<<pgrid, 256, PROJ_SMEM>>>(query, key, Wq, Wk, Wv);

    const int smem = (4 * 64 * 65 + 3 * 64) * sizeof(float);  // ~67.3 KB
    cudaFuncSetAttribute(attn_kernel, cudaFuncAttributeMaxDynamicSharedMemorySize, smem);

    dim3 agrid(LQ / 64, NB * NH);            // (32, 64)
    attn_kernel<<<agrid, 256, smem>>>(out);
}

// round 7
// speedup vs baseline: 3.2553x; 3.2278x over previous
#include <cuda_runtime.h>
#include <cuda_fp16.h>
#include <math.h>
#include <stdint.h>

#define NB   4
#define LQ   2048
#define LK   2048
#define DIM  1024
#define NH   16
#define DH   64

// ---------------- scratch (static device arrays; no allocation) -------------
__device__ __half g_Xqh[NB * LQ * DIM];
__device__ __half g_Xql[NB * LQ * DIM];
__device__ __half g_Xkh[NB * LK * DIM];
__device__ __half g_Xkl[NB * LK * DIM];
__device__ __half g_Wh[3 * DIM * DIM];
__device__ __half g_Wl[3 * DIM * DIM];
__device__ __half g_Qh[NB * NH * LQ * DH];
__device__ __half g_Ql[NB * NH * LQ * DH];
__device__ __half g_Kh[NB * NH * LK * DH];
__device__ __half g_Kl[NB * NH * LK * DH];
__device__ __half g_Vh[NB * NH * LK * DH];
__device__ __half g_Vl[NB * NH * LK * DH];
__device__ int   g_valid[NB];
__device__ float g_rscale[NB];

// ========================= low-level helpers ================================
__device__ __forceinline__ uint32_t smem_u32(const void* p) {
    uint32_t a;
    asm("{ .reg .u64 t; cvta.to.shared.u64 t, %1; cvt.u32.u64 %0, t; }"
        : "=r"(a) : "l"(p));
    return a;
}

__device__ __forceinline__ void cpa16(uint32_t dst, const void* src) {
    asm volatile("cp.async.cg.shared.global [%0], [%1], 16;"
                 :: "r"(dst), "l"(src) : "memory");
}
#define CP_COMMIT() asm volatile("cp.async.commit_group;" ::: "memory")
#define CP_WAIT1()  asm volatile("cp.async.wait_group 1;" ::: "memory")

__device__ __forceinline__ void ldsm4(uint32_t* r, uint32_t addr) {
    asm volatile("ldmatrix.sync.aligned.m8n8.x4.shared.b16 {%0,%1,%2,%3}, [%4];"
                 : "=r"(r[0]), "=r"(r[1]), "=r"(r[2]), "=r"(r[3]) : "r"(addr));
}
__device__ __forceinline__ void ldsm4t(uint32_t* r, uint32_t addr) {
    asm volatile("ldmatrix.sync.aligned.m8n8.x4.trans.shared.b16 {%0,%1,%2,%3}, [%4];"
                 : "=r"(r[0]), "=r"(r[1]), "=r"(r[2]), "=r"(r[3]) : "r"(addr));
}

__device__ __forceinline__ void mma16816(float* d, const uint32_t* a,
                                         const uint32_t* b) {
    asm volatile(
        "mma.sync.aligned.m16n8k16.row.col.f32.f16.f16.f32 "
        "{%0,%1,%2,%3}, {%4,%5,%6,%7}, {%8,%9}, {%0,%1,%2,%3};"
        : "+f"(d[0]), "+f"(d[1]), "+f"(d[2]), "+f"(d[3])
        : "r"(a[0]), "r"(a[1]), "r"(a[2]), "r"(a[3]), "r"(b[0]), "r"(b[1]));
}

__device__ __forceinline__ void hilo_h2(float a, float b, uint32_t& h, uint32_t& l) {
    __half ha = __float2half_rn(a);
    __half hb = __float2half_rn(b);
    float ra = a - __half2float(ha);
    float rb = b - __half2float(hb);
    __half2 H = __halves2half2(ha, hb);
    __half2 L = __floats2half2_rn(ra, rb);
    h = *reinterpret_cast<uint32_t*>(&H);
    l = *reinterpret_cast<uint32_t*>(&L);
}

// ---------------- valid-length + scaling from padding mask ------------------
__global__ void valid_kernel(const void* __restrict__ pad) {
    const int tid = threadIdx.x;
    const int n   = blockIdx.x;
    __shared__ int red[256];

    const unsigned* w = (const unsigned*)pad;
    int f = 0;
    for (int i = tid; i < 2048; i += 256) {
        unsigned v = w[i];
        if (v == 0x3F800000u) f |= 4;
        else if (v == 0x00000001u) f |= 2;
        else if (v == 0x01000000u || v == 0x01010000u ||
                 v == 0x01010100u || v == 0x01010101u) f |= 1;
    }
    red[tid] = f;
    __syncthreads();
    for (int s = 128; s > 0; s >>= 1) {
        if (tid < s) red[tid] |= red[tid + s];
        __syncthreads();
    }
    const int fl = red[0];
    const int layout = (fl & 1) ? 0 : ((fl & 4) ? 2 : 1);
    __syncthreads();

    int c = 0;
    if (layout == 0) {
        const unsigned char* p = (const unsigned char*)pad;
        for (int j = tid; j < LK; j += 256) c += (p[n * LK + j] == 0);
    } else if (layout == 1) {
        const int* p = (const int*)pad;
        for (int j = tid; j < LK; j += 256) c += (p[n * LK + j] == 0);
    } else {
        const float* p = (const float*)pad;
        for (int j = tid; j < LK; j += 256) c += (p[n * LK + j] == 0.0f);
    }
    red[tid] = c;
    __syncthreads();
    for (int s = 128; s > 0; s >>= 1) {
        if (tid < s) red[tid] += red[tid + s];
        __syncthreads();
    }
    if (tid == 0) {
        g_valid[n]  = red[0];
        g_rscale[n] = rsqrtf((float)red[0]);
    }
}

// ---------------- one-shot f32 -> fp16 hi/lo conversion ---------------------
__global__ void cvt_kernel(const float* __restrict__ src,
                           __half* __restrict__ dh, __half* __restrict__ dl,
                           int n) {
    int i = (blockIdx.x * blockDim.x + threadIdx.x) * 8;
    if (i >= n) return;
    float4 a = *reinterpret_cast<const float4*>(src + i);
    float4 b = *reinterpret_cast<const float4*>(src + i + 4);
    uint4 H, L;
    hilo_h2(a.x, a.y, H.x, L.x);
    hilo_h2(a.z, a.w, H.y, L.y);
    hilo_h2(b.x, b.y, H.z, L.z);
    hilo_h2(b.z, b.w, H.w, L.w);
    *reinterpret_cast<uint4*>(dh + i) = H;
    *reinterpret_cast<uint4*>(dl + i) = L;
}

// ============ HMMA projection: Out = X @ W^T (fp16 hi/lo, 3 passes) =========
#define PSTR    40
#define PROWB   (PSTR * 2)               // 80 bytes
#define PMATB   (128 * PROWB)            // 10240 bytes per matrix tile
#define PSTGB   (4 * PMATB)              // 40960 per stage (Ah,Al,Bh,Bl)
#define PSMEM   (2 * PSTGB)              // 81920

__global__ __launch_bounds__(256, 1)
void proj_mma_kernel(int dummy) {
    extern __shared__ char smem[];
    const uint32_t sb = smem_u32(smem);

    const int tid  = threadIdx.x;
    const int wid  = tid >> 5;
    const int lane = tid & 31;
    const int grp  = lane >> 3;

    const int which = blockIdx.z;
    const __half* __restrict__ XH = (which == 0) ? g_Xqh : g_Xkh;
    const __half* __restrict__ XL = (which == 0) ? g_Xql : g_Xkl;
    const __half* __restrict__ WH = g_Wh + (size_t)which * DIM * DIM;
    const __half* __restrict__ WL = g_Wl + (size_t)which * DIM * DIM;
    __half* __restrict__ OutH = (which == 0) ? g_Qh : (which == 1) ? g_Kh : g_Vh;
    __half* __restrict__ OutL = (which == 0) ? g_Ql : (which == 1) ? g_Kl : g_Vl;

    const int m0B = blockIdx.y * 128;
    const int n0B = blockIdx.x * 128;
    const int m0W = (wid >> 2) * 64;
    const int n0W = (wid & 3) * 32;

    // stage loader: explicit buffer + k-offset (never an empty commit group).
    // 128 rows x 32 halfs (64B) per matrix = 4 chunks/row -> complete coverage.
    auto load_stage = [&](int buf, int k0) {
        const uint32_t bo = sb + buf * PSTGB;
#pragma unroll
        for (int hp = 0; hp < 2; hp++) {
            int slot = tid + hp * 256;
            int r  = slot >> 2;
            int cc = slot & 3;
            uint32_t d = bo + r * PROWB + cc * 16;
            size_t ga = (size_t)(m0B + r) * DIM + k0 + cc * 8;
            size_t gb = (size_t)(n0B + r) * DIM + k0 + cc * 8;
            cpa16(d + 0 * PMATB, XH + ga);
            cpa16(d + 1 * PMATB, XL + ga);
            cpa16(d + 2 * PMATB, WH + gb);
            cpa16(d + 3 * PMATB, WL + gb);
        }
    };

    float acc[4][4][4];
#pragma unroll
    for (int mt = 0; mt < 4; mt++)
#pragma unroll
        for (int nt = 0; nt < 4; nt++)
#pragma unroll
            for (int q = 0; q < 4; q++) acc[mt][nt][q] = 0.f;

    const int aoff = (m0W + (lane & 15)) * PROWB + (lane >> 4) * 16;
    const int boff = (n0W + (grp >> 1) * 8 + (lane & 7)) * PROWB + (grp & 1) * 16;

    load_stage(0, 0);  CP_COMMIT();
    load_stage(1, 32); CP_COMMIT();

    for (int it = 0; it < 32; it++) {
        CP_WAIT1();
        __syncthreads();
        const uint32_t bo = sb + (it & 1) * PSTGB;
        const uint32_t aH = bo + 0 * PMATB + aoff;
        const uint32_t aL = bo + 1 * PMATB + aoff;
        const uint32_t bH = bo + 2 * PMATB + boff;
        const uint32_t bL = bo + 3 * PMATB + boff;

#pragma unroll
        for (int ks = 0; ks < 2; ks++) {
            const int kb = ks * 32;
            uint32_t ah[4][4], al[4][4], bh[4][2], bl[4][2];
#pragma unroll
            for (int mt = 0; mt < 4; mt++) {
                ldsm4(ah[mt], aH + mt * 16 * PROWB + kb);
                ldsm4(al[mt], aL + mt * 16 * PROWB + kb);
            }
#pragma unroll
            for (int bt = 0; bt < 2; bt++) {
                uint32_t t[4];
                ldsm4(t, bH + bt * 16 * PROWB + kb);
                bh[bt * 2][0] = t[0]; bh[bt * 2][1] = t[1];
                bh[bt * 2 + 1][0] = t[2]; bh[bt * 2 + 1][1] = t[3];
                ldsm4(t, bL + bt * 16 * PROWB + kb);
                bl[bt * 2][0] = t[0]; bl[bt * 2][1] = t[1];
                bl[bt * 2 + 1][0] = t[2]; bl[bt * 2 + 1][1] = t[3];
            }
#pragma unroll
            for (int mt = 0; mt < 4; mt++)
#pragma unroll
                for (int nt = 0; nt < 4; nt++) {
                    mma16816(acc[mt][nt], ah[mt], bh[nt]);
                    mma16816(acc[mt][nt], ah[mt], bl[nt]);
                    mma16816(acc[mt][nt], al[mt], bh[nt]);
                }
        }
        __syncthreads();
        const int ns = (it + 2 < 32) ? (it + 2) : 31;
        load_stage((it + 2) & 1, ns * 32);
        CP_COMMIT();
    }

    const int rr  = lane >> 2;
    const int cc2 = (lane & 3) * 2;
#pragma unroll
    for (int mt = 0; mt < 4; mt++) {
#pragma unroll
        for (int hp = 0; hp < 2; hp++) {
            const int m = m0B + m0W + mt * 16 + rr + hp * 8;
            const int n = m >> 11;
            const int l = m & 2047;
            const size_t rowb = ((size_t)(n * NH) * LQ + l) * DH;
#pragma unroll
            for (int nt = 0; nt < 4; nt++) {
                const int j  = n0B + n0W + nt * 8 + cc2;
                const int h  = j >> 6;
                const int dh = j & 63;
                uint32_t H, L;
                hilo_h2(acc[mt][nt][hp * 2 + 0], acc[mt][nt][hp * 2 + 1], H, L);
                const size_t o = rowb + (size_t)h * LQ * DH + dh;
                *reinterpret_cast<uint32_t*>(&OutH[o]) = H;
                *reinterpret_cast<uint32_t*>(&OutL[o]) = L;
            }
        }
    }
}

// ================= FA2 attention, fp16 HMMA hi/lo 3-pass ====================
#define ASTR    72
#define AROWB   (ASTR * 2)               // 144 bytes
#define AQB     (128 * AROWB)            // 18432 per Q matrix
#define AKB     (64 * AROWB)             // 9216 per K/V matrix
#define ASTG0   (2 * AQB)
#define ASTGB   (4 * AKB)                // 36864 per stage
#define ASMEM   (ASTG0 + 2 * ASTGB)      // 110592

__global__ __launch_bounds__(256, 1)
void attn_mma_kernel(float* __restrict__ out) {
    extern __shared__ char smem[];
    const uint32_t sb = smem_u32(smem);

    const int tid  = threadIdx.x;
    const int wid  = tid >> 5;
    const int lane = tid & 31;
    const int grp  = lane >> 3;

    const int q0 = blockIdx.x * 128;
    const int nh = blockIdx.y;
    const int n  = nh >> 4;
    const int h  = nh & 15;

    const int   valid  = g_valid[n];
    const float rscale = g_rscale[n];
    const int   kend   = min(valid, q0 + 128);
    const int   nkb    = (kend + 63) >> 6;   // >= 2 always (valid >= 1024)

    const size_t base = (size_t)nh * LK * DH;
    const __half* __restrict__ Qhb = g_Qh + base;
    const __half* __restrict__ Qlb = g_Ql + base;
    const __half* __restrict__ Khb = g_Kh + base;
    const __half* __restrict__ Klb = g_Kl + base;
    const __half* __restrict__ Vhb = g_Vh + base;
    const __half* __restrict__ Vlb = g_Vl + base;

    // Q: 2 matrices x 128 rows x 64 halfs = 2048 x 16B chunks -> 8 per thread
    auto load_q = [&]() {
#pragma unroll
        for (int i = 0; i < 8; i++) {
            int c   = tid + i * 256;          // 0..2047
            int mat = c >> 10;                // 0: hi, 1: lo
            int r   = (c >> 3) & 127;
            int cc  = c & 7;
            const __half* src = (mat ? Qlb : Qhb) + (size_t)(q0 + r) * DH + cc * 8;
            cpa16(sb + mat * AQB + r * AROWB + cc * 16, src);
        }
    };
    // KV: 4 matrices x 64 rows x 64 halfs = 2048 x 16B chunks -> 8 per thread
    auto load_kv = [&](int buf, int kb) {
        const int k0 = kb * 64;
        const uint32_t so = sb + ASTG0 + buf * ASTGB;
#pragma unroll
        for (int i = 0; i < 8; i++) {
            int c   = tid + i * 256;          // 0..2047
            int mat = c >> 9;                 // 0:Kh 1:Kl 2:Vh 3:Vl
            int r   = (c >> 3) & 63;
            int cc  = c & 7;
            const __half* src =
                (mat == 0) ? Khb : (mat == 1) ? Klb : (mat == 2) ? Vhb : Vlb;
            src += (size_t)(k0 + r) * DH + cc * 8;
            cpa16(so + mat * AKB + r * AROWB + cc * 16, src);
        }
    };

    const int wq0 = wid * 16;
    const int r0  = lane >> 2;
    const int qr0 = q0 + wq0 + r0;
    const int qr1 = qr0 + 8;

    const int qoff = (wq0 + (lane & 15)) * AROWB + (lane >> 4) * 16;
    const int koff = ((grp >> 1) * 8 + (lane & 7)) * AROWB + (grp & 1) * 16;
    const int voff = ((grp & 1) * 8 + (lane & 7)) * AROWB + (grp >> 1) * 16;

    uint32_t qh[4][4], ql[4][4];
    float o[8][4];
#pragma unroll
    for (int nt = 0; nt < 8; nt++)
#pragma unroll
        for (int q = 0; q < 4; q++) o[nt][q] = 0.f;
    float m0 = -1e30f, m1 = -1e30f, l0 = 0.f, l1 = 0.f;

    load_q();
    load_kv(0, 0);
    CP_COMMIT();
    load_kv(1, (nkb > 1) ? 1 : 0);
    CP_COMMIT();

    for (int kb = 0; kb < nkb; kb++) {
        CP_WAIT1();
        __syncthreads();
        const int k0 = kb * 64;
        const uint32_t so = sb + ASTG0 + (kb & 1) * ASTGB;

        if (kb == 0) {
#pragma unroll
            for (int kt = 0; kt < 4; kt++) {
                ldsm4(qh[kt], sb + 0 * AQB + qoff + kt * 32);
                ldsm4(ql[kt], sb + 1 * AQB + qoff + kt * 32);
            }
        }

        // ---- S = Q K^T (3-pass) ----
        float sc[8][4];
#pragma unroll
        for (int nt = 0; nt < 8; nt++)
#pragma unroll
            for (int q = 0; q < 4; q++) sc[nt][q] = 0.f;

#pragma unroll
        for (int kt = 0; kt < 4; kt++) {
            uint32_t bh[8][2], bl[8][2];
#pragma unroll
            for (int bt = 0; bt < 4; bt++) {
                uint32_t t[4];
                ldsm4(t, so + 0 * AKB + koff + bt * 16 * AROWB + kt * 32);
                bh[bt * 2][0] = t[0]; bh[bt * 2][1] = t[1];
                bh[bt * 2 + 1][0] = t[2]; bh[bt * 2 + 1][1] = t[3];
                ldsm4(t, so + 1 * AKB + koff + bt * 16 * AROWB + kt * 32);
                bl[bt * 2][0] = t[0]; bl[bt * 2][1] = t[1];
                bl[bt * 2 + 1][0] = t[2]; bl[bt * 2 + 1][1] = t[3];
            }
#pragma unroll
            for (int nt = 0; nt < 8; nt++) {
                mma16816(sc[nt], qh[kt], bh[nt]);
                mma16816(sc[nt], qh[kt], bl[nt]);
                mma16816(sc[nt], ql[kt], bh[nt]);
            }
        }

        // ---- mask + scale ----
#pragma unroll
        for (int nt = 0; nt < 8; nt++) {
            const int kc = k0 + nt * 8 + (lane & 3) * 2;
            sc[nt][0] = (kc     > qr0 || kc     >= valid) ? -1e30f : sc[nt][0] * rscale;
            sc[nt][1] = (kc + 1 > qr0 || kc + 1 >= valid) ? -1e30f : sc[nt][1] * rscale;
            sc[nt][2] = (kc     > qr1 || kc     >= valid) ? -1e30f : sc[nt][2] * rscale;
            sc[nt][3] = (kc + 1 > qr1 || kc + 1 >= valid) ? -1e30f : sc[nt][3] * rscale;
        }

        // ---- online softmax ----
        float mx0 = -1e30f, mx1 = -1e30f;
#pragma unroll
        for (int nt = 0; nt < 8; nt++) {
            mx0 = fmaxf(mx0, fmaxf(sc[nt][0], sc[nt][1]));
            mx1 = fmaxf(mx1, fmaxf(sc[nt][2], sc[nt][3]));
        }
        mx0 = fmaxf(mx0, __shfl_xor_sync(0xffffffffu, mx0, 1));
        mx0 = fmaxf(mx0, __shfl_xor_sync(0xffffffffu, mx0, 2));
        mx1 = fmaxf(mx1, __shfl_xor_sync(0xffffffffu, mx1, 1));
        mx1 = fmaxf(mx1, __shfl_xor_sync(0xffffffffu, mx1, 2));
        const float mn0 = fmaxf(m0, mx0);
        const float mn1 = fmaxf(m1, mx1);
        const float f0 = __expf(m0 - mn0);
        const float f1 = __expf(m1 - mn1);
        m0 = mn0; m1 = mn1;

        float s0 = 0.f, s1 = 0.f;
#pragma unroll
        for (int nt = 0; nt < 8; nt++) {
            sc[nt][0] = __expf(sc[nt][0] - mn0);
            sc[nt][1] = __expf(sc[nt][1] - mn0);
            sc[nt][2] = __expf(sc[nt][2] - mn1);
            sc[nt][3] = __expf(sc[nt][3] - mn1);
            s0 += sc[nt][0] + sc[nt][1];
            s1 += sc[nt][2] + sc[nt][3];
        }
        s0 += __shfl_xor_sync(0xffffffffu, s0, 1);
        s0 += __shfl_xor_sync(0xffffffffu, s0, 2);
        s1 += __shfl_xor_sync(0xffffffffu, s1, 1);
        s1 += __shfl_xor_sync(0xffffffffu, s1, 2);
        l0 = l0 * f0 + s0;
        l1 = l1 * f1 + s1;

#pragma unroll
        for (int nt = 0; nt < 8; nt++) {
            o[nt][0] *= f0; o[nt][1] *= f0;
            o[nt][2] *= f1; o[nt][3] *= f1;
        }

        // ---- O += P V (3-pass) ----
#pragma unroll
        for (int kt = 0; kt < 4; kt++) {
            uint32_t ah[4], al[4];
            hilo_h2(sc[2 * kt][0],     sc[2 * kt][1],     ah[0], al[0]);
            hilo_h2(sc[2 * kt][2],     sc[2 * kt][3],     ah[1], al[1]);
            hilo_h2(sc[2 * kt + 1][0], sc[2 * kt + 1][1], ah[2], al[2]);
            hilo_h2(sc[2 * kt + 1][2], sc[2 * kt + 1][3], ah[3], al[3]);

            uint32_t bvh[8][2], bvl[8][2];
#pragma unroll
            for (int jp = 0; jp < 4; jp++) {
                uint32_t t[4];
                ldsm4t(t, so + 2 * AKB + voff + kt * 16 * AROWB + jp * 32);
                bvh[jp * 2][0] = t[0]; bvh[jp * 2][1] = t[1];
                bvh[jp * 2 + 1][0] = t[2]; bvh[jp * 2 + 1][1] = t[3];
                ldsm4t(t, so + 3 * AKB + voff + kt * 16 * AROWB + jp * 32);
                bvl[jp * 2][0] = t[0]; bvl[jp * 2][1] = t[1];
                bvl[jp * 2 + 1][0] = t[2]; bvl[jp * 2 + 1][1] = t[3];
            }
#pragma unroll
            for (int nt = 0; nt < 8; nt++) {
                mma16816(o[nt], ah, bvh[nt]);
                mma16816(o[nt], ah, bvl[nt]);
                mma16816(o[nt], al, bvh[nt]);
            }
        }

        __syncthreads();
        const int nb2 = (kb + 2 < nkb) ? (kb + 2) : (nkb - 1);
        load_kv((kb + 2) & 1, nb2);
        CP_COMMIT();
    }

    // ---- normalize + store ----
    const float il0 = 1.0f / l0;
    const float il1 = 1.0f / l1;
    const int lr0 = q0 + wq0 + r0;
    float* orow0 = &out[((size_t)n * LQ + lr0) * DIM + h * DH];
    float* orow1 = &out[((size_t)n * LQ + lr0 + 8) * DIM + h * DH];
#pragma unroll
    for (int nt = 0; nt < 8; nt++) {
        const int dh = nt * 8 + (lane & 3) * 2;
        float2 v0; v0.x = o[nt][0] * il0; v0.y = o[nt][1] * il0;
        float2 v1; v1.x = o[nt][2] * il1; v1.y = o[nt][3] * il1;
        *reinterpret_cast<float2*>(orow0 + dh) = v0;
        *reinterpret_cast<float2*>(orow1 + dh) = v1;
    }
}

// ----------------------------- launcher -------------------------------------
extern "C" void kernel_launch(void* const* d_in, const int* in_sizes, int n_in,
                              void* d_out, int out_size) {
    const float* query = (const float*)d_in[0];
    const float* key   = (const float*)d_in[1];
    const float* Wq    = (const float*)d_in[2];
    const float* Wk    = (const float*)d_in[3];
    const float* Wv    = (const float*)d_in[4];
    const void* pad = (in_sizes[6] == NB * LK) ? d_in[6]
                    : (in_sizes[5] == NB * LK) ? d_in[5]
                    : d_in[6];
    float* out = (float*)d_out;

    valid_kernel<<<NB, 256>>>(pad);

    __half *xqh, *xql, *xkh, *xkl, *wh, *wl;
    cudaGetSymbolAddress((void**)&xqh, g_Xqh);
    cudaGetSymbolAddress((void**)&xql, g_Xql);
    cudaGetSymbolAddress((void**)&xkh, g_Xkh);
    cudaGetSymbolAddress((void**)&xkl, g_Xkl);
    cudaGetSymbolAddress((void**)&wh,  g_Wh);
    cudaGetSymbolAddress((void**)&wl,  g_Wl);

    const int nx = NB * LQ * DIM;
    const int nw = DIM * DIM;
    cvt_kernel<<<nx / 8 / 256, 256>>>(query, xqh, xql, nx);
    cvt_kernel<<<nx / 8 / 256, 256>>>(key,   xkh, xkl, nx);
    cvt_kernel<<<nw / 8 / 256, 256>>>(Wq, wh + 0 * (size_t)nw, wl + 0 * (size_t)nw, nw);
    cvt_kernel<<<nw / 8 / 256, 256>>>(Wk, wh + 1 * (size_t)nw, wl + 1 * (size_t)nw, nw);
    cvt_kernel<<<nw / 8 / 256, 256>>>(Wv, wh + 2 * (size_t)nw, wl + 2 * (size_t)nw, nw);

    cudaFuncSetAttribute(proj_mma_kernel,
                         cudaFuncAttributeMaxDynamicSharedMemorySize, PSMEM);
    dim3 pgrid(DIM / 128, (NB * LQ) / 128, 3);
    proj_mma_kernel<<<pgrid, 256, PSMEM>>>(0);

    cudaFuncSetAttribute(attn_mma_kernel,
                         cudaFuncAttributeMaxDynamicSharedMemorySize, ASMEM);
    dim3 agrid(LQ / 128, NB * NH);
    attn_mma_kernel<<<agrid, 256, ASMEM>>>(out);
}

// round 8
// speedup vs baseline: 3.5833x; 1.1007x over previous
#include <cuda_runtime.h>
#include <cuda_fp16.h>
#include <math.h>
#include <stdint.h>

#define NB   4
#define LQ   2048
#define LK   2048
#define DIM  1024
#define NH   16
#define DH   64

// ---------------- scratch (static device arrays; no allocation) -------------
__device__ __half g_Xqh[NB * LQ * DIM];
__device__ __half g_Xql[NB * LQ * DIM];
__device__ __half g_Xkh[NB * LK * DIM];
__device__ __half g_Xkl[NB * LK * DIM];
__device__ __half g_Wh[3 * DIM * DIM];
__device__ __half g_Wl[3 * DIM * DIM];
__device__ __half g_Qh[NB * NH * LQ * DH];
__device__ __half g_Ql[NB * NH * LQ * DH];
__device__ __half g_Kh[NB * NH * LK * DH];   // pre-scaled by rscale[n]
__device__ __half g_Vh[NB * NH * LK * DH];
__device__ __half g_Vl[NB * NH * LK * DH];
__device__ int   g_valid[NB];
__device__ float g_rscale[NB];

// ========================= low-level helpers ================================
__device__ __forceinline__ uint32_t smem_u32(const void* p) {
    uint32_t a;
    asm("{ .reg .u64 t; cvta.to.shared.u64 t, %1; cvt.u32.u64 %0, t; }"
        : "=r"(a) : "l"(p));
    return a;
}

__device__ __forceinline__ void cpa16(uint32_t dst, const void* src) {
    asm volatile("cp.async.cg.shared.global [%0], [%1], 16;"
                 :: "r"(dst), "l"(src) : "memory");
}
#define CP_COMMIT() asm volatile("cp.async.commit_group;" ::: "memory")
#define CP_WAIT1()  asm volatile("cp.async.wait_group 1;" ::: "memory")

__device__ __forceinline__ void ldsm4(uint32_t* r, uint32_t addr) {
    asm volatile("ldmatrix.sync.aligned.m8n8.x4.shared.b16 {%0,%1,%2,%3}, [%4];"
                 : "=r"(r[0]), "=r"(r[1]), "=r"(r[2]), "=r"(r[3]) : "r"(addr));
}
__device__ __forceinline__ void ldsm4t(uint32_t* r, uint32_t addr) {
    asm volatile("ldmatrix.sync.aligned.m8n8.x4.trans.shared.b16 {%0,%1,%2,%3}, [%4];"
                 : "=r"(r[0]), "=r"(r[1]), "=r"(r[2]), "=r"(r[3]) : "r"(addr));
}

__device__ __forceinline__ void mma16816(float* d, const uint32_t* a,
                                         const uint32_t* b) {
    asm volatile(
        "mma.sync.aligned.m16n8k16.row.col.f32.f16.f16.f32 "
        "{%0,%1,%2,%3}, {%4,%5,%6,%7}, {%8,%9}, {%0,%1,%2,%3};"
        : "+f"(d[0]), "+f"(d[1]), "+f"(d[2]), "+f"(d[3])
        : "r"(a[0]), "r"(a[1]), "r"(a[2]), "r"(a[3]), "r"(b[0]), "r"(b[1]));
}

__device__ __forceinline__ void hilo_h2(float a, float b, uint32_t& h, uint32_t& l) {
    __half ha = __float2half_rn(a);
    __half hb = __float2half_rn(b);
    float ra = a - __half2float(ha);
    float rb = b - __half2float(hb);
    __half2 H = __halves2half2(ha, hb);
    __half2 L = __floats2half2_rn(ra, rb);
    h = *reinterpret_cast<uint32_t*>(&H);
    l = *reinterpret_cast<uint32_t*>(&L);
}

// ---------------- valid-length + scaling from padding mask ------------------
__global__ void valid_kernel(const void* __restrict__ pad) {
    const int tid = threadIdx.x;
    const int n   = blockIdx.x;
    __shared__ int red[256];

    const unsigned* w = (const unsigned*)pad;
    int f = 0;
    for (int i = tid; i < 2048; i += 256) {
        unsigned v = w[i];
        if (v == 0x3F800000u) f |= 4;
        else if (v == 0x00000001u) f |= 2;
        else if (v == 0x01000000u || v == 0x01010000u ||
                 v == 0x01010100u || v == 0x01010101u) f |= 1;
    }
    red[tid] = f;
    __syncthreads();
    for (int s = 128; s > 0; s >>= 1) {
        if (tid < s) red[tid] |= red[tid + s];
        __syncthreads();
    }
    const int fl = red[0];
    const int layout = (fl & 1) ? 0 : ((fl & 4) ? 2 : 1);
    __syncthreads();

    int c = 0;
    if (layout == 0) {
        const unsigned char* p = (const unsigned char*)pad;
        for (int j = tid; j < LK; j += 256) c += (p[n * LK + j] == 0);
    } else if (layout == 1) {
        const int* p = (const int*)pad;
        for (int j = tid; j < LK; j += 256) c += (p[n * LK + j] == 0);
    } else {
        const float* p = (const float*)pad;
        for (int j = tid; j < LK; j += 256) c += (p[n * LK + j] == 0.0f);
    }
    red[tid] = c;
    __syncthreads();
    for (int s = 128; s > 0; s >>= 1) {
        if (tid < s) red[tid] += red[tid + s];
        __syncthreads();
    }
    if (tid == 0) {
        g_valid[n]  = red[0];
        g_rscale[n] = rsqrtf((float)red[0]);
    }
}

// ---------------- one-shot f32 -> fp16 hi/lo conversion ---------------------
__global__ void cvt_kernel(const float* __restrict__ src,
                           __half* __restrict__ dh, __half* __restrict__ dl,
                           int n) {
    int i = (blockIdx.x * blockDim.x + threadIdx.x) * 8;
    if (i >= n) return;
    float4 a = *reinterpret_cast<const float4*>(src + i);
    float4 b = *reinterpret_cast<const float4*>(src + i + 4);
    uint4 H, L;
    hilo_h2(a.x, a.y, H.x, L.x);
    hilo_h2(a.z, a.w, H.y, L.y);
    hilo_h2(b.x, b.y, H.z, L.z);
    hilo_h2(b.z, b.w, H.w, L.w);
    *reinterpret_cast<uint4*>(dh + i) = H;
    *reinterpret_cast<uint4*>(dl + i) = L;
}

// ============ HMMA projection: Out = X @ W^T =================================
// Q,K: 2-pass (AhBh + AlBh), W hi only.  V: 3-pass (AhBh + AlBh + AhBl).
// K output pre-scaled by rscale[n].
#define PSTR    40
#define PROWB   (PSTR * 2)               // 80 bytes
#define PMATB   (128 * PROWB)            // 10240 bytes per matrix tile
#define PSTGB   (4 * PMATB)              // 40960 per stage (Ah,Al,Bh,[Bl])
#define PSMEM   (2 * PSTGB)              // 81920

__global__ __launch_bounds__(256, 1)
void proj_mma_kernel(int dummy) {
    extern __shared__ char smem[];
    const uint32_t sb = smem_u32(smem);

    const int tid  = threadIdx.x;
    const int wid  = tid >> 5;
    const int lane = tid & 31;
    const int grp  = lane >> 3;

    const int which = blockIdx.z;
    const bool three_pass = (which == 2);
    const __half* __restrict__ XH = (which == 0) ? g_Xqh : g_Xkh;
    const __half* __restrict__ XL = (which == 0) ? g_Xql : g_Xkl;
    const __half* __restrict__ WH = g_Wh + (size_t)which * DIM * DIM;
    const __half* __restrict__ WL = g_Wl + (size_t)which * DIM * DIM;
    __half* __restrict__ OutH = (which == 0) ? g_Qh : (which == 1) ? g_Kh : g_Vh;
    __half* __restrict__ OutL = (which == 0) ? g_Ql : (which == 1) ? (__half*)nullptr : g_Vl;

    const int m0B = blockIdx.y * 128;
    const int n0B = blockIdx.x * 128;
    const int m0W = (wid >> 2) * 64;
    const int n0W = (wid & 3) * 32;

    auto load_stage = [&](int buf, int k0) {
        const uint32_t bo = sb + buf * PSTGB;
#pragma unroll
        for (int hp = 0; hp < 2; hp++) {
            int slot = tid + hp * 256;
            int r  = slot >> 2;
            int cc = slot & 3;
            uint32_t d = bo + r * PROWB + cc * 16;
            size_t ga = (size_t)(m0B + r) * DIM + k0 + cc * 8;
            size_t gb = (size_t)(n0B + r) * DIM + k0 + cc * 8;
            cpa16(d + 0 * PMATB, XH + ga);
            cpa16(d + 1 * PMATB, XL + ga);
            cpa16(d + 2 * PMATB, WH + gb);
            if (three_pass) cpa16(d + 3 * PMATB, WL + gb);
        }
    };

    float acc[4][4][4];
#pragma unroll
    for (int mt = 0; mt < 4; mt++)
#pragma unroll
        for (int nt = 0; nt < 4; nt++)
#pragma unroll
            for (int q = 0; q < 4; q++) acc[mt][nt][q] = 0.f;

    const int aoff = (m0W + (lane & 15)) * PROWB + (lane >> 4) * 16;
    const int boff = (n0W + (grp >> 1) * 8 + (lane & 7)) * PROWB + (grp & 1) * 16;

    load_stage(0, 0);  CP_COMMIT();
    load_stage(1, 32); CP_COMMIT();

    for (int it = 0; it < 32; it++) {
        CP_WAIT1();
        __syncthreads();
        const uint32_t bo = sb + (it & 1) * PSTGB;
        const uint32_t aH = bo + 0 * PMATB + aoff;
        const uint32_t aL = bo + 1 * PMATB + aoff;
        const uint32_t bH = bo + 2 * PMATB + boff;
        const uint32_t bL = bo + 3 * PMATB + boff;

#pragma unroll
        for (int ks = 0; ks < 2; ks++) {
            const int kb = ks * 32;
            uint32_t ah[4][4], al[4][4], bh[4][2], bl[4][2];
#pragma unroll
            for (int mt = 0; mt < 4; mt++) {
                ldsm4(ah[mt], aH + mt * 16 * PROWB + kb);
                ldsm4(al[mt], aL + mt * 16 * PROWB + kb);
            }
#pragma unroll
            for (int bt = 0; bt < 2; bt++) {
                uint32_t t[4];
                ldsm4(t, bH + bt * 16 * PROWB + kb);
                bh[bt * 2][0] = t[0]; bh[bt * 2][1] = t[1];
                bh[bt * 2 + 1][0] = t[2]; bh[bt * 2 + 1][1] = t[3];
            }
            if (three_pass) {
#pragma unroll
                for (int bt = 0; bt < 2; bt++) {
                    uint32_t t[4];
                    ldsm4(t, bL + bt * 16 * PROWB + kb);
                    bl[bt * 2][0] = t[0]; bl[bt * 2][1] = t[1];
                    bl[bt * 2 + 1][0] = t[2]; bl[bt * 2 + 1][1] = t[3];
                }
            }
#pragma unroll
            for (int mt = 0; mt < 4; mt++)
#pragma unroll
                for (int nt = 0; nt < 4; nt++) {
                    mma16816(acc[mt][nt], ah[mt], bh[nt]);
                    mma16816(acc[mt][nt], al[mt], bh[nt]);
                }
            if (three_pass) {
#pragma unroll
                for (int mt = 0; mt < 4; mt++)
#pragma unroll
                    for (int nt = 0; nt < 4; nt++)
                        mma16816(acc[mt][nt], ah[mt], bl[nt]);
            }
        }
        __syncthreads();
        const int ns = (it + 2 < 32) ? (it + 2) : 31;
        load_stage((it + 2) & 1, ns * 32);
        CP_COMMIT();
    }

    const int rr  = lane >> 2;
    const int cc2 = (lane & 3) * 2;
#pragma unroll
    for (int mt = 0; mt < 4; mt++) {
#pragma unroll
        for (int hp = 0; hp < 2; hp++) {
            const int m = m0B + m0W + mt * 16 + rr + hp * 8;
            const int n = m >> 11;
            const int l = m & 2047;
            const float ksc = (which == 1) ? g_rscale[n] : 1.0f;
            const size_t rowb = ((size_t)(n * NH) * LQ + l) * DH;
#pragma unroll
            for (int nt = 0; nt < 4; nt++) {
                const int j  = n0B + n0W + nt * 8 + cc2;
                const int h  = j >> 6;
                const int dh = j & 63;
                uint32_t H, L;
                hilo_h2(acc[mt][nt][hp * 2 + 0] * ksc,
                        acc[mt][nt][hp * 2 + 1] * ksc, H, L);
                const size_t o = rowb + (size_t)h * LQ * DH + dh;
                *reinterpret_cast<uint32_t*>(&OutH[o]) = H;
                if (OutL) *reinterpret_cast<uint32_t*>(&OutL[o]) = L;
            }
        }
    }
}

// ================= FA2 attention, fp16 HMMA ================================
// S = 2-pass (QhKh + QlKh, K pre-scaled).  PV = 3-pass.
// KV stage: Kh, Vh, Vl (3 matrices).
#define ASTR    72
#define AROWB   (ASTR * 2)               // 144 bytes
#define AQB     (128 * AROWB)            // 18432 per Q matrix
#define AKB     (64 * AROWB)             // 9216 per K/V matrix
#define ASTG0   (2 * AQB)                // 36864
#define ASTGB   (3 * AKB)                // 27648 per stage (Kh,Vh,Vl)
#define ASMEM   (ASTG0 + 2 * ASTGB)      // 92160

__global__ __launch_bounds__(256, 1)
void attn_mma_kernel(float* __restrict__ out) {
    extern __shared__ char smem[];
    const uint32_t sb = smem_u32(smem);

    const int tid  = threadIdx.x;
    const int wid  = tid >> 5;
    const int lane = tid & 31;
    const int grp  = lane >> 3;

    const int q0 = blockIdx.x * 128;
    const int nh = blockIdx.y;
    const int n  = nh >> 4;
    const int h  = nh & 15;

    const int valid = g_valid[n];
    const int kend  = min(valid, q0 + 128);
    const int nkb   = (kend + 63) >> 6;   // >= 2 always (valid >= 1024)

    const size_t base = (size_t)nh * LK * DH;
    const __half* __restrict__ Qhb = g_Qh + base;
    const __half* __restrict__ Qlb = g_Ql + base;
    const __half* __restrict__ Khb = g_Kh + base;
    const __half* __restrict__ Vhb = g_Vh + base;
    const __half* __restrict__ Vlb = g_Vl + base;

    // Q: 2 mats x 128 rows x 8 chunks = 2048 chunks -> 8 per thread
    auto load_q = [&]() {
#pragma unroll
        for (int i = 0; i < 8; i++) {
            int c   = tid + i * 256;
            int mat = c >> 10;
            int r   = (c >> 3) & 127;
            int cc  = c & 7;
            const __half* src = (mat ? Qlb : Qhb) + (size_t)(q0 + r) * DH + cc * 8;
            cpa16(sb + mat * AQB + r * AROWB + cc * 16, src);
        }
    };
    // KV: 3 mats x 64 rows x 8 chunks = 1536 chunks -> 6 per thread
    auto load_kv = [&](int buf, int kb) {
        const int k0 = kb * 64;
        const uint32_t so = sb + ASTG0 + buf * ASTGB;
#pragma unroll
        for (int i = 0; i < 6; i++) {
            int c   = tid + i * 256;          // 0..1535
            int mat = c >> 9;                 // 0:Kh 1:Vh 2:Vl
            int r   = (c >> 3) & 63;
            int cc  = c & 7;
            const __half* src = (mat == 0) ? Khb : (mat == 1) ? Vhb : Vlb;
            src += (size_t)(k0 + r) * DH + cc * 8;
            cpa16(so + mat * AKB + r * AROWB + cc * 16, src);
        }
    };

    const int wq0 = wid * 16;
    const int r0  = lane >> 2;
    const int qr0 = q0 + wq0 + r0;
    const int qr1 = qr0 + 8;

    const int qoff = (wq0 + (lane & 15)) * AROWB + (lane >> 4) * 16;
    const int koff = ((grp >> 1) * 8 + (lane & 7)) * AROWB + (grp & 1) * 16;
    const int voff = ((grp & 1) * 8 + (lane & 7)) * AROWB + (grp >> 1) * 16;

    uint32_t qh[4][4], ql[4][4];
    float o[8][4];
#pragma unroll
    for (int nt = 0; nt < 8; nt++)
#pragma unroll
        for (int q = 0; q < 4; q++) o[nt][q] = 0.f;
    float m0 = -1e30f, m1 = -1e30f, l0 = 0.f, l1 = 0.f;

    load_q();
    load_kv(0, 0);
    CP_COMMIT();
    load_kv(1, (nkb > 1) ? 1 : 0);
    CP_COMMIT();

    for (int kb = 0; kb < nkb; kb++) {
        CP_WAIT1();
        __syncthreads();
        const int k0 = kb * 64;
        const uint32_t so = sb + ASTG0 + (kb & 1) * ASTGB;

        if (kb == 0) {
#pragma unroll
            for (int kt = 0; kt < 4; kt++) {
                ldsm4(qh[kt], sb + 0 * AQB + qoff + kt * 32);
                ldsm4(ql[kt], sb + 1 * AQB + qoff + kt * 32);
            }
        }

        // ---- S = Q K^T (2-pass; K pre-scaled by rscale) ----
        float sc[8][4];
#pragma unroll
        for (int nt = 0; nt < 8; nt++)
#pragma unroll
            for (int q = 0; q < 4; q++) sc[nt][q] = 0.f;

#pragma unroll
        for (int kt = 0; kt < 4; kt++) {
            uint32_t bh[8][2];
#pragma unroll
            for (int bt = 0; bt < 4; bt++) {
                uint32_t t[4];
                ldsm4(t, so + 0 * AKB + koff + bt * 16 * AROWB + kt * 32);
                bh[bt * 2][0] = t[0]; bh[bt * 2][1] = t[1];
                bh[bt * 2 + 1][0] = t[2]; bh[bt * 2 + 1][1] = t[3];
            }
#pragma unroll
            for (int nt = 0; nt < 8; nt++) {
                mma16816(sc[nt], qh[kt], bh[nt]);
                mma16816(sc[nt], ql[kt], bh[nt]);
            }
        }

        // ---- mask (scores already scaled) ----
#pragma unroll
        for (int nt = 0; nt < 8; nt++) {
            const int kc = k0 + nt * 8 + (lane & 3) * 2;
            if (kc     > qr0 || kc     >= valid) sc[nt][0] = -1e30f;
            if (kc + 1 > qr0 || kc + 1 >= valid) sc[nt][1] = -1e30f;
            if (kc     > qr1 || kc     >= valid) sc[nt][2] = -1e30f;
            if (kc + 1 > qr1 || kc + 1 >= valid) sc[nt][3] = -1e30f;
        }

        // ---- online softmax ----
        float mx0 = -1e30f, mx1 = -1e30f;
#pragma unroll
        for (int nt = 0; nt < 8; nt++) {
            mx0 = fmaxf(mx0, fmaxf(sc[nt][0], sc[nt][1]));
            mx1 = fmaxf(mx1, fmaxf(sc[nt][2], sc[nt][3]));
        }
        mx0 = fmaxf(mx0, __shfl_xor_sync(0xffffffffu, mx0, 1));
        mx0 = fmaxf(mx0, __shfl_xor_sync(0xffffffffu, mx0, 2));
        mx1 = fmaxf(mx1, __shfl_xor_sync(0xffffffffu, mx1, 1));
        mx1 = fmaxf(mx1, __shfl_xor_sync(0xffffffffu, mx1, 2));
        const float mn0 = fmaxf(m0, mx0);
        const float mn1 = fmaxf(m1, mx1);
        const float f0 = __expf(m0 - mn0);
        const float f1 = __expf(m1 - mn1);
        m0 = mn0; m1 = mn1;

        float s0 = 0.f, s1 = 0.f;
#pragma unroll
        for (int nt = 0; nt < 8; nt++) {
            sc[nt][0] = __expf(sc[nt][0] - mn0);
            sc[nt][1] = __expf(sc[nt][1] - mn0);
            sc[nt][2] = __expf(sc[nt][2] - mn1);
            sc[nt][3] = __expf(sc[nt][3] - mn1);
            s0 += sc[nt][0] + sc[nt][1];
            s1 += sc[nt][2] + sc[nt][3];
        }
        s0 += __shfl_xor_sync(0xffffffffu, s0, 1);
        s0 += __shfl_xor_sync(0xffffffffu, s0, 2);
        s1 += __shfl_xor_sync(0xffffffffu, s1, 1);
        s1 += __shfl_xor_sync(0xffffffffu, s1, 2);
        l0 = l0 * f0 + s0;
        l1 = l1 * f1 + s1;

#pragma unroll
        for (int nt = 0; nt < 8; nt++) {
            o[nt][0] *= f0; o[nt][1] *= f0;
            o[nt][2] *= f1; o[nt][3] *= f1;
        }

        // ---- O += P V (3-pass) ----
#pragma unroll
        for (int kt = 0; kt < 4; kt++) {
            uint32_t ah[4], al[4];
            hilo_h2(sc[2 * kt][0],     sc[2 * kt][1],     ah[0], al[0]);
            hilo_h2(sc[2 * kt][2],     sc[2 * kt][3],     ah[1], al[1]);
            hilo_h2(sc[2 * kt + 1][0], sc[2 * kt + 1][1], ah[2], al[2]);
            hilo_h2(sc[2 * kt + 1][2], sc[2 * kt + 1][3], ah[3], al[3]);

            uint32_t bvh[8][2], bvl[8][2];
#pragma unroll
            for (int jp = 0; jp < 4; jp++) {
                uint32_t t[4];
                ldsm4t(t, so + 1 * AKB + voff + kt * 16 * AROWB + jp * 32);
                bvh[jp * 2][0] = t[0]; bvh[jp * 2][1] = t[1];
                bvh[jp * 2 + 1][0] = t[2]; bvh[jp * 2 + 1][1] = t[3];
                ldsm4t(t, so + 2 * AKB + voff + kt * 16 * AROWB + jp * 32);
                bvl[jp * 2][0] = t[0]; bvl[jp * 2][1] = t[1];
                bvl[jp * 2 + 1][0] = t[2]; bvl[jp * 2 + 1][1] = t[3];
            }
#pragma unroll
            for (int nt = 0; nt < 8; nt++) {
                mma16816(o[nt], ah, bvh[nt]);
                mma16816(o[nt], ah, bvl[nt]);
                mma16816(o[nt], al, bvh[nt]);
            }
        }

        __syncthreads();
        const int nb2 = (kb + 2 < nkb) ? (kb + 2) : (nkb - 1);
        load_kv((kb + 2) & 1, nb2);
        CP_COMMIT();
    }

    // ---- normalize + store ----
    const float il0 = 1.0f / l0;
    const float il1 = 1.0f / l1;
    const int lr0 = q0 + wq0 + r0;
    float* orow0 = &out[((size_t)n * LQ + lr0) * DIM + h * DH];
    float* orow1 = &out[((size_t)n * LQ + lr0 + 8) * DIM + h * DH];
#pragma unroll
    for (int nt = 0; nt < 8; nt++) {
        const int dh = nt * 8 + (lane & 3) * 2;
        float2 v0; v0.x = o[nt][0] * il0; v0.y = o[nt][1] * il0;
        float2 v1; v1.x = o[nt][2] * il1; v1.y = o[nt][3] * il1;
        *reinterpret_cast<float2*>(orow0 + dh) = v0;
        *reinterpret_cast<float2*>(orow1 + dh) = v1;
    }
}

// ----------------------------- launcher -------------------------------------
extern "C" void kernel_launch(void* const* d_in, const int* in_sizes, int n_in,
                              void* d_out, int out_size) {
    const float* query = (const float*)d_in[0];
    const float* key   = (const float*)d_in[1];
    const float* Wq    = (const float*)d_in[2];
    const float* Wk    = (const float*)d_in[3];
    const float* Wv    = (const float*)d_in[4];
    const void* pad = (in_sizes[6] == NB * LK) ? d_in[6]
                    : (in_sizes[5] == NB * LK) ? d_in[5]
                    : d_in[6];
    float* out = (float*)d_out;

    valid_kernel<<<NB, 256>>>(pad);

    __half *xqh, *xql, *xkh, *xkl, *wh, *wl;
    cudaGetSymbolAddress((void**)&xqh, g_Xqh);
    cudaGetSymbolAddress((void**)&xql, g_Xql);
    cudaGetSymbolAddress((void**)&xkh, g_Xkh);
    cudaGetSymbolAddress((void**)&xkl, g_Xkl);
    cudaGetSymbolAddress((void**)&wh,  g_Wh);
    cudaGetSymbolAddress((void**)&wl,  g_Wl);

    const int nx = NB * LQ * DIM;
    const int nw = DIM * DIM;
    cvt_kernel<<<nx / 8 / 256, 256>>>(query, xqh, xql, nx);
    cvt_kernel<<<nx / 8 / 256, 256>>>(key,   xkh, xkl, nx);
    cvt_kernel<<<nw / 8 / 256, 256>>>(Wq, wh + 0 * (size_t)nw, wl + 0 * (size_t)nw, nw);
    cvt_kernel<<<nw / 8 / 256, 256>>>(Wk, wh + 1 * (size_t)nw, wl + 1 * (size_t)nw, nw);
    cvt_kernel<<<nw / 8 / 256, 256>>>(Wv, wh + 2 * (size_t)nw, wl + 2 * (size_t)nw, nw);

    cudaFuncSetAttribute(proj_mma_kernel,
                         cudaFuncAttributeMaxDynamicSharedMemorySize, PSMEM);
    dim3 pgrid(DIM / 128, (NB * LQ) / 128, 3);
    proj_mma_kernel<<<pgrid, 256, PSMEM>>>(0);

    cudaFuncSetAttribute(attn_mma_kernel,
                         cudaFuncAttributeMaxDynamicSharedMemorySize, ASMEM);
    dim3 agrid(LQ / 128, NB * NH);
    attn_mma_kernel<<<agrid, 256, ASMEM>>>(out);
}

// round 9
// speedup vs baseline: 4.2493x; 1.1859x over previous
#include <cuda_runtime.h>
#include <cuda_fp16.h>
#include <math.h>
#include <stdint.h>

#define NB   4
#define LQ   2048
#define LK   2048
#define DIM  1024
#define NH   16
#define DH   64

// ---------------- scratch (static device arrays; no allocation) -------------
__device__ __half g_Xqh[NB * LQ * DIM];
__device__ __half g_Xql[NB * LQ * DIM];
__device__ __half g_Xkh[NB * LK * DIM];
__device__ __half g_Xkl[NB * LK * DIM];
__device__ __half g_Wh[3 * DIM * DIM];
__device__ __half g_Wl[3 * DIM * DIM];
__device__ __half g_Qh[NB * NH * LQ * DH];
__device__ __half g_Kh[NB * NH * LK * DH];   // pre-scaled by rscale[n]*log2(e)
__device__ __half g_Vh[NB * NH * LK * DH];
__device__ __half g_Vl[NB * NH * LK * DH];
__device__ int   g_valid[NB];
__device__ float g_rscale[NB];

// ========================= low-level helpers ================================
__device__ __forceinline__ uint32_t smem_u32(const void* p) {
    uint32_t a;
    asm("{ .reg .u64 t; cvta.to.shared.u64 t, %1; cvt.u32.u64 %0, t; }"
        : "=r"(a) : "l"(p));
    return a;
}

__device__ __forceinline__ float ex2(float x) {
    float r;
    asm("ex2.approx.f32 %0, %1;" : "=f"(r) : "f"(x));
    return r;
}

__device__ __forceinline__ void cpa16(uint32_t dst, const void* src) {
    asm volatile("cp.async.cg.shared.global [%0], [%1], 16;"
                 :: "r"(dst), "l"(src) : "memory");
}
#define CP_COMMIT() asm volatile("cp.async.commit_group;" ::: "memory")
#define CP_WAIT1()  asm volatile("cp.async.wait_group 1;" ::: "memory")

__device__ __forceinline__ void ldsm4(uint32_t* r, uint32_t addr) {
    asm volatile("ldmatrix.sync.aligned.m8n8.x4.shared.b16 {%0,%1,%2,%3}, [%4];"
                 : "=r"(r[0]), "=r"(r[1]), "=r"(r[2]), "=r"(r[3]) : "r"(addr));
}
__device__ __forceinline__ void ldsm4t(uint32_t* r, uint32_t addr) {
    asm volatile("ldmatrix.sync.aligned.m8n8.x4.trans.shared.b16 {%0,%1,%2,%3}, [%4];"
                 : "=r"(r[0]), "=r"(r[1]), "=r"(r[2]), "=r"(r[3]) : "r"(addr));
}

__device__ __forceinline__ void mma16816(float* d, const uint32_t* a,
                                         const uint32_t* b) {
    asm volatile(
        "mma.sync.aligned.m16n8k16.row.col.f32.f16.f16.f32 "
        "{%0,%1,%2,%3}, {%4,%5,%6,%7}, {%8,%9}, {%0,%1,%2,%3};"
        : "+f"(d[0]), "+f"(d[1]), "+f"(d[2]), "+f"(d[3])
        : "r"(a[0]), "r"(a[1]), "r"(a[2]), "r"(a[3]), "r"(b[0]), "r"(b[1]));
}

__device__ __forceinline__ void hilo_h2(float a, float b, uint32_t& h, uint32_t& l) {
    __half ha = __float2half_rn(a);
    __half hb = __float2half_rn(b);
    float ra = a - __half2float(ha);
    float rb = b - __half2float(hb);
    __half2 H = __halves2half2(ha, hb);
    __half2 L = __floats2half2_rn(ra, rb);
    h = *reinterpret_cast<uint32_t*>(&H);
    l = *reinterpret_cast<uint32_t*>(&L);
}

__device__ __forceinline__ uint32_t h2_only(float a, float b) {
    __half2 H = __floats2half2_rn(a, b);
    return *reinterpret_cast<uint32_t*>(&H);
}

// ---------------- valid-length + scaling from padding mask ------------------
__global__ void valid_kernel(const void* __restrict__ pad) {
    const int tid = threadIdx.x;
    const int n   = blockIdx.x;
    __shared__ int red[256];

    const unsigned* w = (const unsigned*)pad;
    int f = 0;
    for (int i = tid; i < 2048; i += 256) {
        unsigned v = w[i];
        if (v == 0x3F800000u) f |= 4;
        else if (v == 0x00000001u) f |= 2;
        else if (v == 0x01000000u || v == 0x01010000u ||
                 v == 0x01010100u || v == 0x01010101u) f |= 1;
    }
    red[tid] = f;
    __syncthreads();
    for (int s = 128; s > 0; s >>= 1) {
        if (tid < s) red[tid] |= red[tid + s];
        __syncthreads();
    }
    const int fl = red[0];
    const int layout = (fl & 1) ? 0 : ((fl & 4) ? 2 : 1);
    __syncthreads();

    int c = 0;
    if (layout == 0) {
        const unsigned char* p = (const unsigned char*)pad;
        for (int j = tid; j < LK; j += 256) c += (p[n * LK + j] == 0);
    } else if (layout == 1) {
        const int* p = (const int*)pad;
        for (int j = tid; j < LK; j += 256) c += (p[n * LK + j] == 0);
    } else {
        const float* p = (const float*)pad;
        for (int j = tid; j < LK; j += 256) c += (p[n * LK + j] == 0.0f);
    }
    red[tid] = c;
    __syncthreads();
    for (int s = 128; s > 0; s >>= 1) {
        if (tid < s) red[tid] += red[tid + s];
        __syncthreads();
    }
    if (tid == 0) {
        g_valid[n]  = red[0];
        g_rscale[n] = rsqrtf((float)red[0]);
    }
}

// ---------------- one-shot f32 -> fp16 hi/lo conversion ---------------------
__global__ void cvt_kernel(const float* __restrict__ src,
                           __half* __restrict__ dh, __half* __restrict__ dl,
                           int n) {
    int i = (blockIdx.x * blockDim.x + threadIdx.x) * 8;
    if (i >= n) return;
    float4 a = *reinterpret_cast<const float4*>(src + i);
    float4 b = *reinterpret_cast<const float4*>(src + i + 4);
    uint4 H, L;
    hilo_h2(a.x, a.y, H.x, L.x);
    hilo_h2(a.z, a.w, H.y, L.y);
    hilo_h2(b.x, b.y, H.z, L.z);
    hilo_h2(b.z, b.w, H.w, L.w);
    *reinterpret_cast<uint4*>(dh + i) = H;
    *reinterpret_cast<uint4*>(dl + i) = L;
}

// ============ HMMA projection: Out = X @ W^T =================================
// Q,K: 1-pass (AhBh).  V: 3-pass (AhBh + AlBh + AhBl).
// K output pre-scaled by rscale[n]*log2(e).
#define PSTR    40
#define PROWB   (PSTR * 2)               // 80 bytes
#define PMATB   (128 * PROWB)            // 10240 bytes per matrix tile
#define PSTGB   (4 * PMATB)              // 40960 per stage (Ah,Al,Bh,Bl)
#define PSMEM   (2 * PSTGB)              // 81920

__global__ __launch_bounds__(256, 1)
void proj_mma_kernel(int dummy) {
    extern __shared__ char smem[];
    const uint32_t sb = smem_u32(smem);

    const int tid  = threadIdx.x;
    const int wid  = tid >> 5;
    const int lane = tid & 31;
    const int grp  = lane >> 3;

    const int which = blockIdx.z;
    const bool three_pass = (which == 2);
    const __half* __restrict__ XH = (which == 0) ? g_Xqh : g_Xkh;
    const __half* __restrict__ XL = (which == 0) ? g_Xql : g_Xkl;
    const __half* __restrict__ WH = g_Wh + (size_t)which * DIM * DIM;
    const __half* __restrict__ WL = g_Wl + (size_t)which * DIM * DIM;
    __half* __restrict__ OutH = (which == 0) ? g_Qh : (which == 1) ? g_Kh : g_Vh;
    __half* __restrict__ OutL = three_pass ? g_Vl : (__half*)nullptr;

    const int m0B = blockIdx.y * 128;
    const int n0B = blockIdx.x * 128;
    const int m0W = (wid >> 2) * 64;
    const int n0W = (wid & 3) * 32;

    auto load_stage = [&](int buf, int k0) {
        const uint32_t bo = sb + buf * PSTGB;
#pragma unroll
        for (int hp = 0; hp < 2; hp++) {
            int slot = tid + hp * 256;
            int r  = slot >> 2;
            int cc = slot & 3;
            uint32_t d = bo + r * PROWB + cc * 16;
            size_t ga = (size_t)(m0B + r) * DIM + k0 + cc * 8;
            size_t gb = (size_t)(n0B + r) * DIM + k0 + cc * 8;
            cpa16(d + 0 * PMATB, XH + ga);
            cpa16(d + 2 * PMATB, WH + gb);
            if (three_pass) {
                cpa16(d + 1 * PMATB, XL + ga);
                cpa16(d + 3 * PMATB, WL + gb);
            }
        }
    };

    float acc[4][4][4];
#pragma unroll
    for (int mt = 0; mt < 4; mt++)
#pragma unroll
        for (int nt = 0; nt < 4; nt++)
#pragma unroll
            for (int q = 0; q < 4; q++) acc[mt][nt][q] = 0.f;

    const int aoff = (m0W + (lane & 15)) * PROWB + (lane >> 4) * 16;
    const int boff = (n0W + (grp >> 1) * 8 + (lane & 7)) * PROWB + (grp & 1) * 16;

    load_stage(0, 0);  CP_COMMIT();
    load_stage(1, 32); CP_COMMIT();

    for (int it = 0; it < 32; it++) {
        CP_WAIT1();
        __syncthreads();
        const uint32_t bo = sb + (it & 1) * PSTGB;
        const uint32_t aH = bo + 0 * PMATB + aoff;
        const uint32_t aL = bo + 1 * PMATB + aoff;
        const uint32_t bH = bo + 2 * PMATB + boff;
        const uint32_t bL = bo + 3 * PMATB + boff;

#pragma unroll
        for (int ks = 0; ks < 2; ks++) {
            const int kb = ks * 32;
            uint32_t ah[4][4], al[4][4], bh[4][2], bl[4][2];
#pragma unroll
            for (int mt = 0; mt < 4; mt++) {
                ldsm4(ah[mt], aH + mt * 16 * PROWB + kb);
                if (three_pass) ldsm4(al[mt], aL + mt * 16 * PROWB + kb);
            }
#pragma unroll
            for (int bt = 0; bt < 2; bt++) {
                uint32_t t[4];
                ldsm4(t, bH + bt * 16 * PROWB + kb);
                bh[bt * 2][0] = t[0]; bh[bt * 2][1] = t[1];
                bh[bt * 2 + 1][0] = t[2]; bh[bt * 2 + 1][1] = t[3];
            }
            if (three_pass) {
#pragma unroll
                for (int bt = 0; bt < 2; bt++) {
                    uint32_t t[4];
                    ldsm4(t, bL + bt * 16 * PROWB + kb);
                    bl[bt * 2][0] = t[0]; bl[bt * 2][1] = t[1];
                    bl[bt * 2 + 1][0] = t[2]; bl[bt * 2 + 1][1] = t[3];
                }
            }
#pragma unroll
            for (int mt = 0; mt < 4; mt++)
#pragma unroll
                for (int nt = 0; nt < 4; nt++)
                    mma16816(acc[mt][nt], ah[mt], bh[nt]);
            if (three_pass) {
#pragma unroll
                for (int mt = 0; mt < 4; mt++)
#pragma unroll
                    for (int nt = 0; nt < 4; nt++) {
                        mma16816(acc[mt][nt], al[mt], bh[nt]);
                        mma16816(acc[mt][nt], ah[mt], bl[nt]);
                    }
            }
        }
        __syncthreads();
        const int ns = (it + 2 < 32) ? (it + 2) : 31;
        load_stage((it + 2) & 1, ns * 32);
        CP_COMMIT();
    }

    const int rr  = lane >> 2;
    const int cc2 = (lane & 3) * 2;
#pragma unroll
    for (int mt = 0; mt < 4; mt++) {
#pragma unroll
        for (int hp = 0; hp < 2; hp++) {
            const int m = m0B + m0W + mt * 16 + rr + hp * 8;
            const int n = m >> 11;
            const int l = m & 2047;
            const float ksc = (which == 1) ? g_rscale[n] * 1.44269504f : 1.0f;
            const size_t rowb = ((size_t)(n * NH) * LQ + l) * DH;
#pragma unroll
            for (int nt = 0; nt < 4; nt++) {
                const int j  = n0B + n0W + nt * 8 + cc2;
                const int h  = j >> 6;
                const int dh = j & 63;
                const size_t o = rowb + (size_t)h * LQ * DH + dh;
                if (three_pass) {
                    uint32_t H, L;
                    hilo_h2(acc[mt][nt][hp * 2 + 0], acc[mt][nt][hp * 2 + 1], H, L);
                    *reinterpret_cast<uint32_t*>(&OutH[o]) = H;
                    *reinterpret_cast<uint32_t*>(&OutL[o]) = L;
                } else {
                    *reinterpret_cast<uint32_t*>(&OutH[o]) =
                        h2_only(acc[mt][nt][hp * 2 + 0] * ksc,
                                acc[mt][nt][hp * 2 + 1] * ksc);
                }
            }
        }
    }
}

// ================= FA2 attention, fp16 HMMA ================================
// S = 1-pass (Qh·Kh; K pre-scaled by rscale*log2e; exp -> ex2).
// PV = 3-pass.  KV stage: Kh, Vh, Vl.
#define ASTR    72
#define AROWB   (ASTR * 2)               // 144 bytes
#define AQB     (128 * AROWB)            // 18432 (Qh only)
#define AKB     (64 * AROWB)             // 9216 per K/V matrix
#define ASTG0   AQB                      // 18432
#define ASTGB   (3 * AKB)                // 27648 per stage (Kh,Vh,Vl)
#define ASMEM   (ASTG0 + 2 * ASTGB)      // 73728

__global__ __launch_bounds__(256, 1)
void attn_mma_kernel(float* __restrict__ out) {
    extern __shared__ char smem[];
    const uint32_t sb = smem_u32(smem);

    const int tid  = threadIdx.x;
    const int wid  = tid >> 5;
    const int lane = tid & 31;
    const int grp  = lane >> 3;

    const int q0 = blockIdx.x * 128;
    const int nh = blockIdx.y;
    const int n  = nh >> 4;
    const int h  = nh & 15;

    const int valid = g_valid[n];
    const int kend  = min(valid, q0 + 128);
    const int nkb   = (kend + 63) >> 6;   // >= 2 always (valid >= 1024)

    const size_t base = (size_t)nh * LK * DH;
    const __half* __restrict__ Qhb = g_Qh + base;
    const __half* __restrict__ Khb = g_Kh + base;
    const __half* __restrict__ Vhb = g_Vh + base;
    const __half* __restrict__ Vlb = g_Vl + base;

    // Q: 1 mat x 128 rows x 8 chunks = 1024 chunks -> 4 per thread
    auto load_q = [&]() {
#pragma unroll
        for (int i = 0; i < 4; i++) {
            int c  = tid + i * 256;           // 0..1023
            int r  = c >> 3;                  // 0..127
            int cc = c & 7;
            cpa16(sb + r * AROWB + cc * 16, Qhb + (size_t)(q0 + r) * DH + cc * 8);
        }
    };
    // KV: 3 mats x 64 rows x 8 chunks = 1536 chunks -> 6 per thread
    auto load_kv = [&](int buf, int kb) {
        const int k0 = kb * 64;
        const uint32_t so = sb + ASTG0 + buf * ASTGB;
#pragma unroll
        for (int i = 0; i < 6; i++) {
            int c   = tid + i * 256;          // 0..1535
            int mat = c >> 9;                 // 0:Kh 1:Vh 2:Vl
            int r   = (c >> 3) & 63;
            int cc  = c & 7;
            const __half* src = (mat == 0) ? Khb : (mat == 1) ? Vhb : Vlb;
            src += (size_t)(k0 + r) * DH + cc * 8;
            cpa16(so + mat * AKB + r * AROWB + cc * 16, src);
        }
    };

    const int wq0 = wid * 16;
    const int r0  = lane >> 2;
    const int qr0 = q0 + wq0 + r0;
    const int qr1 = qr0 + 8;

    const int qoff = (wq0 + (lane & 15)) * AROWB + (lane >> 4) * 16;
    const int koff = ((grp >> 1) * 8 + (lane & 7)) * AROWB + (grp & 1) * 16;
    const int voff = ((grp & 1) * 8 + (lane & 7)) * AROWB + (grp >> 1) * 16;

    uint32_t qh[4][4];
    float o[8][4];
#pragma unroll
    for (int nt = 0; nt < 8; nt++)
#pragma unroll
        for (int q = 0; q < 4; q++) o[nt][q] = 0.f;
    float m0 = -1e30f, m1 = -1e30f, l0 = 0.f, l1 = 0.f;

    load_q();
    load_kv(0, 0);
    CP_COMMIT();
    load_kv(1, (nkb > 1) ? 1 : 0);
    CP_COMMIT();

    for (int kb = 0; kb < nkb; kb++) {
        CP_WAIT1();
        __syncthreads();
        const int k0 = kb * 64;
        const uint32_t so = sb + ASTG0 + (kb & 1) * ASTGB;

        if (kb == 0) {
#pragma unroll
            for (int kt = 0; kt < 4; kt++)
                ldsm4(qh[kt], sb + qoff + kt * 32);
        }

        // ---- S = Q K^T (1-pass; K carries rscale*log2e) ----
        float sc[8][4];
#pragma unroll
        for (int nt = 0; nt < 8; nt++)
#pragma unroll
            for (int q = 0; q < 4; q++) sc[nt][q] = 0.f;

#pragma unroll
        for (int kt = 0; kt < 4; kt++) {
            uint32_t bh[8][2];
#pragma unroll
            for (int bt = 0; bt < 4; bt++) {
                uint32_t t[4];
                ldsm4(t, so + 0 * AKB + koff + bt * 16 * AROWB + kt * 32);
                bh[bt * 2][0] = t[0]; bh[bt * 2][1] = t[1];
                bh[bt * 2 + 1][0] = t[2]; bh[bt * 2 + 1][1] = t[3];
            }
#pragma unroll
            for (int nt = 0; nt < 8; nt++)
                mma16816(sc[nt], qh[kt], bh[nt]);
        }

        // ---- mask (scores already scaled, log2 domain) ----
#pragma unroll
        for (int nt = 0; nt < 8; nt++) {
            const int kc = k0 + nt * 8 + (lane & 3) * 2;
            if (kc     > qr0 || kc     >= valid) sc[nt][0] = -1e30f;
            if (kc + 1 > qr0 || kc + 1 >= valid) sc[nt][1] = -1e30f;
            if (kc     > qr1 || kc     >= valid) sc[nt][2] = -1e30f;
            if (kc + 1 > qr1 || kc + 1 >= valid) sc[nt][3] = -1e30f;
        }

        // ---- online softmax (base-2) ----
        float mx0 = -1e30f, mx1 = -1e30f;
#pragma unroll
        for (int nt = 0; nt < 8; nt++) {
            mx0 = fmaxf(mx0, fmaxf(sc[nt][0], sc[nt][1]));
            mx1 = fmaxf(mx1, fmaxf(sc[nt][2], sc[nt][3]));
        }
        mx0 = fmaxf(mx0, __shfl_xor_sync(0xffffffffu, mx0, 1));
        mx0 = fmaxf(mx0, __shfl_xor_sync(0xffffffffu, mx0, 2));
        mx1 = fmaxf(mx1, __shfl_xor_sync(0xffffffffu, mx1, 1));
        mx1 = fmaxf(mx1, __shfl_xor_sync(0xffffffffu, mx1, 2));
        const float mn0 = fmaxf(m0, mx0);
        const float mn1 = fmaxf(m1, mx1);
        const float f0 = ex2(m0 - mn0);
        const float f1 = ex2(m1 - mn1);
        m0 = mn0; m1 = mn1;

        float s0 = 0.f, s1 = 0.f;
#pragma unroll
        for (int nt = 0; nt < 8; nt++) {
            sc[nt][0] = ex2(sc[nt][0] - mn0);
            sc[nt][1] = ex2(sc[nt][1] - mn0);
            sc[nt][2] = ex2(sc[nt][2] - mn1);
            sc[nt][3] = ex2(sc[nt][3] - mn1);
            s0 += sc[nt][0] + sc[nt][1];
            s1 += sc[nt][2] + sc[nt][3];
        }
        s0 += __shfl_xor_sync(0xffffffffu, s0, 1);
        s0 += __shfl_xor_sync(0xffffffffu, s0, 2);
        s1 += __shfl_xor_sync(0xffffffffu, s1, 1);
        s1 += __shfl_xor_sync(0xffffffffu, s1, 2);
        l0 = l0 * f0 + s0;
        l1 = l1 * f1 + s1;

#pragma unroll
        for (int nt = 0; nt < 8; nt++) {
            o[nt][0] *= f0; o[nt][1] *= f0;
            o[nt][2] *= f1; o[nt][3] *= f1;
        }

        // ---- O += P V (3-pass) ----
#pragma unroll
        for (int kt = 0; kt < 4; kt++) {
            uint32_t ah[4], al[4];
            hilo_h2(sc[2 * kt][0],     sc[2 * kt][1],     ah[0], al[0]);
            hilo_h2(sc[2 * kt][2],     sc[2 * kt][3],     ah[1], al[1]);
            hilo_h2(sc[2 * kt + 1][0], sc[2 * kt + 1][1], ah[2], al[2]);
            hilo_h2(sc[2 * kt + 1][2], sc[2 * kt + 1][3], ah[3], al[3]);

            uint32_t bvh[8][2], bvl[8][2];
#pragma unroll
            for (int jp = 0; jp < 4; jp++) {
                uint32_t t[4];
                ldsm4t(t, so + 1 * AKB + voff + kt * 16 * AROWB + jp * 32);
                bvh[jp * 2][0] = t[0]; bvh[jp * 2][1] = t[1];
                bvh[jp * 2 + 1][0] = t[2]; bvh[jp * 2 + 1][1] = t[3];
                ldsm4t(t, so + 2 * AKB + voff + kt * 16 * AROWB + jp * 32);
                bvl[jp * 2][0] = t[0]; bvl[jp * 2][1] = t[1];
                bvl[jp * 2 + 1][0] = t[2]; bvl[jp * 2 + 1][1] = t[3];
            }
#pragma unroll
            for (int nt = 0; nt < 8; nt++) {
                mma16816(o[nt], ah, bvh[nt]);
                mma16816(o[nt], ah, bvl[nt]);
                mma16816(o[nt], al, bvh[nt]);
            }
        }

        __syncthreads();
        const int nb2 = (kb + 2 < nkb) ? (kb + 2) : (nkb - 1);
        load_kv((kb + 2) & 1, nb2);
        CP_COMMIT();
    }

    // ---- normalize + store ----
    const float il0 = 1.0f / l0;
    const float il1 = 1.0f / l1;
    const int lr0 = q0 + wq0 + r0;
    float* orow0 = &out[((size_t)n * LQ + lr0) * DIM + h * DH];
    float* orow1 = &out[((size_t)n * LQ + lr0 + 8) * DIM + h * DH];
#pragma unroll
    for (int nt = 0; nt < 8; nt++) {
        const int dh = nt * 8 + (lane & 3) * 2;
        float2 v0; v0.x = o[nt][0] * il0; v0.y = o[nt][1] * il0;
        float2 v1; v1.x = o[nt][2] * il1; v1.y = o[nt][3] * il1;
        *reinterpret_cast<float2*>(orow0 + dh) = v0;
        *reinterpret_cast<float2*>(orow1 + dh) = v1;
    }
}

// ----------------------------- launcher -------------------------------------
extern "C" void kernel_launch(void* const* d_in, const int* in_sizes, int n_in,
                              void* d_out, int out_size) {
    const float* query = (const float*)d_in[0];
    const float* key   = (const float*)d_in[1];
    const float* Wq    = (const float*)d_in[2];
    const float* Wk    = (const float*)d_in[3];
    const float* Wv    = (const float*)d_in[4];
    const void* pad = (in_sizes[6] == NB * LK) ? d_in[6]
                    : (in_sizes[5] == NB * LK) ? d_in[5]
                    : d_in[6];
    float* out = (float*)d_out;

    valid_kernel<<<NB, 256>>>(pad);

    __half *xqh, *xql, *xkh, *xkl, *wh, *wl;
    cudaGetSymbolAddress((void**)&xqh, g_Xqh);
    cudaGetSymbolAddress((void**)&xql, g_Xql);
    cudaGetSymbolAddress((void**)&xkh, g_Xkh);
    cudaGetSymbolAddress((void**)&xkl, g_Xkl);
    cudaGetSymbolAddress((void**)&wh,  g_Wh);
    cudaGetSymbolAddress((void**)&wl,  g_Wl);

    const int nx = NB * LQ * DIM;
    const int nw = DIM * DIM;
    cvt_kernel<<<nx / 8 / 256, 256>>>(query, xqh, xql, nx);
    cvt_kernel<<<nx / 8 / 256, 256>>>(key,   xkh, xkl, nx);
    cvt_kernel<<<nw / 8 / 256, 256>>>(Wq, wh + 0 * (size_t)nw, wl + 0 * (size_t)nw, nw);
    cvt_kernel<<<nw / 8 / 256, 256>>>(Wk, wh + 1 * (size_t)nw, wl + 1 * (size_t)nw, nw);
    cvt_kernel<<<nw / 8 / 256, 256>>>(Wv, wh + 2 * (size_t)nw, wl + 2 * (size_t)nw, nw);

    cudaFuncSetAttribute(proj_mma_kernel,
                         cudaFuncAttributeMaxDynamicSharedMemorySize, PSMEM);
    dim3 pgrid(DIM / 128, (NB * LQ) / 128, 3);
    proj_mma_kernel<<<pgrid, 256, PSMEM>>>(0);

    cudaFuncSetAttribute(attn_mma_kernel,
                         cudaFuncAttributeMaxDynamicSharedMemorySize, ASMEM);
    dim3 agrid(LQ / 128, NB * NH);
    attn_mma_kernel<<<agrid, 256, ASMEM>>>(out);
}

// round 10
// speedup vs baseline: 4.8704x; 1.1462x over previous
#include <cuda_runtime.h>
#include <cuda_fp16.h>
#include <math.h>
#include <stdint.h>

#define NB   4
#define LQ   2048
#define LK   2048
#define DIM  1024
#define NH   16
#define DH   64

// ---------------- scratch (static device arrays; no allocation) -------------
__device__ __half g_Xqh[NB * LQ * DIM];
__device__ __half g_Xql[NB * LQ * DIM];
__device__ __half g_Xkh[NB * LK * DIM];
__device__ __half g_Xkl[NB * LK * DIM];
__device__ __half g_Wh[3 * DIM * DIM];
__device__ __half g_Wl[3 * DIM * DIM];
__device__ __half g_Qh[NB * NH * LQ * DH];
__device__ __half g_Kh[NB * NH * LK * DH];   // pre-scaled by rscale[n]*log2(e)
__device__ __half g_Vh[NB * NH * LK * DH];   // correctly-rounded fp16 of V
__device__ int   g_valid[NB];
__device__ float g_rscale[NB];

// ========================= low-level helpers ================================
__device__ __forceinline__ uint32_t smem_u32(const void* p) {
    uint32_t a;
    asm("{ .reg .u64 t; cvta.to.shared.u64 t, %1; cvt.u32.u64 %0, t; }"
        : "=r"(a) : "l"(p));
    return a;
}

__device__ __forceinline__ float ex2(float x) {
    float r;
    asm("ex2.approx.f32 %0, %1;" : "=f"(r) : "f"(x));
    return r;
}

__device__ __forceinline__ void cpa16(uint32_t dst, const void* src) {
    asm volatile("cp.async.cg.shared.global [%0], [%1], 16;"
                 :: "r"(dst), "l"(src) : "memory");
}
#define CP_COMMIT() asm volatile("cp.async.commit_group;" ::: "memory")
#define CP_WAIT1()  asm volatile("cp.async.wait_group 1;" ::: "memory")

__device__ __forceinline__ void ldsm4(uint32_t* r, uint32_t addr) {
    asm volatile("ldmatrix.sync.aligned.m8n8.x4.shared.b16 {%0,%1,%2,%3}, [%4];"
                 : "=r"(r[0]), "=r"(r[1]), "=r"(r[2]), "=r"(r[3]) : "r"(addr));
}
__device__ __forceinline__ void ldsm4t(uint32_t* r, uint32_t addr) {
    asm volatile("ldmatrix.sync.aligned.m8n8.x4.trans.shared.b16 {%0,%1,%2,%3}, [%4];"
                 : "=r"(r[0]), "=r"(r[1]), "=r"(r[2]), "=r"(r[3]) : "r"(addr));
}

__device__ __forceinline__ void mma16816(float* d, const uint32_t* a,
                                         const uint32_t* b) {
    asm volatile(
        "mma.sync.aligned.m16n8k16.row.col.f32.f16.f16.f32 "
        "{%0,%1,%2,%3}, {%4,%5,%6,%7}, {%8,%9}, {%0,%1,%2,%3};"
        : "+f"(d[0]), "+f"(d[1]), "+f"(d[2]), "+f"(d[3])
        : "r"(a[0]), "r"(a[1]), "r"(a[2]), "r"(a[3]), "r"(b[0]), "r"(b[1]));
}

__device__ __forceinline__ void hilo_h2(float a, float b, uint32_t& h, uint32_t& l) {
    __half ha = __float2half_rn(a);
    __half hb = __float2half_rn(b);
    float ra = a - __half2float(ha);
    float rb = b - __half2float(hb);
    __half2 H = __halves2half2(ha, hb);
    __half2 L = __floats2half2_rn(ra, rb);
    h = *reinterpret_cast<uint32_t*>(&H);
    l = *reinterpret_cast<uint32_t*>(&L);
}

__device__ __forceinline__ uint32_t h2_only(float a, float b) {
    __half2 H = __floats2half2_rn(a, b);
    return *reinterpret_cast<uint32_t*>(&H);
}

// ---------------- valid-length + scaling from padding mask ------------------
__global__ void valid_kernel(const void* __restrict__ pad) {
    const int tid = threadIdx.x;
    const int n   = blockIdx.x;
    __shared__ int red[256];

    const unsigned* w = (const unsigned*)pad;
    int f = 0;
    for (int i = tid; i < 2048; i += 256) {
        unsigned v = w[i];
        if (v == 0x3F800000u) f |= 4;
        else if (v == 0x00000001u) f |= 2;
        else if (v == 0x01000000u || v == 0x01010000u ||
                 v == 0x01010100u || v == 0x01010101u) f |= 1;
    }
    red[tid] = f;
    __syncthreads();
    for (int s = 128; s > 0; s >>= 1) {
        if (tid < s) red[tid] |= red[tid + s];
        __syncthreads();
    }
    const int fl = red[0];
    const int layout = (fl & 1) ? 0 : ((fl & 4) ? 2 : 1);
    __syncthreads();

    int c = 0;
    if (layout == 0) {
        const unsigned char* p = (const unsigned char*)pad;
        for (int j = tid; j < LK; j += 256) c += (p[n * LK + j] == 0);
    } else if (layout == 1) {
        const int* p = (const int*)pad;
        for (int j = tid; j < LK; j += 256) c += (p[n * LK + j] == 0);
    } else {
        const float* p = (const float*)pad;
        for (int j = tid; j < LK; j += 256) c += (p[n * LK + j] == 0.0f);
    }
    red[tid] = c;
    __syncthreads();
    for (int s = 128; s > 0; s >>= 1) {
        if (tid < s) red[tid] += red[tid + s];
        __syncthreads();
    }
    if (tid == 0) {
        g_valid[n]  = red[0];
        g_rscale[n] = rsqrtf((float)red[0]);
    }
}

// ---------------- one-shot f32 -> fp16 hi/lo conversion ---------------------
__global__ void cvt_kernel(const float* __restrict__ src,
                           __half* __restrict__ dh, __half* __restrict__ dl,
                           int n) {
    int i = (blockIdx.x * blockDim.x + threadIdx.x) * 8;
    if (i >= n) return;
    float4 a = *reinterpret_cast<const float4*>(src + i);
    float4 b = *reinterpret_cast<const float4*>(src + i + 4);
    uint4 H, L;
    hilo_h2(a.x, a.y, H.x, L.x);
    hilo_h2(a.z, a.w, H.y, L.y);
    hilo_h2(b.x, b.y, H.z, L.z);
    hilo_h2(b.z, b.w, H.w, L.w);
    *reinterpret_cast<uint4*>(dh + i) = H;
    *reinterpret_cast<uint4*>(dl + i) = L;
}

// ============ HMMA projection: Out = X @ W^T =================================
// Q,K: 1-pass (AhBh).  V: 3-pass (fp32 accurate) -> Vh only.
// K output pre-scaled by rscale[n]*log2(e).
#define PSTR    40
#define PROWB   (PSTR * 2)               // 80 bytes
#define PMATB   (128 * PROWB)            // 10240 bytes per matrix tile
#define PSTGB   (4 * PMATB)              // 40960 per stage (Ah,Al,Bh,Bl)
#define PSMEM   (2 * PSTGB)              // 81920

__global__ __launch_bounds__(256, 1)
void proj_mma_kernel(int dummy) {
    extern __shared__ char smem[];
    const uint32_t sb = smem_u32(smem);

    const int tid  = threadIdx.x;
    const int wid  = tid >> 5;
    const int lane = tid & 31;
    const int grp  = lane >> 3;

    const int which = blockIdx.z;
    const bool three_pass = (which == 2);
    const __half* __restrict__ XH = (which == 0) ? g_Xqh : g_Xkh;
    const __half* __restrict__ XL = (which == 0) ? g_Xql : g_Xkl;
    const __half* __restrict__ WH = g_Wh + (size_t)which * DIM * DIM;
    const __half* __restrict__ WL = g_Wl + (size_t)which * DIM * DIM;
    __half* __restrict__ OutH = (which == 0) ? g_Qh : (which == 1) ? g_Kh : g_Vh;

    const int m0B = blockIdx.y * 128;
    const int n0B = blockIdx.x * 128;
    const int m0W = (wid >> 2) * 64;
    const int n0W = (wid & 3) * 32;

    auto load_stage = [&](int buf, int k0) {
        const uint32_t bo = sb + buf * PSTGB;
#pragma unroll
        for (int hp = 0; hp < 2; hp++) {
            int slot = tid + hp * 256;
            int r  = slot >> 2;
            int cc = slot & 3;
            uint32_t d = bo + r * PROWB + cc * 16;
            size_t ga = (size_t)(m0B + r) * DIM + k0 + cc * 8;
            size_t gb = (size_t)(n0B + r) * DIM + k0 + cc * 8;
            cpa16(d + 0 * PMATB, XH + ga);
            cpa16(d + 2 * PMATB, WH + gb);
            if (three_pass) {
                cpa16(d + 1 * PMATB, XL + ga);
                cpa16(d + 3 * PMATB, WL + gb);
            }
        }
    };

    float acc[4][4][4];
#pragma unroll
    for (int mt = 0; mt < 4; mt++)
#pragma unroll
        for (int nt = 0; nt < 4; nt++)
#pragma unroll
            for (int q = 0; q < 4; q++) acc[mt][nt][q] = 0.f;

    const int aoff = (m0W + (lane & 15)) * PROWB + (lane >> 4) * 16;
    const int boff = (n0W + (grp >> 1) * 8 + (lane & 7)) * PROWB + (grp & 1) * 16;

    load_stage(0, 0);  CP_COMMIT();
    load_stage(1, 32); CP_COMMIT();

    for (int it = 0; it < 32; it++) {
        CP_WAIT1();
        __syncthreads();
        const uint32_t bo = sb + (it & 1) * PSTGB;
        const uint32_t aH = bo + 0 * PMATB + aoff;
        const uint32_t aL = bo + 1 * PMATB + aoff;
        const uint32_t bH = bo + 2 * PMATB + boff;
        const uint32_t bL = bo + 3 * PMATB + boff;

#pragma unroll
        for (int ks = 0; ks < 2; ks++) {
            const int kb = ks * 32;
            uint32_t ah[4][4], al[4][4], bh[4][2], bl[4][2];
#pragma unroll
            for (int mt = 0; mt < 4; mt++) {
                ldsm4(ah[mt], aH + mt * 16 * PROWB + kb);
                if (three_pass) ldsm4(al[mt], aL + mt * 16 * PROWB + kb);
            }
#pragma unroll
            for (int bt = 0; bt < 2; bt++) {
                uint32_t t[4];
                ldsm4(t, bH + bt * 16 * PROWB + kb);
                bh[bt * 2][0] = t[0]; bh[bt * 2][1] = t[1];
                bh[bt * 2 + 1][0] = t[2]; bh[bt * 2 + 1][1] = t[3];
            }
            if (three_pass) {
#pragma unroll
                for (int bt = 0; bt < 2; bt++) {
                    uint32_t t[4];
                    ldsm4(t, bL + bt * 16 * PROWB + kb);
                    bl[bt * 2][0] = t[0]; bl[bt * 2][1] = t[1];
                    bl[bt * 2 + 1][0] = t[2]; bl[bt * 2 + 1][1] = t[3];
                }
            }
#pragma unroll
            for (int mt = 0; mt < 4; mt++)
#pragma unroll
                for (int nt = 0; nt < 4; nt++)
                    mma16816(acc[mt][nt], ah[mt], bh[nt]);
            if (three_pass) {
#pragma unroll
                for (int mt = 0; mt < 4; mt++)
#pragma unroll
                    for (int nt = 0; nt < 4; nt++) {
                        mma16816(acc[mt][nt], al[mt], bh[nt]);
                        mma16816(acc[mt][nt], ah[mt], bl[nt]);
                    }
            }
        }
        __syncthreads();
        const int ns = (it + 2 < 32) ? (it + 2) : 31;
        load_stage((it + 2) & 1, ns * 32);
        CP_COMMIT();
    }

    const int rr  = lane >> 2;
    const int cc2 = (lane & 3) * 2;
#pragma unroll
    for (int mt = 0; mt < 4; mt++) {
#pragma unroll
        for (int hp = 0; hp < 2; hp++) {
            const int m = m0B + m0W + mt * 16 + rr + hp * 8;
            const int n = m >> 11;
            const int l = m & 2047;
            const float ksc = (which == 1) ? g_rscale[n] * 1.44269504f : 1.0f;
            const size_t rowb = ((size_t)(n * NH) * LQ + l) * DH;
#pragma unroll
            for (int nt = 0; nt < 4; nt++) {
                const int j  = n0B + n0W + nt * 8 + cc2;
                const int h  = j >> 6;
                const int dh = j & 63;
                const size_t o = rowb + (size_t)h * LQ * DH + dh;
                *reinterpret_cast<uint32_t*>(&OutH[o]) =
                    h2_only(acc[mt][nt][hp * 2 + 0] * ksc,
                            acc[mt][nt][hp * 2 + 1] * ksc);
            }
        }
    }
}

// ================= FA2 attention, fp16 HMMA ================================
// S = 1-pass (Qh·Kh; K pre-scaled by rscale*log2e; exp -> ex2).
// PV = 1-pass (Ph·Vh).  KV stage: Kh, Vh.
#define ASTR    72
#define AROWB   (ASTR * 2)               // 144 bytes
#define AQB     (128 * AROWB)            // 18432 (Qh only)
#define AKB     (64 * AROWB)             // 9216 per K/V matrix
#define ASTG0   AQB                      // 18432
#define ASTGB   (2 * AKB)                // 18432 per stage (Kh,Vh)
#define ASMEM   (ASTG0 + 2 * ASTGB)      // 55296

__global__ __launch_bounds__(256, 1)
void attn_mma_kernel(float* __restrict__ out) {
    extern __shared__ char smem[];
    const uint32_t sb = smem_u32(smem);

    const int tid  = threadIdx.x;
    const int wid  = tid >> 5;
    const int lane = tid & 31;
    const int grp  = lane >> 3;

    const int q0 = blockIdx.x * 128;
    const int nh = blockIdx.y;
    const int n  = nh >> 4;
    const int h  = nh & 15;

    const int valid = g_valid[n];
    const int kend  = min(valid, q0 + 128);
    const int nkb   = (kend + 63) >> 6;   // >= 2 always (valid >= 1024)

    const size_t base = (size_t)nh * LK * DH;
    const __half* __restrict__ Qhb = g_Qh + base;
    const __half* __restrict__ Khb = g_Kh + base;
    const __half* __restrict__ Vhb = g_Vh + base;

    // Q: 1 mat x 128 rows x 8 chunks = 1024 chunks -> 4 per thread
    auto load_q = [&]() {
#pragma unroll
        for (int i = 0; i < 4; i++) {
            int c  = tid + i * 256;
            int r  = c >> 3;
            int cc = c & 7;
            cpa16(sb + r * AROWB + cc * 16, Qhb + (size_t)(q0 + r) * DH + cc * 8);
        }
    };
    // KV: 2 mats x 64 rows x 8 chunks = 1024 chunks -> 4 per thread
    auto load_kv = [&](int buf, int kb) {
        const int k0 = kb * 64;
        const uint32_t so = sb + ASTG0 + buf * ASTGB;
#pragma unroll
        for (int i = 0; i < 4; i++) {
            int c   = tid + i * 256;          // 0..1023
            int mat = c >> 9;                 // 0:Kh 1:Vh
            int r   = (c >> 3) & 63;
            int cc  = c & 7;
            const __half* src = (mat == 0) ? Khb : Vhb;
            src += (size_t)(k0 + r) * DH + cc * 8;
            cpa16(so + mat * AKB + r * AROWB + cc * 16, src);
        }
    };

    const int wq0 = wid * 16;
    const int r0  = lane >> 2;
    const int qr0 = q0 + wq0 + r0;
    const int qr1 = qr0 + 8;

    const int qoff = (wq0 + (lane & 15)) * AROWB + (lane >> 4) * 16;
    const int koff = ((grp >> 1) * 8 + (lane & 7)) * AROWB + (grp & 1) * 16;
    const int voff = ((grp & 1) * 8 + (lane & 7)) * AROWB + (grp >> 1) * 16;

    uint32_t qh[4][4];
    float o[8][4];
#pragma unroll
    for (int nt = 0; nt < 8; nt++)
#pragma unroll
        for (int q = 0; q < 4; q++) o[nt][q] = 0.f;
    float m0 = -1e30f, m1 = -1e30f, l0 = 0.f, l1 = 0.f;

    load_q();
    load_kv(0, 0);
    CP_COMMIT();
    load_kv(1, (nkb > 1) ? 1 : 0);
    CP_COMMIT();

    for (int kb = 0; kb < nkb; kb++) {
        CP_WAIT1();
        __syncthreads();
        const int k0 = kb * 64;
        const uint32_t so = sb + ASTG0 + (kb & 1) * ASTGB;

        if (kb == 0) {
#pragma unroll
            for (int kt = 0; kt < 4; kt++)
                ldsm4(qh[kt], sb + qoff + kt * 32);
        }

        // ---- S = Q K^T (1-pass; K carries rscale*log2e) ----
        float sc[8][4];
#pragma unroll
        for (int nt = 0; nt < 8; nt++)
#pragma unroll
            for (int q = 0; q < 4; q++) sc[nt][q] = 0.f;

#pragma unroll
        for (int kt = 0; kt < 4; kt++) {
            uint32_t bh[8][2];
#pragma unroll
            for (int bt = 0; bt < 4; bt++) {
                uint32_t t[4];
                ldsm4(t, so + 0 * AKB + koff + bt * 16 * AROWB + kt * 32);
                bh[bt * 2][0] = t[0]; bh[bt * 2][1] = t[1];
                bh[bt * 2 + 1][0] = t[2]; bh[bt * 2 + 1][1] = t[3];
            }
#pragma unroll
            for (int nt = 0; nt < 8; nt++)
                mma16816(sc[nt], qh[kt], bh[nt]);
        }

        // ---- mask (scores already scaled, log2 domain) ----
#pragma unroll
        for (int nt = 0; nt < 8; nt++) {
            const int kc = k0 + nt * 8 + (lane & 3) * 2;
            if (kc     > qr0 || kc     >= valid) sc[nt][0] = -1e30f;
            if (kc + 1 > qr0 || kc + 1 >= valid) sc[nt][1] = -1e30f;
            if (kc     > qr1 || kc     >= valid) sc[nt][2] = -1e30f;
            if (kc + 1 > qr1 || kc + 1 >= valid) sc[nt][3] = -1e30f;
        }

        // ---- online softmax (base-2) ----
        float mx0 = -1e30f, mx1 = -1e30f;
#pragma unroll
        for (int nt = 0; nt < 8; nt++) {
            mx0 = fmaxf(mx0, fmaxf(sc[nt][0], sc[nt][1]));
            mx1 = fmaxf(mx1, fmaxf(sc[nt][2], sc[nt][3]));
        }
        mx0 = fmaxf(mx0, __shfl_xor_sync(0xffffffffu, mx0, 1));
        mx0 = fmaxf(mx0, __shfl_xor_sync(0xffffffffu, mx0, 2));
        mx1 = fmaxf(mx1, __shfl_xor_sync(0xffffffffu, mx1, 1));
        mx1 = fmaxf(mx1, __shfl_xor_sync(0xffffffffu, mx1, 2));
        const float mn0 = fmaxf(m0, mx0);
        const float mn1 = fmaxf(m1, mx1);
        const float f0 = ex2(m0 - mn0);
        const float f1 = ex2(m1 - mn1);
        m0 = mn0; m1 = mn1;

        float s0 = 0.f, s1 = 0.f;
#pragma unroll
        for (int nt = 0; nt < 8; nt++) {
            sc[nt][0] = ex2(sc[nt][0] - mn0);
            sc[nt][1] = ex2(sc[nt][1] - mn0);
            sc[nt][2] = ex2(sc[nt][2] - mn1);
            sc[nt][3] = ex2(sc[nt][3] - mn1);
            s0 += sc[nt][0] + sc[nt][1];
            s1 += sc[nt][2] + sc[nt][3];
        }
        s0 += __shfl_xor_sync(0xffffffffu, s0, 1);
        s0 += __shfl_xor_sync(0xffffffffu, s0, 2);
        s1 += __shfl_xor_sync(0xffffffffu, s1, 1);
        s1 += __shfl_xor_sync(0xffffffffu, s1, 2);
        l0 = l0 * f0 + s0;
        l1 = l1 * f1 + s1;

#pragma unroll
        for (int nt = 0; nt < 8; nt++) {
            o[nt][0] *= f0; o[nt][1] *= f0;
            o[nt][2] *= f1; o[nt][3] *= f1;
        }

        // ---- O += P V (1-pass: Ph x Vh) ----
#pragma unroll
        for (int kt = 0; kt < 4; kt++) {
            uint32_t ah[4];
            ah[0] = h2_only(sc[2 * kt][0],     sc[2 * kt][1]);
            ah[1] = h2_only(sc[2 * kt][2],     sc[2 * kt][3]);
            ah[2] = h2_only(sc[2 * kt + 1][0], sc[2 * kt + 1][1]);
            ah[3] = h2_only(sc[2 * kt + 1][2], sc[2 * kt + 1][3]);

            uint32_t bvh[8][2];
#pragma unroll
            for (int jp = 0; jp < 4; jp++) {
                uint32_t t[4];
                ldsm4t(t, so + 1 * AKB + voff + kt * 16 * AROWB + jp * 32);
                bvh[jp * 2][0] = t[0]; bvh[jp * 2][1] = t[1];
                bvh[jp * 2 + 1][0] = t[2]; bvh[jp * 2 + 1][1] = t[3];
            }
#pragma unroll
            for (int nt = 0; nt < 8; nt++)
                mma16816(o[nt], ah, bvh[nt]);
        }

        __syncthreads();
        const int nb2 = (kb + 2 < nkb) ? (kb + 2) : (nkb - 1);
        load_kv((kb + 2) & 1, nb2);
        CP_COMMIT();
    }

    // ---- normalize + store ----
    const float il0 = 1.0f / l0;
    const float il1 = 1.0f / l1;
    const int lr0 = q0 + wq0 + r0;
    float* orow0 = &out[((size_t)n * LQ + lr0) * DIM + h * DH];
    float* orow1 = &out[((size_t)n * LQ + lr0 + 8) * DIM + h * DH];
#pragma unroll
    for (int nt = 0; nt < 8; nt++) {
        const int dh = nt * 8 + (lane & 3) * 2;
        float2 v0; v0.x = o[nt][0] * il0; v0.y = o[nt][1] * il0;
        float2 v1; v1.x = o[nt][2] * il1; v1.y = o[nt][3] * il1;
        *reinterpret_cast<float2*>(orow0 + dh) = v0;
        *reinterpret_cast<float2*>(orow1 + dh) = v1;
    }
}

// ----------------------------- launcher -------------------------------------
extern "C" void kernel_launch(void* const* d_in, const int* in_sizes, int n_in,
                              void* d_out, int out_size) {
    const float* query = (const float*)d_in[0];
    const float* key   = (const float*)d_in[1];
    const float* Wq    = (const float*)d_in[2];
    const float* Wk    = (const float*)d_in[3];
    const float* Wv    = (const float*)d_in[4];
    const void* pad = (in_sizes[6] == NB * LK) ? d_in[6]
                    : (in_sizes[5] == NB * LK) ? d_in[5]
                    : d_in[6];
    float* out = (float*)d_out;

    valid_kernel<<<NB, 256>>>(pad);

    __half *xqh, *xql, *xkh, *xkl, *wh, *wl;
    cudaGetSymbolAddress((void**)&xqh, g_Xqh);
    cudaGetSymbolAddress((void**)&xql, g_Xql);
    cudaGetSymbolAddress((void**)&xkh, g_Xkh);
    cudaGetSymbolAddress((void**)&xkl, g_Xkl);
    cudaGetSymbolAddress((void**)&wh,  g_Wh);
    cudaGetSymbolAddress((void**)&wl,  g_Wl);

    const int nx = NB * LQ * DIM;
    const int nw = DIM * DIM;
    cvt_kernel<<<nx / 8 / 256, 256>>>(query, xqh, xql, nx);
    cvt_kernel<<<nx / 8 / 256, 256>>>(key,   xkh, xkl, nx);
    cvt_kernel<<<nw / 8 / 256, 256>>>(Wq, wh + 0 * (size_t)nw, wl + 0 * (size_t)nw, nw);
    cvt_kernel<<<nw / 8 / 256, 256>>>(Wk, wh + 1 * (size_t)nw, wl + 1 * (size_t)nw, nw);
    cvt_kernel<<<nw / 8 / 256, 256>>>(Wv, wh + 2 * (size_t)nw, wl + 2 * (size_t)nw, nw);

    cudaFuncSetAttribute(proj_mma_kernel,
                         cudaFuncAttributeMaxDynamicSharedMemorySize, PSMEM);
    dim3 pgrid(DIM / 128, (NB * LQ) / 128, 3);
    proj_mma_kernel<<<pgrid, 256, PSMEM>>>(0);

    cudaFuncSetAttribute(attn_mma_kernel,
                         cudaFuncAttributeMaxDynamicSharedMemorySize, ASMEM);
    dim3 agrid(LQ / 128, NB * NH);
    attn_mma_kernel<<<agrid, 256, ASMEM>>>(out);
}

// round 11
// speedup vs baseline: 5.1958x; 1.0668x over previous
#include <cuda_runtime.h>
#include <cuda_fp16.h>
#include <math.h>
#include <stdint.h>

#define NB   4
#define LQ   2048
#define LK   2048
#define DIM  1024
#define NH   16
#define DH   64

// ---------------- scratch (static device arrays; no allocation) -------------
__device__ __half g_Xqh[NB * LQ * DIM];
__device__ __half g_Xkh[NB * LK * DIM];
__device__ __half g_Xkl[NB * LK * DIM];
__device__ __half g_Wh[3 * DIM * DIM];
__device__ __half g_Wl[DIM * DIM];           // V only
__device__ __half g_Qh[NB * NH * LQ * DH];
__device__ __half g_Kh[NB * NH * LK * DH];   // pre-scaled by rscale[n]*log2(e)
__device__ __half g_Vh[NB * NH * LK * DH];   // correctly-rounded fp16 of V
__device__ int   g_valid[NB];
__device__ float g_rscale[NB];

// ========================= low-level helpers ================================
__device__ __forceinline__ uint32_t smem_u32(const void* p) {
    uint32_t a;
    asm("{ .reg .u64 t; cvta.to.shared.u64 t, %1; cvt.u32.u64 %0, t; }"
        : "=r"(a) : "l"(p));
    return a;
}

__device__ __forceinline__ float ex2(float x) {
    float r;
    asm("ex2.approx.f32 %0, %1;" : "=f"(r) : "f"(x));
    return r;
}

__device__ __forceinline__ void cpa16(uint32_t dst, const void* src) {
    asm volatile("cp.async.cg.shared.global [%0], [%1], 16;"
                 :: "r"(dst), "l"(src) : "memory");
}
#define CP_COMMIT() asm volatile("cp.async.commit_group;" ::: "memory")
#define CP_WAIT1()  asm volatile("cp.async.wait_group 1;" ::: "memory")

__device__ __forceinline__ void ldsm4(uint32_t* r, uint32_t addr) {
    asm volatile("ldmatrix.sync.aligned.m8n8.x4.shared.b16 {%0,%1,%2,%3}, [%4];"
                 : "=r"(r[0]), "=r"(r[1]), "=r"(r[2]), "=r"(r[3]) : "r"(addr));
}
__device__ __forceinline__ void ldsm4t(uint32_t* r, uint32_t addr) {
    asm volatile("ldmatrix.sync.aligned.m8n8.x4.trans.shared.b16 {%0,%1,%2,%3}, [%4];"
                 : "=r"(r[0]), "=r"(r[1]), "=r"(r[2]), "=r"(r[3]) : "r"(addr));
}

__device__ __forceinline__ void mma16816(float* d, const uint32_t* a,
                                         const uint32_t* b) {
    asm volatile(
        "mma.sync.aligned.m16n8k16.row.col.f32.f16.f16.f32 "
        "{%0,%1,%2,%3}, {%4,%5,%6,%7}, {%8,%9}, {%0,%1,%2,%3};"
        : "+f"(d[0]), "+f"(d[1]), "+f"(d[2]), "+f"(d[3])
        : "r"(a[0]), "r"(a[1]), "r"(a[2]), "r"(a[3]), "r"(b[0]), "r"(b[1]));
}

__device__ __forceinline__ void hilo_h2(float a, float b, uint32_t& h, uint32_t& l) {
    __half ha = __float2half_rn(a);
    __half hb = __float2half_rn(b);
    float ra = a - __half2float(ha);
    float rb = b - __half2float(hb);
    __half2 H = __halves2half2(ha, hb);
    __half2 L = __floats2half2_rn(ra, rb);
    h = *reinterpret_cast<uint32_t*>(&H);
    l = *reinterpret_cast<uint32_t*>(&L);
}

__device__ __forceinline__ uint32_t h2_only(float a, float b) {
    __half2 H = __floats2half2_rn(a, b);
    return *reinterpret_cast<uint32_t*>(&H);
}

// ---------------- valid-length + scaling from padding mask ------------------
__global__ void valid_kernel(const void* __restrict__ pad) {
    const int tid = threadIdx.x;
    const int n   = blockIdx.x;
    __shared__ int red[256];

    const unsigned* w = (const unsigned*)pad;
    int f = 0;
    for (int i = tid; i < 2048; i += 256) {
        unsigned v = w[i];
        if (v == 0x3F800000u) f |= 4;
        else if (v == 0x00000001u) f |= 2;
        else if (v == 0x01000000u || v == 0x01010000u ||
                 v == 0x01010100u || v == 0x01010101u) f |= 1;
    }
    red[tid] = f;
    __syncthreads();
    for (int s = 128; s > 0; s >>= 1) {
        if (tid < s) red[tid] |= red[tid + s];
        __syncthreads();
    }
    const int fl = red[0];
    const int layout = (fl & 1) ? 0 : ((fl & 4) ? 2 : 1);
    __syncthreads();

    int c = 0;
    if (layout == 0) {
        const unsigned char* p = (const unsigned char*)pad;
        for (int j = tid; j < LK; j += 256) c += (p[n * LK + j] == 0);
    } else if (layout == 1) {
        const int* p = (const int*)pad;
        for (int j = tid; j < LK; j += 256) c += (p[n * LK + j] == 0);
    } else {
        const float* p = (const float*)pad;
        for (int j = tid; j < LK; j += 256) c += (p[n * LK + j] == 0.0f);
    }
    red[tid] = c;
    __syncthreads();
    for (int s = 128; s > 0; s >>= 1) {
        if (tid < s) red[tid] += red[tid + s];
        __syncthreads();
    }
    if (tid == 0) {
        g_valid[n]  = red[0];
        g_rscale[n] = rsqrtf((float)red[0]);
    }
}

// ---------------- f32 -> fp16 conversions -----------------------------------
__global__ void cvt_kernel(const float* __restrict__ src,
                           __half* __restrict__ dh, __half* __restrict__ dl,
                           int n) {
    int i = (blockIdx.x * blockDim.x + threadIdx.x) * 8;
    if (i >= n) return;
    float4 a = *reinterpret_cast<const float4*>(src + i);
    float4 b = *reinterpret_cast<const float4*>(src + i + 4);
    uint4 H, L;
    hilo_h2(a.x, a.y, H.x, L.x);
    hilo_h2(a.z, a.w, H.y, L.y);
    hilo_h2(b.x, b.y, H.z, L.z);
    hilo_h2(b.z, b.w, H.w, L.w);
    *reinterpret_cast<uint4*>(dh + i) = H;
    *reinterpret_cast<uint4*>(dl + i) = L;
}

__global__ void cvt_hi_kernel(const float* __restrict__ src,
                              __half* __restrict__ dh, int n) {
    int i = (blockIdx.x * blockDim.x + threadIdx.x) * 8;
    if (i >= n) return;
    float4 a = *reinterpret_cast<const float4*>(src + i);
    float4 b = *reinterpret_cast<const float4*>(src + i + 4);
    uint4 H;
    H.x = h2_only(a.x, a.y);
    H.y = h2_only(a.z, a.w);
    H.z = h2_only(b.x, b.y);
    H.w = h2_only(b.z, b.w);
    *reinterpret_cast<uint4*>(dh + i) = H;
}

// ============ HMMA projection: Out = X @ W^T =================================
// Q,K: 1-pass (AhBh).  V: 3-pass (fp32 accurate) -> Vh only.
// K output pre-scaled by rscale[n]*log2(e).
#define PSTR    40
#define PROWB   (PSTR * 2)               // 80 bytes
#define PMATB   (128 * PROWB)            // 10240 bytes per matrix tile
#define PSTGB   (4 * PMATB)              // 40960 per stage (Ah,Al,Bh,Bl)
#define PSMEM   (2 * PSTGB)              // 81920

__global__ __launch_bounds__(256, 1)
void proj_mma_kernel(int dummy) {
    extern __shared__ char smem[];
    const uint32_t sb = smem_u32(smem);

    const int tid  = threadIdx.x;
    const int wid  = tid >> 5;
    const int lane = tid & 31;
    const int grp  = lane >> 3;

    const int which = blockIdx.z;
    const bool three_pass = (which == 2);
    const __half* __restrict__ XH = (which == 0) ? g_Xqh : g_Xkh;
    const __half* __restrict__ XL = g_Xkl;               // only read when which==2
    const __half* __restrict__ WH = g_Wh + (size_t)which * DIM * DIM;
    const __half* __restrict__ WL = g_Wl;                // only read when which==2
    __half* __restrict__ OutH = (which == 0) ? g_Qh : (which == 1) ? g_Kh : g_Vh;

    const int m0B = blockIdx.y * 128;
    const int n0B = blockIdx.x * 128;
    const int m0W = (wid >> 2) * 64;
    const int n0W = (wid & 3) * 32;

    auto load_stage = [&](int buf, int k0) {
        const uint32_t bo = sb + buf * PSTGB;
#pragma unroll
        for (int hp = 0; hp < 2; hp++) {
            int slot = tid + hp * 256;
            int r  = slot >> 2;
            int cc = slot & 3;
            uint32_t d = bo + r * PROWB + cc * 16;
            size_t ga = (size_t)(m0B + r) * DIM + k0 + cc * 8;
            size_t gb = (size_t)(n0B + r) * DIM + k0 + cc * 8;
            cpa16(d + 0 * PMATB, XH + ga);
            cpa16(d + 2 * PMATB, WH + gb);
            if (three_pass) {
                cpa16(d + 1 * PMATB, XL + ga);
                cpa16(d + 3 * PMATB, WL + gb);
            }
        }
    };

    float acc[4][4][4];
#pragma unroll
    for (int mt = 0; mt < 4; mt++)
#pragma unroll
        for (int nt = 0; nt < 4; nt++)
#pragma unroll
            for (int q = 0; q < 4; q++) acc[mt][nt][q] = 0.f;

    const int aoff = (m0W + (lane & 15)) * PROWB + (lane >> 4) * 16;
    const int boff = (n0W + (grp >> 1) * 8 + (lane & 7)) * PROWB + (grp & 1) * 16;

    load_stage(0, 0);  CP_COMMIT();
    load_stage(1, 32); CP_COMMIT();

    for (int it = 0; it < 32; it++) {
        CP_WAIT1();
        __syncthreads();
        const uint32_t bo = sb + (it & 1) * PSTGB;
        const uint32_t aH = bo + 0 * PMATB + aoff;
        const uint32_t aL = bo + 1 * PMATB + aoff;
        const uint32_t bH = bo + 2 * PMATB + boff;
        const uint32_t bL = bo + 3 * PMATB + boff;

#pragma unroll
        for (int ks = 0; ks < 2; ks++) {
            const int kb = ks * 32;
            uint32_t ah[4][4], al[4][4], bh[4][2], bl[4][2];
#pragma unroll
            for (int mt = 0; mt < 4; mt++) {
                ldsm4(ah[mt], aH + mt * 16 * PROWB + kb);
                if (three_pass) ldsm4(al[mt], aL + mt * 16 * PROWB + kb);
            }
#pragma unroll
            for (int bt = 0; bt < 2; bt++) {
                uint32_t t[4];
                ldsm4(t, bH + bt * 16 * PROWB + kb);
                bh[bt * 2][0] = t[0]; bh[bt * 2][1] = t[1];
                bh[bt * 2 + 1][0] = t[2]; bh[bt * 2 + 1][1] = t[3];
            }
            if (three_pass) {
#pragma unroll
                for (int bt = 0; bt < 2; bt++) {
                    uint32_t t[4];
                    ldsm4(t, bL + bt * 16 * PROWB + kb);
                    bl[bt * 2][0] = t[0]; bl[bt * 2][1] = t[1];
                    bl[bt * 2 + 1][0] = t[2]; bl[bt * 2 + 1][1] = t[3];
                }
            }
#pragma unroll
            for (int mt = 0; mt < 4; mt++)
#pragma unroll
                for (int nt = 0; nt < 4; nt++)
                    mma16816(acc[mt][nt], ah[mt], bh[nt]);
            if (three_pass) {
#pragma unroll
                for (int mt = 0; mt < 4; mt++)
#pragma unroll
                    for (int nt = 0; nt < 4; nt++) {
                        mma16816(acc[mt][nt], al[mt], bh[nt]);
                        mma16816(acc[mt][nt], ah[mt], bl[nt]);
                    }
            }
        }
        __syncthreads();
        const int ns = (it + 2 < 32) ? (it + 2) : 31;
        load_stage((it + 2) & 1, ns * 32);
        CP_COMMIT();
    }

    const int rr  = lane >> 2;
    const int cc2 = (lane & 3) * 2;
#pragma unroll
    for (int mt = 0; mt < 4; mt++) {
#pragma unroll
        for (int hp = 0; hp < 2; hp++) {
            const int m = m0B + m0W + mt * 16 + rr + hp * 8;
            const int n = m >> 11;
            const int l = m & 2047;
            const float ksc = (which == 1) ? g_rscale[n] * 1.44269504f : 1.0f;
            const size_t rowb = ((size_t)(n * NH) * LQ + l) * DH;
#pragma unroll
            for (int nt = 0; nt < 4; nt++) {
                const int j  = n0B + n0W + nt * 8 + cc2;
                const int h  = j >> 6;
                const int dh = j & 63;
                const size_t o = rowb + (size_t)h * LQ * DH + dh;
                *reinterpret_cast<uint32_t*>(&OutH[o]) =
                    h2_only(acc[mt][nt][hp * 2 + 0] * ksc,
                            acc[mt][nt][hp * 2 + 1] * ksc);
            }
        }
    }
}

// ================= FA2 attention, fp16 HMMA ================================
// S = 1-pass (Qh·Kh; K pre-scaled by rscale*log2e; exp -> ex2).
// PV = 1-pass (Ph·Vh).  KV stage: Kh, Vh.  Occupancy 2.
#define ASTR    72
#define AROWB   (ASTR * 2)               // 144 bytes
#define AQB     (128 * AROWB)            // 18432 (Qh only)
#define AKB     (64 * AROWB)             // 9216 per K/V matrix
#define ASTG0   AQB                      // 18432
#define ASTGB   (2 * AKB)                // 18432 per stage (Kh,Vh)
#define ASMEM   (ASTG0 + 2 * ASTGB)      // 55296

__global__ __launch_bounds__(256, 2)
void attn_mma_kernel(float* __restrict__ out) {
    extern __shared__ char smem[];
    const uint32_t sb = smem_u32(smem);

    const int tid  = threadIdx.x;
    const int wid  = tid >> 5;
    const int lane = tid & 31;
    const int grp  = lane >> 3;

    const int q0 = blockIdx.x * 128;
    const int nh = blockIdx.y;
    const int n  = nh >> 4;
    const int h  = nh & 15;

    const int valid = g_valid[n];
    const int kend  = min(valid, q0 + 128);
    const int nkb   = (kend + 63) >> 6;   // >= 2 always (valid >= 1024)

    const size_t base = (size_t)nh * LK * DH;
    const __half* __restrict__ Qhb = g_Qh + base;
    const __half* __restrict__ Khb = g_Kh + base;
    const __half* __restrict__ Vhb = g_Vh + base;

    auto load_q = [&]() {
#pragma unroll
        for (int i = 0; i < 4; i++) {
            int c  = tid + i * 256;
            int r  = c >> 3;
            int cc = c & 7;
            cpa16(sb + r * AROWB + cc * 16, Qhb + (size_t)(q0 + r) * DH + cc * 8);
        }
    };
    auto load_kv = [&](int buf, int kb) {
        const int k0 = kb * 64;
        const uint32_t so = sb + ASTG0 + buf * ASTGB;
#pragma unroll
        for (int i = 0; i < 4; i++) {
            int c   = tid + i * 256;
            int mat = c >> 9;                 // 0:Kh 1:Vh
            int r   = (c >> 3) & 63;
            int cc  = c & 7;
            const __half* src = (mat == 0) ? Khb : Vhb;
            src += (size_t)(k0 + r) * DH + cc * 8;
            cpa16(so + mat * AKB + r * AROWB + cc * 16, src);
        }
    };

    const int wq0 = wid * 16;
    const int r0  = lane >> 2;
    const int qr0 = q0 + wq0 + r0;
    const int qr1 = qr0 + 8;

    const int qoff = (wq0 + (lane & 15)) * AROWB + (lane >> 4) * 16;
    const int koff = ((grp >> 1) * 8 + (lane & 7)) * AROWB + (grp & 1) * 16;
    const int voff = ((grp & 1) * 8 + (lane & 7)) * AROWB + (grp >> 1) * 16;

    uint32_t qh[4][4];
    float o[8][4];
#pragma unroll
    for (int nt = 0; nt < 8; nt++)
#pragma unroll
        for (int q = 0; q < 4; q++) o[nt][q] = 0.f;
    float m0 = -1e30f, m1 = -1e30f, l0 = 0.f, l1 = 0.f;

    load_q();
    load_kv(0, 0);
    CP_COMMIT();
    load_kv(1, (nkb > 1) ? 1 : 0);
    CP_COMMIT();

    for (int kb = 0; kb < nkb; kb++) {
        CP_WAIT1();
        __syncthreads();
        const int k0 = kb * 64;
        const uint32_t so = sb + ASTG0 + (kb & 1) * ASTGB;

        if (kb == 0) {
#pragma unroll
            for (int kt = 0; kt < 4; kt++)
                ldsm4(qh[kt], sb + qoff + kt * 32);
        }

        // ---- S = Q K^T (1-pass; K carries rscale*log2e) ----
        float sc[8][4];
#pragma unroll
        for (int nt = 0; nt < 8; nt++)
#pragma unroll
            for (int q = 0; q < 4; q++) sc[nt][q] = 0.f;

#pragma unroll
        for (int kt = 0; kt < 4; kt++) {
            uint32_t bh[8][2];
#pragma unroll
            for (int bt = 0; bt < 4; bt++) {
                uint32_t t[4];
                ldsm4(t, so + 0 * AKB + koff + bt * 16 * AROWB + kt * 32);
                bh[bt * 2][0] = t[0]; bh[bt * 2][1] = t[1];
                bh[bt * 2 + 1][0] = t[2]; bh[bt * 2 + 1][1] = t[3];
            }
#pragma unroll
            for (int nt = 0; nt < 8; nt++)
                mma16816(sc[nt], qh[kt], bh[nt]);
        }

        // ---- mask only when this warp's rows intersect causal/pad boundary ----
        if (k0 + 63 > q0 + wq0 || k0 + 64 > valid) {
#pragma unroll
            for (int nt = 0; nt < 8; nt++) {
                const int kc = k0 + nt * 8 + (lane & 3) * 2;
                if (kc     > qr0 || kc     >= valid) sc[nt][0] = -1e30f;
                if (kc + 1 > qr0 || kc + 1 >= valid) sc[nt][1] = -1e30f;
                if (kc     > qr1 || kc     >= valid) sc[nt][2] = -1e30f;
                if (kc + 1 > qr1 || kc + 1 >= valid) sc[nt][3] = -1e30f;
            }
        }

        // ---- online softmax (base-2) ----
        float mx0 = -1e30f, mx1 = -1e30f;
#pragma unroll
        for (int nt = 0; nt < 8; nt++) {
            mx0 = fmaxf(mx0, fmaxf(sc[nt][0], sc[nt][1]));
            mx1 = fmaxf(mx1, fmaxf(sc[nt][2], sc[nt][3]));
        }
        mx0 = fmaxf(mx0, __shfl_xor_sync(0xffffffffu, mx0, 1));
        mx0 = fmaxf(mx0, __shfl_xor_sync(0xffffffffu, mx0, 2));
        mx1 = fmaxf(mx1, __shfl_xor_sync(0xffffffffu, mx1, 1));
        mx1 = fmaxf(mx1, __shfl_xor_sync(0xffffffffu, mx1, 2));
        const float mn0 = fmaxf(m0, mx0);
        const float mn1 = fmaxf(m1, mx1);
        const float f0 = ex2(m0 - mn0);
        const float f1 = ex2(m1 - mn1);
        m0 = mn0; m1 = mn1;

        float s0 = 0.f, s1 = 0.f;
#pragma unroll
        for (int nt = 0; nt < 8; nt++) {
            sc[nt][0] = ex2(sc[nt][0] - mn0);
            sc[nt][1] = ex2(sc[nt][1] - mn0);
            sc[nt][2] = ex2(sc[nt][2] - mn1);
            sc[nt][3] = ex2(sc[nt][3] - mn1);
            s0 += sc[nt][0] + sc[nt][1];
            s1 += sc[nt][2] + sc[nt][3];
        }
        s0 += __shfl_xor_sync(0xffffffffu, s0, 1);
        s0 += __shfl_xor_sync(0xffffffffu, s0, 2);
        s1 += __shfl_xor_sync(0xffffffffu, s1, 1);
        s1 += __shfl_xor_sync(0xffffffffu, s1, 2);
        l0 = l0 * f0 + s0;
        l1 = l1 * f1 + s1;

#pragma unroll
        for (int nt = 0; nt < 8; nt++) {
            o[nt][0] *= f0; o[nt][1] *= f0;
            o[nt][2] *= f1; o[nt][3] *= f1;
        }

        // ---- O += P V (1-pass: Ph x Vh) ----
#pragma unroll
        for (int kt = 0; kt < 4; kt++) {
            uint32_t ah[4];
            ah[0] = h2_only(sc[2 * kt][0],     sc[2 * kt][1]);
            ah[1] = h2_only(sc[2 * kt][2],     sc[2 * kt][3]);
            ah[2] = h2_only(sc[2 * kt + 1][0], sc[2 * kt + 1][1]);
            ah[3] = h2_only(sc[2 * kt + 1][2], sc[2 * kt + 1][3]);

            uint32_t bvh[8][2];
#pragma unroll
            for (int jp = 0; jp < 4; jp++) {
                uint32_t t[4];
                ldsm4t(t, so + 1 * AKB + voff + kt * 16 * AROWB + jp * 32);
                bvh[jp * 2][0] = t[0]; bvh[jp * 2][1] = t[1];
                bvh[jp * 2 + 1][0] = t[2]; bvh[jp * 2 + 1][1] = t[3];
            }
#pragma unroll
            for (int nt = 0; nt < 8; nt++)
                mma16816(o[nt], ah, bvh[nt]);
        }

        __syncthreads();
        const int nb2 = (kb + 2 < nkb) ? (kb + 2) : (nkb - 1);
        load_kv((kb + 2) & 1, nb2);
        CP_COMMIT();
    }

    // ---- normalize + store ----
    const float il0 = 1.0f / l0;
    const float il1 = 1.0f / l1;
    const int lr0 = q0 + wq0 + r0;
    float* orow0 = &out[((size_t)n * LQ + lr0) * DIM + h * DH];
    float* orow1 = &out[((size_t)n * LQ + lr0 + 8) * DIM + h * DH];
#pragma unroll
    for (int nt = 0; nt < 8; nt++) {
        const int dh = nt * 8 + (lane & 3) * 2;
        float2 v0; v0.x = o[nt][0] * il0; v0.y = o[nt][1] * il0;
        float2 v1; v1.x = o[nt][2] * il1; v1.y = o[nt][3] * il1;
        *reinterpret_cast<float2*>(orow0 + dh) = v0;
        *reinterpret_cast<float2*>(orow1 + dh) = v1;
    }
}

// ----------------------------- launcher -------------------------------------
extern "C" void kernel_launch(void* const* d_in, const int* in_sizes, int n_in,
                              void* d_out, int out_size) {
    const float* query = (const float*)d_in[0];
    const float* key   = (const float*)d_in[1];
    const float* Wq    = (const float*)d_in[2];
    const float* Wk    = (const float*)d_in[3];
    const float* Wv    = (const float*)d_in[4];
    const void* pad = (in_sizes[6] == NB * LK) ? d_in[6]
                    : (in_sizes[5] == NB * LK) ? d_in[5]
                    : d_in[6];
    float* out = (float*)d_out;

    valid_kernel<<<NB, 256>>>(pad);

    __half *xqh, *xkh, *xkl, *wh, *wl;
    cudaGetSymbolAddress((void**)&xqh, g_Xqh);
    cudaGetSymbolAddress((void**)&xkh, g_Xkh);
    cudaGetSymbolAddress((void**)&xkl, g_Xkl);
    cudaGetSymbolAddress((void**)&wh,  g_Wh);
    cudaGetSymbolAddress((void**)&wl,  g_Wl);

    const int nx = NB * LQ * DIM;
    const int nw = DIM * DIM;
    cvt_hi_kernel<<<nx / 8 / 256, 256>>>(query, xqh, nx);
    cvt_kernel<<<nx / 8 / 256, 256>>>(key, xkh, xkl, nx);
    cvt_hi_kernel<<<nw / 8 / 256, 256>>>(Wq, wh + 0 * (size_t)nw, nw);
    cvt_hi_kernel<<<nw / 8 / 256, 256>>>(Wk, wh + 1 * (size_t)nw, nw);
    cvt_kernel<<<nw / 8 / 256, 256>>>(Wv, wh + 2 * (size_t)nw, wl, nw);

    cudaFuncSetAttribute(proj_mma_kernel,
                         cudaFuncAttributeMaxDynamicSharedMemorySize, PSMEM);
    dim3 pgrid(DIM / 128, (NB * LQ) / 128, 3);
    proj_mma_kernel<<<pgrid, 256, PSMEM>>>(0);

    cudaFuncSetAttribute(attn_mma_kernel,
                         cudaFuncAttributeMaxDynamicSharedMemorySize, ASMEM);
    dim3 agrid(LQ / 128, NB * NH);
    attn_mma_kernel<<<agrid, 256, ASMEM>>>(out);
}

// round 12
// speedup vs baseline: 5.9929x; 1.1534x over previous
#include <cuda_runtime.h>
#include <cuda_fp16.h>
#include <math.h>
#include <stdint.h>

#define NB   4
#define LQ   2048
#define LK   2048
#define DIM  1024
#define NH   16
#define DH   64

// ---------------- scratch (static device arrays; no allocation) -------------
__device__ __half g_Xqh[NB * LQ * DIM];
__device__ __half g_Xkh[NB * LK * DIM];
__device__ __half g_Xkl[NB * LK * DIM];
__device__ __half g_Wh[3 * DIM * DIM];
__device__ __half g_Wl[DIM * DIM];           // V only
__device__ __half g_Qh[NB * NH * LQ * DH];
__device__ __half g_Kh[NB * NH * LK * DH];   // pre-scaled by rscale[n]*log2(e)
__device__ __half g_Vh[NB * NH * LK * DH];   // correctly-rounded fp16 of V
__device__ int   g_valid[NB];
__device__ float g_rscale[NB];

// ========================= low-level helpers ================================
__device__ __forceinline__ uint32_t smem_u32(const void* p) {
    uint32_t a;
    asm("{ .reg .u64 t; cvta.to.shared.u64 t, %1; cvt.u32.u64 %0, t; }"
        : "=r"(a) : "l"(p));
    return a;
}

__device__ __forceinline__ float ex2(float x) {
    float r;
    asm("ex2.approx.f32 %0, %1;" : "=f"(r) : "f"(x));
    return r;
}

__device__ __forceinline__ void cpa16(uint32_t dst, const void* src) {
    asm volatile("cp.async.cg.shared.global [%0], [%1], 16;"
                 :: "r"(dst), "l"(src) : "memory");
}
#define CP_COMMIT() asm volatile("cp.async.commit_group;" ::: "memory")
#define CP_WAIT1()  asm volatile("cp.async.wait_group 1;" ::: "memory")

__device__ __forceinline__ void ldsm4(uint32_t* r, uint32_t addr) {
    asm volatile("ldmatrix.sync.aligned.m8n8.x4.shared.b16 {%0,%1,%2,%3}, [%4];"
                 : "=r"(r[0]), "=r"(r[1]), "=r"(r[2]), "=r"(r[3]) : "r"(addr));
}
__device__ __forceinline__ void ldsm4t(uint32_t* r, uint32_t addr) {
    asm volatile("ldmatrix.sync.aligned.m8n8.x4.trans.shared.b16 {%0,%1,%2,%3}, [%4];"
                 : "=r"(r[0]), "=r"(r[1]), "=r"(r[2]), "=r"(r[3]) : "r"(addr));
}

__device__ __forceinline__ void mma16816(float* d, const uint32_t* a,
                                         const uint32_t* b) {
    asm volatile(
        "mma.sync.aligned.m16n8k16.row.col.f32.f16.f16.f32 "
        "{%0,%1,%2,%3}, {%4,%5,%6,%7}, {%8,%9}, {%0,%1,%2,%3};"
        : "+f"(d[0]), "+f"(d[1]), "+f"(d[2]), "+f"(d[3])
        : "r"(a[0]), "r"(a[1]), "r"(a[2]), "r"(a[3]), "r"(b[0]), "r"(b[1]));
}

__device__ __forceinline__ void hilo_h2(float a, float b, uint32_t& h, uint32_t& l) {
    __half ha = __float2half_rn(a);
    __half hb = __float2half_rn(b);
    float ra = a - __half2float(ha);
    float rb = b - __half2float(hb);
    __half2 H = __halves2half2(ha, hb);
    __half2 L = __floats2half2_rn(ra, rb);
    h = *reinterpret_cast<uint32_t*>(&H);
    l = *reinterpret_cast<uint32_t*>(&L);
}

__device__ __forceinline__ uint32_t h2_only(float a, float b) {
    __half2 H = __floats2half2_rn(a, b);
    return *reinterpret_cast<uint32_t*>(&H);
}

// ---------------- valid-length + scaling from padding mask ------------------
__global__ void valid_kernel(const void* __restrict__ pad) {
    const int tid = threadIdx.x;
    const int n   = blockIdx.x;
    __shared__ int red[256];

    const unsigned* w = (const unsigned*)pad;
    int f = 0;
    for (int i = tid; i < 2048; i += 256) {
        unsigned v = w[i];
        if (v == 0x3F800000u) f |= 4;
        else if (v == 0x00000001u) f |= 2;
        else if (v == 0x01000000u || v == 0x01010000u ||
                 v == 0x01010100u || v == 0x01010101u) f |= 1;
    }
    red[tid] = f;
    __syncthreads();
    for (int s = 128; s > 0; s >>= 1) {
        if (tid < s) red[tid] |= red[tid + s];
        __syncthreads();
    }
    const int fl = red[0];
    const int layout = (fl & 1) ? 0 : ((fl & 4) ? 2 : 1);
    __syncthreads();

    int c = 0;
    if (layout == 0) {
        const unsigned char* p = (const unsigned char*)pad;
        for (int j = tid; j < LK; j += 256) c += (p[n * LK + j] == 0);
    } else if (layout == 1) {
        const int* p = (const int*)pad;
        for (int j = tid; j < LK; j += 256) c += (p[n * LK + j] == 0);
    } else {
        const float* p = (const float*)pad;
        for (int j = tid; j < LK; j += 256) c += (p[n * LK + j] == 0.0f);
    }
    red[tid] = c;
    __syncthreads();
    for (int s = 128; s > 0; s >>= 1) {
        if (tid < s) red[tid] += red[tid + s];
        __syncthreads();
    }
    if (tid == 0) {
        g_valid[n]  = red[0];
        g_rscale[n] = rsqrtf((float)red[0]);
    }
}

// ---------------- f32 -> fp16 conversions -----------------------------------
__global__ void cvt_kernel(const float* __restrict__ src,
                           __half* __restrict__ dh, __half* __restrict__ dl,
                           int n) {
    int i = (blockIdx.x * blockDim.x + threadIdx.x) * 8;
    if (i >= n) return;
    float4 a = *reinterpret_cast<const float4*>(src + i);
    float4 b = *reinterpret_cast<const float4*>(src + i + 4);
    uint4 H, L;
    hilo_h2(a.x, a.y, H.x, L.x);
    hilo_h2(a.z, a.w, H.y, L.y);
    hilo_h2(b.x, b.y, H.z, L.z);
    hilo_h2(b.z, b.w, H.w, L.w);
    *reinterpret_cast<uint4*>(dh + i) = H;
    *reinterpret_cast<uint4*>(dl + i) = L;
}

__global__ void cvt_hi_kernel(const float* __restrict__ src,
                              __half* __restrict__ dh, int n) {
    int i = (blockIdx.x * blockDim.x + threadIdx.x) * 8;
    if (i >= n) return;
    float4 a = *reinterpret_cast<const float4*>(src + i);
    float4 b = *reinterpret_cast<const float4*>(src + i + 4);
    uint4 H;
    H.x = h2_only(a.x, a.y);
    H.y = h2_only(a.z, a.w);
    H.z = h2_only(b.x, b.y);
    H.w = h2_only(b.z, b.w);
    *reinterpret_cast<uint4*>(dh + i) = H;
}

// ======================= shared proj constants ===============================
#define PSTR    40
#define PROWB   (PSTR * 2)               // 80 bytes
#define PMATB   (128 * PROWB)            // 10240 bytes per matrix tile

// ============ Q/K projection: 1-pass, 2 matrices/stage, occupancy 2 ==========
#define QK_STGB (2 * PMATB)              // 20480 per stage (Ah, Bh)
#define QK_SMEM (2 * QK_STGB)            // 40960

__global__ __launch_bounds__(256, 2)
void qk_proj_kernel(int dummy) {
    extern __shared__ char smem[];
    const uint32_t sb = smem_u32(smem);

    const int tid  = threadIdx.x;
    const int wid  = tid >> 5;
    const int lane = tid & 31;
    const int grp  = lane >> 3;

    const int which = blockIdx.z;        // 0:Q 1:K
    const __half* __restrict__ XH = (which == 0) ? g_Xqh : g_Xkh;
    const __half* __restrict__ WH = g_Wh + (size_t)which * DIM * DIM;
    __half* __restrict__ OutH = (which == 0) ? g_Qh : g_Kh;

    const int m0B = blockIdx.y * 128;
    const int n0B = blockIdx.x * 128;
    const int m0W = (wid >> 2) * 64;
    const int n0W = (wid & 3) * 32;

    auto load_stage = [&](int buf, int k0) {
        const uint32_t bo = sb + buf * QK_STGB;
#pragma unroll
        for (int hp = 0; hp < 2; hp++) {
            int slot = tid + hp * 256;
            int r  = slot >> 2;
            int cc = slot & 3;
            uint32_t d = bo + r * PROWB + cc * 16;
            cpa16(d + 0 * PMATB, XH + (size_t)(m0B + r) * DIM + k0 + cc * 8);
            cpa16(d + 1 * PMATB, WH + (size_t)(n0B + r) * DIM + k0 + cc * 8);
        }
    };

    float acc[4][4][4];
#pragma unroll
    for (int mt = 0; mt < 4; mt++)
#pragma unroll
        for (int nt = 0; nt < 4; nt++)
#pragma unroll
            for (int q = 0; q < 4; q++) acc[mt][nt][q] = 0.f;

    const int aoff = (m0W + (lane & 15)) * PROWB + (lane >> 4) * 16;
    const int boff = (n0W + (grp >> 1) * 8 + (lane & 7)) * PROWB + (grp & 1) * 16;

    load_stage(0, 0);  CP_COMMIT();
    load_stage(1, 32); CP_COMMIT();

    for (int it = 0; it < 32; it++) {
        CP_WAIT1();
        __syncthreads();
        const uint32_t bo = sb + (it & 1) * QK_STGB;
        const uint32_t aH = bo + 0 * PMATB + aoff;
        const uint32_t bH = bo + 1 * PMATB + boff;

#pragma unroll
        for (int ks = 0; ks < 2; ks++) {
            const int kb = ks * 32;
            uint32_t ah[4][4], bh[4][2];
#pragma unroll
            for (int mt = 0; mt < 4; mt++)
                ldsm4(ah[mt], aH + mt * 16 * PROWB + kb);
#pragma unroll
            for (int bt = 0; bt < 2; bt++) {
                uint32_t t[4];
                ldsm4(t, bH + bt * 16 * PROWB + kb);
                bh[bt * 2][0] = t[0]; bh[bt * 2][1] = t[1];
                bh[bt * 2 + 1][0] = t[2]; bh[bt * 2 + 1][1] = t[3];
            }
#pragma unroll
            for (int mt = 0; mt < 4; mt++)
#pragma unroll
                for (int nt = 0; nt < 4; nt++)
                    mma16816(acc[mt][nt], ah[mt], bh[nt]);
        }
        __syncthreads();
        const int ns = (it + 2 < 32) ? (it + 2) : 31;
        load_stage((it + 2) & 1, ns * 32);
        CP_COMMIT();
    }

    const int rr  = lane >> 2;
    const int cc2 = (lane & 3) * 2;
#pragma unroll
    for (int mt = 0; mt < 4; mt++) {
#pragma unroll
        for (int hp = 0; hp < 2; hp++) {
            const int m = m0B + m0W + mt * 16 + rr + hp * 8;
            const int n = m >> 11;
            const int l = m & 2047;
            const float ksc = (which == 1) ? g_rscale[n] * 1.44269504f : 1.0f;
            const size_t rowb = ((size_t)(n * NH) * LQ + l) * DH;
#pragma unroll
            for (int nt = 0; nt < 4; nt++) {
                const int j  = n0B + n0W + nt * 8 + cc2;
                const int h  = j >> 6;
                const int dh = j & 63;
                *reinterpret_cast<uint32_t*>(&OutH[rowb + (size_t)h * LQ * DH + dh]) =
                    h2_only(acc[mt][nt][hp * 2 + 0] * ksc,
                            acc[mt][nt][hp * 2 + 1] * ksc);
            }
        }
    }
}

// ============ V projection: 3-pass (fp32 accurate), occupancy 1 ==============
#define V_STGB  (4 * PMATB)              // 40960 per stage (Ah,Al,Bh,Bl)
#define V_SMEM  (2 * V_STGB)             // 81920

__global__ __launch_bounds__(256, 1)
void v_proj_kernel(int dummy) {
    extern __shared__ char smem[];
    const uint32_t sb = smem_u32(smem);

    const int tid  = threadIdx.x;
    const int wid  = tid >> 5;
    const int lane = tid & 31;
    const int grp  = lane >> 3;

    const __half* __restrict__ XH = g_Xkh;
    const __half* __restrict__ XL = g_Xkl;
    const __half* __restrict__ WH = g_Wh + 2 * (size_t)DIM * DIM;
    const __half* __restrict__ WL = g_Wl;

    const int m0B = blockIdx.y * 128;
    const int n0B = blockIdx.x * 128;
    const int m0W = (wid >> 2) * 64;
    const int n0W = (wid & 3) * 32;

    auto load_stage = [&](int buf, int k0) {
        const uint32_t bo = sb + buf * V_STGB;
#pragma unroll
        for (int hp = 0; hp < 2; hp++) {
            int slot = tid + hp * 256;
            int r  = slot >> 2;
            int cc = slot & 3;
            uint32_t d = bo + r * PROWB + cc * 16;
            size_t ga = (size_t)(m0B + r) * DIM + k0 + cc * 8;
            size_t gb = (size_t)(n0B + r) * DIM + k0 + cc * 8;
            cpa16(d + 0 * PMATB, XH + ga);
            cpa16(d + 1 * PMATB, XL + ga);
            cpa16(d + 2 * PMATB, WH + gb);
            cpa16(d + 3 * PMATB, WL + gb);
        }
    };

    float acc[4][4][4];
#pragma unroll
    for (int mt = 0; mt < 4; mt++)
#pragma unroll
        for (int nt = 0; nt < 4; nt++)
#pragma unroll
            for (int q = 0; q < 4; q++) acc[mt][nt][q] = 0.f;

    const int aoff = (m0W + (lane & 15)) * PROWB + (lane >> 4) * 16;
    const int boff = (n0W + (grp >> 1) * 8 + (lane & 7)) * PROWB + (grp & 1) * 16;

    load_stage(0, 0);  CP_COMMIT();
    load_stage(1, 32); CP_COMMIT();

    for (int it = 0; it < 32; it++) {
        CP_WAIT1();
        __syncthreads();
        const uint32_t bo = sb + (it & 1) * V_STGB;
        const uint32_t aH = bo + 0 * PMATB + aoff;
        const uint32_t aL = bo + 1 * PMATB + aoff;
        const uint32_t bH = bo + 2 * PMATB + boff;
        const uint32_t bL = bo + 3 * PMATB + boff;

#pragma unroll
        for (int ks = 0; ks < 2; ks++) {
            const int kb = ks * 32;
            uint32_t ah[4][4], al[4][4], bh[4][2], bl[4][2];
#pragma unroll
            for (int mt = 0; mt < 4; mt++) {
                ldsm4(ah[mt], aH + mt * 16 * PROWB + kb);
                ldsm4(al[mt], aL + mt * 16 * PROWB + kb);
            }
#pragma unroll
            for (int bt = 0; bt < 2; bt++) {
                uint32_t t[4];
                ldsm4(t, bH + bt * 16 * PROWB + kb);
                bh[bt * 2][0] = t[0]; bh[bt * 2][1] = t[1];
                bh[bt * 2 + 1][0] = t[2]; bh[bt * 2 + 1][1] = t[3];
                ldsm4(t, bL + bt * 16 * PROWB + kb);
                bl[bt * 2][0] = t[0]; bl[bt * 2][1] = t[1];
                bl[bt * 2 + 1][0] = t[2]; bl[bt * 2 + 1][1] = t[3];
            }
#pragma unroll
            for (int mt = 0; mt < 4; mt++)
#pragma unroll
                for (int nt = 0; nt < 4; nt++) {
                    mma16816(acc[mt][nt], ah[mt], bh[nt]);
                    mma16816(acc[mt][nt], al[mt], bh[nt]);
                    mma16816(acc[mt][nt], ah[mt], bl[nt]);
                }
        }
        __syncthreads();
        const int ns = (it + 2 < 32) ? (it + 2) : 31;
        load_stage((it + 2) & 1, ns * 32);
        CP_COMMIT();
    }

    const int rr  = lane >> 2;
    const int cc2 = (lane & 3) * 2;
#pragma unroll
    for (int mt = 0; mt < 4; mt++) {
#pragma unroll
        for (int hp = 0; hp < 2; hp++) {
            const int m = m0B + m0W + mt * 16 + rr + hp * 8;
            const int n = m >> 11;
            const int l = m & 2047;
            const size_t rowb = ((size_t)(n * NH) * LQ + l) * DH;
#pragma unroll
            for (int nt = 0; nt < 4; nt++) {
                const int j  = n0B + n0W + nt * 8 + cc2;
                const int h  = j >> 6;
                const int dh = j & 63;
                *reinterpret_cast<uint32_t*>(&g_Vh[rowb + (size_t)h * LQ * DH + dh]) =
                    h2_only(acc[mt][nt][hp * 2 + 0], acc[mt][nt][hp * 2 + 1]);
            }
        }
    }
}

// ================= FA2 attention, fp16 HMMA ================================
// S = 1-pass (Qh·Kh; K pre-scaled by rscale*log2e; exp -> ex2).
// PV = 1-pass (Ph·Vh).  KV stage: Kh, Vh.  Occupancy 2.  LPT block order.
#define ASTR    72
#define AROWB   (ASTR * 2)               // 144 bytes
#define AQB     (128 * AROWB)            // 18432 (Qh only)
#define AKB     (64 * AROWB)             // 9216 per K/V matrix
#define ASTG0   AQB                      // 18432
#define ASTGB   (2 * AKB)                // 18432 per stage (Kh,Vh)
#define ASMEM   (ASTG0 + 2 * ASTGB)      // 55296

__global__ __launch_bounds__(256, 2)
void attn_mma_kernel(float* __restrict__ out) {
    extern __shared__ char smem[];
    const uint32_t sb = smem_u32(smem);

    const int tid  = threadIdx.x;
    const int wid  = tid >> 5;
    const int lane = tid & 31;
    const int grp  = lane >> 3;

    // LPT: heavy (large q0) blocks launch first
    const int q0 = (gridDim.x - 1 - blockIdx.x) * 128;
    const int nh = blockIdx.y;
    const int n  = nh >> 4;
    const int h  = nh & 15;

    const int valid = g_valid[n];
    const int kend  = min(valid, q0 + 128);
    const int nkb   = (kend + 63) >> 6;   // >= 2 always (valid >= 1024)

    const size_t base = (size_t)nh * LK * DH;
    const __half* __restrict__ Qhb = g_Qh + base;
    const __half* __restrict__ Khb = g_Kh + base;
    const __half* __restrict__ Vhb = g_Vh + base;

    auto load_q = [&]() {
#pragma unroll
        for (int i = 0; i < 4; i++) {
            int c  = tid + i * 256;
            int r  = c >> 3;
            int cc = c & 7;
            cpa16(sb + r * AROWB + cc * 16, Qhb + (size_t)(q0 + r) * DH + cc * 8);
        }
    };
    auto load_kv = [&](int buf, int kb) {
        const int k0 = kb * 64;
        const uint32_t so = sb + ASTG0 + buf * ASTGB;
#pragma unroll
        for (int i = 0; i < 4; i++) {
            int c   = tid + i * 256;
            int mat = c >> 9;                 // 0:Kh 1:Vh
            int r   = (c >> 3) & 63;
            int cc  = c & 7;
            const __half* src = (mat == 0) ? Khb : Vhb;
            src += (size_t)(k0 + r) * DH + cc * 8;
            cpa16(so + mat * AKB + r * AROWB + cc * 16, src);
        }
    };

    const int wq0 = wid * 16;
    const int r0  = lane >> 2;
    const int qr0 = q0 + wq0 + r0;
    const int qr1 = qr0 + 8;

    const int qoff = (wq0 + (lane & 15)) * AROWB + (lane >> 4) * 16;
    const int koff = ((grp >> 1) * 8 + (lane & 7)) * AROWB + (grp & 1) * 16;
    const int voff = ((grp & 1) * 8 + (lane & 7)) * AROWB + (grp >> 1) * 16;

    uint32_t qh[4][4];
    float o[8][4];
#pragma unroll
    for (int nt = 0; nt < 8; nt++)
#pragma unroll
        for (int q = 0; q < 4; q++) o[nt][q] = 0.f;
    float m0 = -1e30f, m1 = -1e30f, l0 = 0.f, l1 = 0.f;

    load_q();
    load_kv(0, 0);
    CP_COMMIT();
    load_kv(1, (nkb > 1) ? 1 : 0);
    CP_COMMIT();

    for (int kb = 0; kb < nkb; kb++) {
        CP_WAIT1();
        __syncthreads();
        const int k0 = kb * 64;
        const uint32_t so = sb + ASTG0 + (kb & 1) * ASTGB;

        if (kb == 0) {
#pragma unroll
            for (int kt = 0; kt < 4; kt++)
                ldsm4(qh[kt], sb + qoff + kt * 32);
        }

        // ---- S = Q K^T (1-pass; K carries rscale*log2e) ----
        float sc[8][4];
#pragma unroll
        for (int nt = 0; nt < 8; nt++)
#pragma unroll
            for (int q = 0; q < 4; q++) sc[nt][q] = 0.f;

#pragma unroll
        for (int kt = 0; kt < 4; kt++) {
            uint32_t bh[8][2];
#pragma unroll
            for (int bt = 0; bt < 4; bt++) {
                uint32_t t[4];
                ldsm4(t, so + 0 * AKB + koff + bt * 16 * AROWB + kt * 32);
                bh[bt * 2][0] = t[0]; bh[bt * 2][1] = t[1];
                bh[bt * 2 + 1][0] = t[2]; bh[bt * 2 + 1][1] = t[3];
            }
#pragma unroll
            for (int nt = 0; nt < 8; nt++)
                mma16816(sc[nt], qh[kt], bh[nt]);
        }

        // ---- mask only when this warp's rows intersect causal/pad boundary ----
        if (k0 + 63 > q0 + wq0 || k0 + 64 > valid) {
#pragma unroll
            for (int nt = 0; nt < 8; nt++) {
                const int kc = k0 + nt * 8 + (lane & 3) * 2;
                if (kc     > qr0 || kc     >= valid) sc[nt][0] = -1e30f;
                if (kc + 1 > qr0 || kc + 1 >= valid) sc[nt][1] = -1e30f;
                if (kc     > qr1 || kc     >= valid) sc[nt][2] = -1e30f;
                if (kc + 1 > qr1 || kc + 1 >= valid) sc[nt][3] = -1e30f;
            }
        }

        // ---- online softmax (base-2) ----
        float mx0 = -1e30f, mx1 = -1e30f;
#pragma unroll
        for (int nt = 0; nt < 8; nt++) {
            mx0 = fmaxf(mx0, fmaxf(sc[nt][0], sc[nt][1]));
            mx1 = fmaxf(mx1, fmaxf(sc[nt][2], sc[nt][3]));
        }
        mx0 = fmaxf(mx0, __shfl_xor_sync(0xffffffffu, mx0, 1));
        mx0 = fmaxf(mx0, __shfl_xor_sync(0xffffffffu, mx0, 2));
        mx1 = fmaxf(mx1, __shfl_xor_sync(0xffffffffu, mx1, 1));
        mx1 = fmaxf(mx1, __shfl_xor_sync(0xffffffffu, mx1, 2));
        const float mn0 = fmaxf(m0, mx0);
        const float mn1 = fmaxf(m1, mx1);
        const float f0 = ex2(m0 - mn0);
        const float f1 = ex2(m1 - mn1);
        m0 = mn0; m1 = mn1;

        float s0 = 0.f, s1 = 0.f;
#pragma unroll
        for (int nt = 0; nt < 8; nt++) {
            sc[nt][0] = ex2(sc[nt][0] - mn0);
            sc[nt][1] = ex2(sc[nt][1] - mn0);
            sc[nt][2] = ex2(sc[nt][2] - mn1);
            sc[nt][3] = ex2(sc[nt][3] - mn1);
            s0 += sc[nt][0] + sc[nt][1];
            s1 += sc[nt][2] + sc[nt][3];
        }
        s0 += __shfl_xor_sync(0xffffffffu, s0, 1);
        s0 += __shfl_xor_sync(0xffffffffu, s0, 2);
        s1 += __shfl_xor_sync(0xffffffffu, s1, 1);
        s1 += __shfl_xor_sync(0xffffffffu, s1, 2);
        l0 = l0 * f0 + s0;
        l1 = l1 * f1 + s1;

#pragma unroll
        for (int nt = 0; nt < 8; nt++) {
            o[nt][0] *= f0; o[nt][1] *= f0;
            o[nt][2] *= f1; o[nt][3] *= f1;
        }

        // ---- O += P V (1-pass: Ph x Vh) ----
#pragma unroll
        for (int kt = 0; kt < 4; kt++) {
            uint32_t ah[4];
            ah[0] = h2_only(sc[2 * kt][0],     sc[2 * kt][1]);
            ah[1] = h2_only(sc[2 * kt][2],     sc[2 * kt][3]);
            ah[2] = h2_only(sc[2 * kt + 1][0], sc[2 * kt + 1][1]);
            ah[3] = h2_only(sc[2 * kt + 1][2], sc[2 * kt + 1][3]);

            uint32_t bvh[8][2];
#pragma unroll
            for (int jp = 0; jp < 4; jp++) {
                uint32_t t[4];
                ldsm4t(t, so + 1 * AKB + voff + kt * 16 * AROWB + jp * 32);
                bvh[jp * 2][0] = t[0]; bvh[jp * 2][1] = t[1];
                bvh[jp * 2 + 1][0] = t[2]; bvh[jp * 2 + 1][1] = t[3];
            }
#pragma unroll
            for (int nt = 0; nt < 8; nt++)
                mma16816(o[nt], ah, bvh[nt]);
        }

        __syncthreads();
        const int nb2 = (kb + 2 < nkb) ? (kb + 2) : (nkb - 1);
        load_kv((kb + 2) & 1, nb2);
        CP_COMMIT();
    }

    // ---- normalize + store ----
    const float il0 = 1.0f / l0;
    const float il1 = 1.0f / l1;
    const int lr0 = q0 + wq0 + r0;
    float* orow0 = &out[((size_t)n * LQ + lr0) * DIM + h * DH];
    float* orow1 = &out[((size_t)n * LQ + lr0 + 8) * DIM + h * DH];
#pragma unroll
    for (int nt = 0; nt < 8; nt++) {
        const int dh = nt * 8 + (lane & 3) * 2;
        float2 v0; v0.x = o[nt][0] * il0; v0.y = o[nt][1] * il0;
        float2 v1; v1.x = o[nt][2] * il1; v1.y = o[nt][3] * il1;
        *reinterpret_cast<float2*>(orow0 + dh) = v0;
        *reinterpret_cast<float2*>(orow1 + dh) = v1;
    }
}

// ----------------------------- launcher -------------------------------------
extern "C" void kernel_launch(void* const* d_in, const int* in_sizes, int n_in,
                              void* d_out, int out_size) {
    const float* query = (const float*)d_in[0];
    const float* key   = (const float*)d_in[1];
    const float* Wq    = (const float*)d_in[2];
    const float* Wk    = (const float*)d_in[3];
    const float* Wv    = (const float*)d_in[4];
    const void* pad = (in_sizes[6] == NB * LK) ? d_in[6]
                    : (in_sizes[5] == NB * LK) ? d_in[5]
                    : d_in[6];
    float* out = (float*)d_out;

    valid_kernel<<<NB, 256>>>(pad);

    __half *xqh, *xkh, *xkl, *wh, *wl;
    cudaGetSymbolAddress((void**)&xqh, g_Xqh);
    cudaGetSymbolAddress((void**)&xkh, g_Xkh);
    cudaGetSymbolAddress((void**)&xkl, g_Xkl);
    cudaGetSymbolAddress((void**)&wh,  g_Wh);
    cudaGetSymbolAddress((void**)&wl,  g_Wl);

    const int nx = NB * LQ * DIM;
    const int nw = DIM * DIM;
    cvt_hi_kernel<<<nx / 8 / 256, 256>>>(query, xqh, nx);
    cvt_kernel<<<nx / 8 / 256, 256>>>(key, xkh, xkl, nx);
    cvt_hi_kernel<<<nw / 8 / 256, 256>>>(Wq, wh + 0 * (size_t)nw, nw);
    cvt_hi_kernel<<<nw / 8 / 256, 256>>>(Wk, wh + 1 * (size_t)nw, nw);
    cvt_kernel<<<nw / 8 / 256, 256>>>(Wv, wh + 2 * (size_t)nw, wl, nw);

    cudaFuncSetAttribute(qk_proj_kernel,
                         cudaFuncAttributeMaxDynamicSharedMemorySize, QK_SMEM);
    dim3 qkgrid(DIM / 128, (NB * LQ) / 128, 2);   // (8, 64, 2)
    qk_proj_kernel<<<qkgrid, 256, QK_SMEM>>>(0);

    cudaFuncSetAttribute(v_proj_kernel,
                         cudaFuncAttributeMaxDynamicSharedMemorySize, V_SMEM);
    dim3 vgrid(DIM / 128, (NB * LQ) / 128);       // (8, 64)
    v_proj_kernel<<<vgrid, 256, V_SMEM>>>(0);

    cudaFuncSetAttribute(attn_mma_kernel,
                         cudaFuncAttributeMaxDynamicSharedMemorySize, ASMEM);
    dim3 agrid(LQ / 128, NB * NH);
    attn_mma_kernel<<<agrid, 256, ASMEM>>>(out);
}

// round 13
// speedup vs baseline: 6.9888x; 1.1662x over previous
#include <cuda_runtime.h>
#include <cuda_fp16.h>
#include <math.h>
#include <stdint.h>

#define NB   4
#define LQ   2048
#define LK   2048
#define DIM  1024
#define NH   16
#define DH   64

// ---------------- scratch (static device arrays; no allocation) -------------
__device__ __half g_Xqh[NB * LQ * DIM];
__device__ __half g_Xkh[NB * LK * DIM];
__device__ __half g_Xkl[NB * LK * DIM];
__device__ __half g_Wh[3 * DIM * DIM];
__device__ __half g_Qh[NB * NH * LQ * DH];
__device__ __half g_Kh[NB * NH * LK * DH];   // pre-scaled by rscale[n]*log2(e)
__device__ __half g_Vh[NB * NH * LK * DH];
__device__ int   g_valid[NB];
__device__ float g_rscale[NB];

// ========================= low-level helpers ================================
__device__ __forceinline__ uint32_t smem_u32(const void* p) {
    uint32_t a;
    asm("{ .reg .u64 t; cvta.to.shared.u64 t, %1; cvt.u32.u64 %0, t; }"
        : "=r"(a) : "l"(p));
    return a;
}

__device__ __forceinline__ float ex2(float x) {
    float r;
    asm("ex2.approx.f32 %0, %1;" : "=f"(r) : "f"(x));
    return r;
}

__device__ __forceinline__ void cpa16(uint32_t dst, const void* src) {
    asm volatile("cp.async.cg.shared.global [%0], [%1], 16;"
                 :: "r"(dst), "l"(src) : "memory");
}
#define CP_COMMIT() asm volatile("cp.async.commit_group;" ::: "memory")
#define CP_WAIT1()  asm volatile("cp.async.wait_group 1;" ::: "memory")

__device__ __forceinline__ void ldsm4(uint32_t* r, uint32_t addr) {
    asm volatile("ldmatrix.sync.aligned.m8n8.x4.shared.b16 {%0,%1,%2,%3}, [%4];"
                 : "=r"(r[0]), "=r"(r[1]), "=r"(r[2]), "=r"(r[3]) : "r"(addr));
}
__device__ __forceinline__ void ldsm4t(uint32_t* r, uint32_t addr) {
    asm volatile("ldmatrix.sync.aligned.m8n8.x4.trans.shared.b16 {%0,%1,%2,%3}, [%4];"
                 : "=r"(r[0]), "=r"(r[1]), "=r"(r[2]), "=r"(r[3]) : "r"(addr));
}

__device__ __forceinline__ void mma16816(float* d, const uint32_t* a,
                                         const uint32_t* b) {
    asm volatile(
        "mma.sync.aligned.m16n8k16.row.col.f32.f16.f16.f32 "
        "{%0,%1,%2,%3}, {%4,%5,%6,%7}, {%8,%9}, {%0,%1,%2,%3};"
        : "+f"(d[0]), "+f"(d[1]), "+f"(d[2]), "+f"(d[3])
        : "r"(a[0]), "r"(a[1]), "r"(a[2]), "r"(a[3]), "r"(b[0]), "r"(b[1]));
}

__device__ __forceinline__ void hilo_h2(float a, float b, uint32_t& h, uint32_t& l) {
    __half ha = __float2half_rn(a);
    __half hb = __float2half_rn(b);
    float ra = a - __half2float(ha);
    float rb = b - __half2float(hb);
    __half2 H = __halves2half2(ha, hb);
    __half2 L = __floats2half2_rn(ra, rb);
    h = *reinterpret_cast<uint32_t*>(&H);
    l = *reinterpret_cast<uint32_t*>(&L);
}

__device__ __forceinline__ uint32_t h2_only(float a, float b) {
    __half2 H = __floats2half2_rn(a, b);
    return *reinterpret_cast<uint32_t*>(&H);
}

// ---------------- valid-length + scaling from padding mask ------------------
__global__ void valid_kernel(const void* __restrict__ pad) {
    const int tid = threadIdx.x;
    const int n   = blockIdx.x;
    __shared__ int red[256];

    const unsigned* w = (const unsigned*)pad;
    int f = 0;
    for (int i = tid; i < 2048; i += 256) {
        unsigned v = w[i];
        if (v == 0x3F800000u) f |= 4;
        else if (v == 0x00000001u) f |= 2;
        else if (v == 0x01000000u || v == 0x01010000u ||
                 v == 0x01010100u || v == 0x01010101u) f |= 1;
    }
    red[tid] = f;
    __syncthreads();
    for (int s = 128; s > 0; s >>= 1) {
        if (tid < s) red[tid] |= red[tid + s];
        __syncthreads();
    }
    const int fl = red[0];
    const int layout = (fl & 1) ? 0 : ((fl & 4) ? 2 : 1);
    __syncthreads();

    int c = 0;
    if (layout == 0) {
        const unsigned char* p = (const unsigned char*)pad;
        for (int j = tid; j < LK; j += 256) c += (p[n * LK + j] == 0);
    } else if (layout == 1) {
        const int* p = (const int*)pad;
        for (int j = tid; j < LK; j += 256) c += (p[n * LK + j] == 0);
    } else {
        const float* p = (const float*)pad;
        for (int j = tid; j < LK; j += 256) c += (p[n * LK + j] == 0.0f);
    }
    red[tid] = c;
    __syncthreads();
    for (int s = 128; s > 0; s >>= 1) {
        if (tid < s) red[tid] += red[tid + s];
        __syncthreads();
    }
    if (tid == 0) {
        g_valid[n]  = red[0];
        g_rscale[n] = rsqrtf((float)red[0]);
    }
}

// ---------------- f32 -> fp16 conversions -----------------------------------
__global__ void cvt_kernel(const float* __restrict__ src,
                           __half* __restrict__ dh, __half* __restrict__ dl,
                           int n) {
    int i = (blockIdx.x * blockDim.x + threadIdx.x) * 8;
    if (i >= n) return;
    float4 a = *reinterpret_cast<const float4*>(src + i);
    float4 b = *reinterpret_cast<const float4*>(src + i + 4);
    uint4 H, L;
    hilo_h2(a.x, a.y, H.x, L.x);
    hilo_h2(a.z, a.w, H.y, L.y);
    hilo_h2(b.x, b.y, H.z, L.z);
    hilo_h2(b.z, b.w, H.w, L.w);
    *reinterpret_cast<uint4*>(dh + i) = H;
    *reinterpret_cast<uint4*>(dl + i) = L;
}

__global__ void cvt_hi_kernel(const float* __restrict__ src,
                              __half* __restrict__ dh, int n) {
    int i = (blockIdx.x * blockDim.x + threadIdx.x) * 8;
    if (i >= n) return;
    float4 a = *reinterpret_cast<const float4*>(src + i);
    float4 b = *reinterpret_cast<const float4*>(src + i + 4);
    uint4 H;
    H.x = h2_only(a.x, a.y);
    H.y = h2_only(a.z, a.w);
    H.z = h2_only(b.x, b.y);
    H.w = h2_only(b.z, b.w);
    *reinterpret_cast<uint4*>(dh + i) = H;
}

// ======================= shared proj constants ===============================
#define PSTR    40
#define PROWB   (PSTR * 2)               // 80 bytes
#define PMATB   (128 * PROWB)            // 10240 bytes per matrix tile

// ============ Q/K projection: 1-pass, 2 matrices/stage, occupancy 2 ==========
#define QK_STGB (2 * PMATB)              // 20480 per stage (Ah, Bh)
#define QK_SMEM (2 * QK_STGB)            // 40960

__global__ __launch_bounds__(256, 2)
void qk_proj_kernel(int dummy) {
    extern __shared__ char smem[];
    const uint32_t sb = smem_u32(smem);

    const int tid  = threadIdx.x;
    const int wid  = tid >> 5;
    const int lane = tid & 31;
    const int grp  = lane >> 3;

    const int which = blockIdx.z;        // 0:Q 1:K
    const __half* __restrict__ XH = (which == 0) ? g_Xqh : g_Xkh;
    const __half* __restrict__ WH = g_Wh + (size_t)which * DIM * DIM;
    __half* __restrict__ OutH = (which == 0) ? g_Qh : g_Kh;

    const int m0B = blockIdx.y * 128;
    const int n0B = blockIdx.x * 128;
    const int m0W = (wid >> 2) * 64;
    const int n0W = (wid & 3) * 32;

    auto load_stage = [&](int buf, int k0) {
        const uint32_t bo = sb + buf * QK_STGB;
#pragma unroll
        for (int hp = 0; hp < 2; hp++) {
            int slot = tid + hp * 256;
            int r  = slot >> 2;
            int cc = slot & 3;
            uint32_t d = bo + r * PROWB + cc * 16;
            cpa16(d + 0 * PMATB, XH + (size_t)(m0B + r) * DIM + k0 + cc * 8);
            cpa16(d + 1 * PMATB, WH + (size_t)(n0B + r) * DIM + k0 + cc * 8);
        }
    };

    float acc[4][4][4];
#pragma unroll
    for (int mt = 0; mt < 4; mt++)
#pragma unroll
        for (int nt = 0; nt < 4; nt++)
#pragma unroll
            for (int q = 0; q < 4; q++) acc[mt][nt][q] = 0.f;

    const int aoff = (m0W + (lane & 15)) * PROWB + (lane >> 4) * 16;
    const int boff = (n0W + (grp >> 1) * 8 + (lane & 7)) * PROWB + (grp & 1) * 16;

    load_stage(0, 0);  CP_COMMIT();
    load_stage(1, 32); CP_COMMIT();

    for (int it = 0; it < 32; it++) {
        CP_WAIT1();
        __syncthreads();
        const uint32_t bo = sb + (it & 1) * QK_STGB;
        const uint32_t aH = bo + 0 * PMATB + aoff;
        const uint32_t bH = bo + 1 * PMATB + boff;

#pragma unroll
        for (int ks = 0; ks < 2; ks++) {
            const int kb = ks * 32;
            uint32_t ah[4][4], bh[4][2];
#pragma unroll
            for (int mt = 0; mt < 4; mt++)
                ldsm4(ah[mt], aH + mt * 16 * PROWB + kb);
#pragma unroll
            for (int bt = 0; bt < 2; bt++) {
                uint32_t t[4];
                ldsm4(t, bH + bt * 16 * PROWB + kb);
                bh[bt * 2][0] = t[0]; bh[bt * 2][1] = t[1];
                bh[bt * 2 + 1][0] = t[2]; bh[bt * 2 + 1][1] = t[3];
            }
#pragma unroll
            for (int mt = 0; mt < 4; mt++)
#pragma unroll
                for (int nt = 0; nt < 4; nt++)
                    mma16816(acc[mt][nt], ah[mt], bh[nt]);
        }
        __syncthreads();
        const int ns = (it + 2 < 32) ? (it + 2) : 31;
        load_stage((it + 2) & 1, ns * 32);
        CP_COMMIT();
    }

    const int rr  = lane >> 2;
    const int cc2 = (lane & 3) * 2;
#pragma unroll
    for (int mt = 0; mt < 4; mt++) {
#pragma unroll
        for (int hp = 0; hp < 2; hp++) {
            const int m = m0B + m0W + mt * 16 + rr + hp * 8;
            const int n = m >> 11;
            const int l = m & 2047;
            const float ksc = (which == 1) ? g_rscale[n] * 1.44269504f : 1.0f;
            const size_t rowb = ((size_t)(n * NH) * LQ + l) * DH;
#pragma unroll
            for (int nt = 0; nt < 4; nt++) {
                const int j  = n0B + n0W + nt * 8 + cc2;
                const int h  = j >> 6;
                const int dh = j & 63;
                *reinterpret_cast<uint32_t*>(&OutH[rowb + (size_t)h * LQ * DH + dh]) =
                    h2_only(acc[mt][nt][hp * 2 + 0] * ksc,
                            acc[mt][nt][hp * 2 + 1] * ksc);
            }
        }
    }
}

// ============ V projection: 2-pass (AhBh + AlBh), 3 mats/stage, occ 2 ========
#define V_STGB  (3 * PMATB)              // 30720 per stage (Ah, Al, Bh)
#define V_SMEM  (2 * V_STGB)             // 61440

__global__ __launch_bounds__(256, 2)
void v_proj_kernel(int dummy) {
    extern __shared__ char smem[];
    const uint32_t sb = smem_u32(smem);

    const int tid  = threadIdx.x;
    const int wid  = tid >> 5;
    const int lane = tid & 31;
    const int grp  = lane >> 3;

    const __half* __restrict__ XH = g_Xkh;
    const __half* __restrict__ XL = g_Xkl;
    const __half* __restrict__ WH = g_Wh + 2 * (size_t)DIM * DIM;

    const int m0B = blockIdx.y * 128;
    const int n0B = blockIdx.x * 128;
    const int m0W = (wid >> 2) * 64;
    const int n0W = (wid & 3) * 32;

    auto load_stage = [&](int buf, int k0) {
        const uint32_t bo = sb + buf * V_STGB;
#pragma unroll
        for (int hp = 0; hp < 2; hp++) {
            int slot = tid + hp * 256;
            int r  = slot >> 2;
            int cc = slot & 3;
            uint32_t d = bo + r * PROWB + cc * 16;
            size_t ga = (size_t)(m0B + r) * DIM + k0 + cc * 8;
            cpa16(d + 0 * PMATB, XH + ga);
            cpa16(d + 1 * PMATB, XL + ga);
            cpa16(d + 2 * PMATB, WH + (size_t)(n0B + r) * DIM + k0 + cc * 8);
        }
    };

    float acc[4][4][4];
#pragma unroll
    for (int mt = 0; mt < 4; mt++)
#pragma unroll
        for (int nt = 0; nt < 4; nt++)
#pragma unroll
            for (int q = 0; q < 4; q++) acc[mt][nt][q] = 0.f;

    const int aoff = (m0W + (lane & 15)) * PROWB + (lane >> 4) * 16;
    const int boff = (n0W + (grp >> 1) * 8 + (lane & 7)) * PROWB + (grp & 1) * 16;

    load_stage(0, 0);  CP_COMMIT();
    load_stage(1, 32); CP_COMMIT();

    for (int it = 0; it < 32; it++) {
        CP_WAIT1();
        __syncthreads();
        const uint32_t bo = sb + (it & 1) * V_STGB;
        const uint32_t aH = bo + 0 * PMATB + aoff;
        const uint32_t aL = bo + 1 * PMATB + aoff;
        const uint32_t bH = bo + 2 * PMATB + boff;

#pragma unroll
        for (int ks = 0; ks < 2; ks++) {
            const int kb = ks * 32;
            uint32_t ah[4][4], al[4][4], bh[4][2];
#pragma unroll
            for (int mt = 0; mt < 4; mt++) {
                ldsm4(ah[mt], aH + mt * 16 * PROWB + kb);
                ldsm4(al[mt], aL + mt * 16 * PROWB + kb);
            }
#pragma unroll
            for (int bt = 0; bt < 2; bt++) {
                uint32_t t[4];
                ldsm4(t, bH + bt * 16 * PROWB + kb);
                bh[bt * 2][0] = t[0]; bh[bt * 2][1] = t[1];
                bh[bt * 2 + 1][0] = t[2]; bh[bt * 2 + 1][1] = t[3];
            }
#pragma unroll
            for (int mt = 0; mt < 4; mt++)
#pragma unroll
                for (int nt = 0; nt < 4; nt++) {
                    mma16816(acc[mt][nt], ah[mt], bh[nt]);
                    mma16816(acc[mt][nt], al[mt], bh[nt]);
                }
        }
        __syncthreads();
        const int ns = (it + 2 < 32) ? (it + 2) : 31;
        load_stage((it + 2) & 1, ns * 32);
        CP_COMMIT();
    }

    const int rr  = lane >> 2;
    const int cc2 = (lane & 3) * 2;
#pragma unroll
    for (int mt = 0; mt < 4; mt++) {
#pragma unroll
        for (int hp = 0; hp < 2; hp++) {
            const int m = m0B + m0W + mt * 16 + rr + hp * 8;
            const int n = m >> 11;
            const int l = m & 2047;
            const size_t rowb = ((size_t)(n * NH) * LQ + l) * DH;
#pragma unroll
            for (int nt = 0; nt < 4; nt++) {
                const int j  = n0B + n0W + nt * 8 + cc2;
                const int h  = j >> 6;
                const int dh = j & 63;
                *reinterpret_cast<uint32_t*>(&g_Vh[rowb + (size_t)h * LQ * DH + dh]) =
                    h2_only(acc[mt][nt][hp * 2 + 0], acc[mt][nt][hp * 2 + 1]);
            }
        }
    }
}

// ================= FA2 attention, fp16 HMMA ================================
// S = 1-pass (Qh·Kh; K pre-scaled by rscale*log2e; exp -> ex2).
// PV = 1-pass (Ph·Vh).  KV stage: Kh, Vh.  Occupancy 2.  LPT block order.
#define ASTR    72
#define AROWB   (ASTR * 2)               // 144 bytes
#define AQB     (128 * AROWB)            // 18432 (Qh only)
#define AKB     (64 * AROWB)             // 9216 per K/V matrix
#define ASTG0   AQB                      // 18432
#define ASTGB   (2 * AKB)                // 18432 per stage (Kh,Vh)
#define ASMEM   (ASTG0 + 2 * ASTGB)      // 55296

__global__ __launch_bounds__(256, 2)
void attn_mma_kernel(float* __restrict__ out) {
    extern __shared__ char smem[];
    const uint32_t sb = smem_u32(smem);

    const int tid  = threadIdx.x;
    const int wid  = tid >> 5;
    const int lane = tid & 31;
    const int grp  = lane >> 3;

    // LPT: heavy (large q0) blocks launch first
    const int q0 = (gridDim.x - 1 - blockIdx.x) * 128;
    const int nh = blockIdx.y;
    const int n  = nh >> 4;
    const int h  = nh & 15;

    const int valid = g_valid[n];
    const int kend  = min(valid, q0 + 128);
    const int nkb   = (kend + 63) >> 6;   // >= 2 always (valid >= 1024)

    const size_t base = (size_t)nh * LK * DH;
    const __half* __restrict__ Qhb = g_Qh + base;
    const __half* __restrict__ Khb = g_Kh + base;
    const __half* __restrict__ Vhb = g_Vh + base;

    auto load_q = [&]() {
#pragma unroll
        for (int i = 0; i < 4; i++) {
            int c  = tid + i * 256;
            int r  = c >> 3;
            int cc = c & 7;
            cpa16(sb + r * AROWB + cc * 16, Qhb + (size_t)(q0 + r) * DH + cc * 8);
        }
    };
    auto load_kv = [&](int buf, int kb) {
        const int k0 = kb * 64;
        const uint32_t so = sb + ASTG0 + buf * ASTGB;
#pragma unroll
        for (int i = 0; i < 4; i++) {
            int c   = tid + i * 256;
            int mat = c >> 9;                 // 0:Kh 1:Vh
            int r   = (c >> 3) & 63;
            int cc  = c & 7;
            const __half* src = (mat == 0) ? Khb : Vhb;
            src += (size_t)(k0 + r) * DH + cc * 8;
            cpa16(so + mat * AKB + r * AROWB + cc * 16, src);
        }
    };

    const int wq0 = wid * 16;
    const int r0  = lane >> 2;
    const int qr0 = q0 + wq0 + r0;
    const int qr1 = qr0 + 8;

    const int qoff = (wq0 + (lane & 15)) * AROWB + (lane >> 4) * 16;
    const int koff = ((grp >> 1) * 8 + (lane & 7)) * AROWB + (grp & 1) * 16;
    const int voff = ((grp & 1) * 8 + (lane & 7)) * AROWB + (grp >> 1) * 16;

    uint32_t qh[4][4];
    float o[8][4];
#pragma unroll
    for (int nt = 0; nt < 8; nt++)
#pragma unroll
        for (int q = 0; q < 4; q++) o[nt][q] = 0.f;
    float m0 = -1e30f, m1 = -1e30f, l0 = 0.f, l1 = 0.f;

    load_q();
    load_kv(0, 0);
    CP_COMMIT();
    load_kv(1, (nkb > 1) ? 1 : 0);
    CP_COMMIT();

    for (int kb = 0; kb < nkb; kb++) {
        CP_WAIT1();
        __syncthreads();
        const int k0 = kb * 64;
        const uint32_t so = sb + ASTG0 + (kb & 1) * ASTGB;

        if (kb == 0) {
#pragma unroll
            for (int kt = 0; kt < 4; kt++)
                ldsm4(qh[kt], sb + qoff + kt * 32);
        }

        // ---- S = Q K^T (1-pass; K carries rscale*log2e) ----
        float sc[8][4];
#pragma unroll
        for (int nt = 0; nt < 8; nt++)
#pragma unroll
            for (int q = 0; q < 4; q++) sc[nt][q] = 0.f;

#pragma unroll
        for (int kt = 0; kt < 4; kt++) {
            uint32_t bh[8][2];
#pragma unroll
            for (int bt = 0; bt < 4; bt++) {
                uint32_t t[4];
                ldsm4(t, so + 0 * AKB + koff + bt * 16 * AROWB + kt * 32);
                bh[bt * 2][0] = t[0]; bh[bt * 2][1] = t[1];
                bh[bt * 2 + 1][0] = t[2]; bh[bt * 2 + 1][1] = t[3];
            }
#pragma unroll
            for (int nt = 0; nt < 8; nt++)
                mma16816(sc[nt], qh[kt], bh[nt]);
        }

        // ---- mask only when this warp's rows intersect causal/pad boundary ----
        if (k0 + 63 > q0 + wq0 || k0 + 64 > valid) {
#pragma unroll
            for (int nt = 0; nt < 8; nt++) {
                const int kc = k0 + nt * 8 + (lane & 3) * 2;
                if (kc     > qr0 || kc     >= valid) sc[nt][0] = -1e30f;
                if (kc + 1 > qr0 || kc + 1 >= valid) sc[nt][1] = -1e30f;
                if (kc     > qr1 || kc     >= valid) sc[nt][2] = -1e30f;
                if (kc + 1 > qr1 || kc + 1 >= valid) sc[nt][3] = -1e30f;
            }
        }

        // ---- online softmax (base-2) ----
        float mx0 = -1e30f, mx1 = -1e30f;
#pragma unroll
        for (int nt = 0; nt < 8; nt++) {
            mx0 = fmaxf(mx0, fmaxf(sc[nt][0], sc[nt][1]));
            mx1 = fmaxf(mx1, fmaxf(sc[nt][2], sc[nt][3]));
        }
        mx0 = fmaxf(mx0, __shfl_xor_sync(0xffffffffu, mx0, 1));
        mx0 = fmaxf(mx0, __shfl_xor_sync(0xffffffffu, mx0, 2));
        mx1 = fmaxf(mx1, __shfl_xor_sync(0xffffffffu, mx1, 1));
        mx1 = fmaxf(mx1, __shfl_xor_sync(0xffffffffu, mx1, 2));
        const float mn0 = fmaxf(m0, mx0);
        const float mn1 = fmaxf(m1, mx1);
        const float f0 = ex2(m0 - mn0);
        const float f1 = ex2(m1 - mn1);
        m0 = mn0; m1 = mn1;

        float s0 = 0.f, s1 = 0.f;
#pragma unroll
        for (int nt = 0; nt < 8; nt++) {
            sc[nt][0] = ex2(sc[nt][0] - mn0);
            sc[nt][1] = ex2(sc[nt][1] - mn0);
            sc[nt][2] = ex2(sc[nt][2] - mn1);
            sc[nt][3] = ex2(sc[nt][3] - mn1);
            s0 += sc[nt][0] + sc[nt][1];
            s1 += sc[nt][2] + sc[nt][3];
        }
        s0 += __shfl_xor_sync(0xffffffffu, s0, 1);
        s0 += __shfl_xor_sync(0xffffffffu, s0, 2);
        s1 += __shfl_xor_sync(0xffffffffu, s1, 1);
        s1 += __shfl_xor_sync(0xffffffffu, s1, 2);
        l0 = l0 * f0 + s0;
        l1 = l1 * f1 + s1;

#pragma unroll
        for (int nt = 0; nt < 8; nt++) {
            o[nt][0] *= f0; o[nt][1] *= f0;
            o[nt][2] *= f1; o[nt][3] *= f1;
        }

        // ---- O += P V (1-pass: Ph x Vh) ----
#pragma unroll
        for (int kt = 0; kt < 4; kt++) {
            uint32_t ah[4];
            ah[0] = h2_only(sc[2 * kt][0],     sc[2 * kt][1]);
            ah[1] = h2_only(sc[2 * kt][2],     sc[2 * kt][3]);
            ah[2] = h2_only(sc[2 * kt + 1][0], sc[2 * kt + 1][1]);
            ah[3] = h2_only(sc[2 * kt + 1][2], sc[2 * kt + 1][3]);

            uint32_t bvh[8][2];
#pragma unroll
            for (int jp = 0; jp < 4; jp++) {
                uint32_t t[4];
                ldsm4t(t, so + 1 * AKB + voff + kt * 16 * AROWB + jp * 32);
                bvh[jp * 2][0] = t[0]; bvh[jp * 2][1] = t[1];
                bvh[jp * 2 + 1][0] = t[2]; bvh[jp * 2 + 1][1] = t[3];
            }
#pragma unroll
            for (int nt = 0; nt < 8; nt++)
                mma16816(o[nt], ah, bvh[nt]);
        }

        __syncthreads();
        const int nb2 = (kb + 2 < nkb) ? (kb + 2) : (nkb - 1);
        load_kv((kb + 2) & 1, nb2);
        CP_COMMIT();
    }

    // ---- normalize + store ----
    const float il0 = 1.0f / l0;
    const float il1 = 1.0f / l1;
    const int lr0 = q0 + wq0 + r0;
    float* orow0 = &out[((size_t)n * LQ + lr0) * DIM + h * DH];
    float* orow1 = &out[((size_t)n * LQ + lr0 + 8) * DIM + h * DH];
#pragma unroll
    for (int nt = 0; nt < 8; nt++) {
        const int dh = nt * 8 + (lane & 3) * 2;
        float2 v0; v0.x = o[nt][0] * il0; v0.y = o[nt][1] * il0;
        float2 v1; v1.x = o[nt][2] * il1; v1.y = o[nt][3] * il1;
        *reinterpret_cast<float2*>(orow0 + dh) = v0;
        *reinterpret_cast<float2*>(orow1 + dh) = v1;
    }
}

// ----------------------------- launcher -------------------------------------
extern "C" void kernel_launch(void* const* d_in, const int* in_sizes, int n_in,
                              void* d_out, int out_size) {
    const float* query = (const float*)d_in[0];
    const float* key   = (const float*)d_in[1];
    const float* Wq    = (const float*)d_in[2];
    const float* Wk    = (const float*)d_in[3];
    const float* Wv    = (const float*)d_in[4];
    const void* pad = (in_sizes[6] == NB * LK) ? d_in[6]
                    : (in_sizes[5] == NB * LK) ? d_in[5]
                    : d_in[6];
    float* out = (float*)d_out;

    valid_kernel<<<NB, 256>>>(pad);

    __half *xqh, *xkh, *xkl, *wh;
    cudaGetSymbolAddress((void**)&xqh, g_Xqh);
    cudaGetSymbolAddress((void**)&xkh, g_Xkh);
    cudaGetSymbolAddress((void**)&xkl, g_Xkl);
    cudaGetSymbolAddress((void**)&wh,  g_Wh);

    const int nx = NB * LQ * DIM;
    const int nw = DIM * DIM;
    cvt_hi_kernel<<<nx / 8 / 256, 256>>>(query, xqh, nx);
    cvt_kernel<<<nx / 8 / 256, 256>>>(key, xkh, xkl, nx);
    cvt_hi_kernel<<<nw / 8 / 256, 256>>>(Wq, wh + 0 * (size_t)nw, nw);
    cvt_hi_kernel<<<nw / 8 / 256, 256>>>(Wk, wh + 1 * (size_t)nw, nw);
    cvt_hi_kernel<<<nw / 8 / 256, 256>>>(Wv, wh + 2 * (size_t)nw, nw);

    cudaFuncSetAttribute(qk_proj_kernel,
                         cudaFuncAttributeMaxDynamicSharedMemorySize, QK_SMEM);
    dim3 qkgrid(DIM / 128, (NB * LQ) / 128, 2);   // (8, 64, 2)
    qk_proj_kernel<<<qkgrid, 256, QK_SMEM>>>(0);

    cudaFuncSetAttribute(v_proj_kernel,
                         cudaFuncAttributeMaxDynamicSharedMemorySize, V_SMEM);
    dim3 vgrid(DIM / 128, (NB * LQ) / 128);       // (8, 64)
    v_proj_kernel<<<vgrid, 256, V_SMEM>>>(0);

    cudaFuncSetAttribute(attn_mma_kernel,
                         cudaFuncAttributeMaxDynamicSharedMemorySize, ASMEM);
    dim3 agrid(LQ / 128, NB * NH);
    attn_mma_kernel<<<agrid, 256, ASMEM>>>(out);
}